// round 4
// baseline (speedup 1.0000x reference)
#include <cuda_runtime.h>
#include <cuda_bf16.h>
#include <math.h>

// ---------------------------------------------------------------------------
// dividedSpaceTimeAttention  (B=8, NH=12, DIM=768, NP=196, NF=16, DH=64)
//   D3=192/head, 3*DIM=2304, SEQ=3136, SCALE=1/96
// Exploited structure:
//   * ti has only 195 unique rows/batch (temporal tile)
//   * final matmul has only 17 unique rows/batch (cls + 16 outs)
//   * _att_sum => accumulate key weights w, then w @ V
//   * rope applied on the fly (P buffers stay raw: cls path needs raw rows)
//   * xi-attention: keys are rows xi..xi+15; query row xi has multiplicity 2
// ---------------------------------------------------------------------------

#define SCALE_C (1.0f/96.0f)

// scratch (device globals; allocation-free)
__device__ float g_Pq[57821184];          // 8*3137*2304
__device__ float g_Pk[57821184];
__device__ float g_Pv[57821184];
__device__ float g_tmp[8*195*2304];
__device__ float g_ti [8*195*768];
__device__ float g_Aq [8*195*2304];
__device__ float g_Ak [8*195*2304];
__device__ float g_Av [8*195*2304];
__device__ float g_S  [96*195*195];       // xi=0 score matrices
__device__ float g_U  [8*17*2304];        // row0 = cls_out, rows 1..16 = outs[xi]
__device__ float g_Ou [8*17*768];
__device__ float g_cos[3136*32];
__device__ float g_sin[3136*32];

// ---------------------------------------------------------------------------
__global__ void rope_init_k() {
    int idx = blockIdx.x * 256 + threadIdx.x;
    if (idx >= 3136*32) return;
    int s = idx >> 5, i = idx & 31;
    float e = (float)(2*i) / 64.f;
    float invf = 1.f / powf(10000.f, e);          // fp32, like reference
    float ang = (float)s * invf;                  // fp32 product, like reference
    g_cos[idx] = (float)cos((double)ang);
    g_sin[idx] = (float)sin((double)ang);
}

// ---------------------------------------------------------------------------
// SGEMM 128x128x8, 256 threads, 8x8/thread.  C = A(MxK) @ B(KxN) + bias(N)
// requires N%128==0, K%8==0; M guarded.
// ---------------------------------------------------------------------------
__global__ void __launch_bounds__(256) sgemm_k(
    const float* __restrict__ A, const float* __restrict__ B,
    const float* __restrict__ bias, float* __restrict__ C,
    int M, int N, int K)
{
    __shared__ float As[8][128];
    __shared__ float Bs[8][128];
    const int bm = blockIdx.y * 128;
    const int bn = blockIdx.x * 128;
    const int tid = threadIdx.x;
    const int tx = tid & 15;
    const int ty = tid >> 4;
    const int arow = tid >> 1;
    const int acol = (tid & 1) * 4;
    const int brow = tid >> 5;
    const int bcol = (tid & 31) * 4;

    float acc[8][8];
#pragma unroll
    for (int i = 0; i < 8; i++)
#pragma unroll
        for (int j = 0; j < 8; j++) acc[i][j] = 0.f;

    const bool arow_ok = (bm + arow) < M;
    const float* Aptr = A + (size_t)(bm + arow) * K + acol;
    const float* Bptr = B + (size_t)brow * N + bn + bcol;

    for (int k0 = 0; k0 < K; k0 += 8) {
        float4 av = make_float4(0.f, 0.f, 0.f, 0.f);
        if (arow_ok) av = *(const float4*)(Aptr + k0);
        float4 bv = *(const float4*)(Bptr + (size_t)k0 * N);
        As[acol + 0][arow] = av.x;
        As[acol + 1][arow] = av.y;
        As[acol + 2][arow] = av.z;
        As[acol + 3][arow] = av.w;
        *(float4*)&Bs[brow][bcol] = bv;
        __syncthreads();
#pragma unroll
        for (int kk = 0; kk < 8; kk++) {
            float ar[8], br[8];
            *(float4*)(ar)     = *(const float4*)&As[kk][ty * 8];
            *(float4*)(ar + 4) = *(const float4*)&As[kk][ty * 8 + 4];
            *(float4*)(br)     = *(const float4*)&Bs[kk][tx * 8];
            *(float4*)(br + 4) = *(const float4*)&Bs[kk][tx * 8 + 4];
#pragma unroll
            for (int i = 0; i < 8; i++)
#pragma unroll
                for (int j = 0; j < 8; j++)
                    acc[i][j] += ar[i] * br[j];
        }
        __syncthreads();
    }
#pragma unroll
    for (int i = 0; i < 8; i++) {
        int m = bm + ty * 8 + i;
        if (m < M) {
            float* Crow = C + (size_t)m * N + bn + tx * 8;
#pragma unroll
            for (int j = 0; j < 8; j++)
                Crow[j] = acc[i][j] + bias[bn + tx * 8 + j];
        }
    }
}

// small variant: 64x64 tile, 4x4/thread (final 136-row GEMM)
__global__ void __launch_bounds__(256) sgemm64_k(
    const float* __restrict__ A, const float* __restrict__ B,
    const float* __restrict__ bias, float* __restrict__ C,
    int M, int N, int K)
{
    __shared__ float As[8][64];
    __shared__ float Bs[8][64];
    const int bm = blockIdx.y * 64, bn = blockIdx.x * 64;
    const int tid = threadIdx.x;
    const int tx = tid & 15, ty = tid >> 4;
    const int arow = tid >> 2, acol = (tid & 3) * 2;
    const int brow = tid >> 5, bcol = (tid & 31) * 2;
    float acc[4][4];
#pragma unroll
    for (int i = 0; i < 4; i++)
#pragma unroll
        for (int j = 0; j < 4; j++) acc[i][j] = 0.f;
    const bool arow_ok = (bm + arow) < M;
    for (int k0 = 0; k0 < K; k0 += 8) {
        float2 av = make_float2(0.f, 0.f);
        if (arow_ok) av = *(const float2*)(A + (size_t)(bm + arow) * K + k0 + acol);
        As[acol][arow] = av.x;  As[acol + 1][arow] = av.y;
        float2 bv = *(const float2*)(B + (size_t)(k0 + brow) * N + bn + bcol);
        Bs[brow][bcol] = bv.x;  Bs[brow][bcol + 1] = bv.y;
        __syncthreads();
#pragma unroll
        for (int kk = 0; kk < 8; kk++) {
            float ar[4], br[4];
#pragma unroll
            for (int i = 0; i < 4; i++) ar[i] = As[kk][ty * 4 + i];
#pragma unroll
            for (int j = 0; j < 4; j++) br[j] = Bs[kk][tx * 4 + j];
#pragma unroll
            for (int i = 0; i < 4; i++)
#pragma unroll
                for (int j = 0; j < 4; j++)
                    acc[i][j] += ar[i] * br[j];
        }
        __syncthreads();
    }
#pragma unroll
    for (int i = 0; i < 4; i++) {
        int m = bm + ty * 4 + i;
        if (m < M)
#pragma unroll
            for (int j = 0; j < 4; j++)
                C[(size_t)m * N + bn + tx * 4 + j] = acc[i][j] + bias[bn + tx * 4 + j];
    }
}

// ---------------------------------------------------------------------------
// Grouped frame-attention + sum over query frames.
// block (p-1, h, b), p in 1..195.  q<-Pq (roped), k<-Pv (roped), v<-Pk.
// out: g_tmp[b*195+p-1][h*192+d]
// ---------------------------------------------------------------------------
#define GA 193   // 193 % 32 == 1 -> conflict-free per-key column reads
__global__ void __launch_bounds__(256) grattn_k() {
    const int p = blockIdx.x + 1;
    const int h = blockIdx.y;
    const int b = blockIdx.z;
    __shared__ float qs[16*GA], ks[16*GA], vs[16*GA];
    __shared__ float S[256], wg[16];
    const int tid = threadIdx.x;

    for (int idx = tid; idx < 16*192; idx += 256) {
        int f = idx / 192, d = idx - f * 192;
        size_t off = ((size_t)(b * 3137 + 1 + f * 196 + p)) * 2304 + h * 192 + d;
        qs[f*GA + d] = g_Pq[off];
        ks[f*GA + d] = g_Pv[off];
        vs[f*GA + d] = g_Pk[off];
    }
    __syncthreads();
    // rope q and k on dims 0..63 (pairs)
    for (int idx = tid; idx < 16*32; idx += 256) {
        int f = idx >> 5, i = idx & 31;
        int s = f * 196 + p;
        float c = g_cos[s*32 + i], sn = g_sin[s*32 + i];
        float a0 = qs[f*GA + 2*i], a1 = qs[f*GA + 2*i + 1];
        qs[f*GA + 2*i]     = a0 * c - a1 * sn;
        qs[f*GA + 2*i + 1] = a1 * c + a0 * sn;
        float b0 = ks[f*GA + 2*i], b1 = ks[f*GA + 2*i + 1];
        ks[f*GA + 2*i]     = b0 * c - b1 * sn;
        ks[f*GA + 2*i + 1] = b1 * c + b0 * sn;
    }
    __syncthreads();
    {   // 16x16 scores, one thread per (f,g)
        int f = tid >> 4, g = tid & 15;
        const float* qp = qs + f * GA;
        const float* kp = ks + g * GA;
        float s = 0.f;
#pragma unroll 8
        for (int d = 0; d < 192; d++) s += qp[d] * kp[d];
        S[tid] = s * SCALE_C;
    }
    __syncthreads();
    if (tid < 16) {                 // softmax row f over g
        float m = -1e30f;
        for (int g = 0; g < 16; g++) m = fmaxf(m, S[tid*16 + g]);
        float sum = 0.f;
        for (int g = 0; g < 16; g++) { float e = expf(S[tid*16 + g] - m); S[tid*16 + g] = e; sum += e; }
        float inv = 1.f / sum;
        for (int g = 0; g < 16; g++) S[tid*16 + g] *= inv;
    }
    __syncthreads();
    if (tid < 16) {                 // column sums over f
        float a = 0.f;
        for (int f = 0; f < 16; f++) a += S[f*16 + tid];
        wg[tid] = a;
    }
    __syncthreads();
    if (tid < 192) {
        float o = 0.f;
#pragma unroll
        for (int g = 0; g < 16; g++) o += wg[g] * vs[g*GA + tid];
        g_tmp[((size_t)(b * 195 + (p - 1))) * 2304 + h * 192 + tid] = o;
    }
}

// ---------------------------------------------------------------------------
// CLS attention: per (h,b), q = Pq row 0, 3137 keys from Pk, values from Pv.
// ---------------------------------------------------------------------------
__global__ void __launch_bounds__(256) cls_k() {
    const int h = blockIdx.x, b = blockIdx.y;
    __shared__ float qv[192];
    __shared__ float Sv[3137];
    __shared__ float red[256];
    const int tid = threadIdx.x;
    const float* Pq_ = g_Pq + (size_t)b*3137*2304 + h*192;
    const float* Pk_ = g_Pk + (size_t)b*3137*2304 + h*192;
    const float* Pv_ = g_Pv + (size_t)b*3137*2304 + h*192;
    if (tid < 192) qv[tid] = Pq_[tid];
    __syncthreads();
    float lm = -1e30f;
    for (int t = tid; t < 3137; t += 256) {
        const float* kr = Pk_ + (size_t)t*2304;
        float s = 0.f;
        for (int d = 0; d < 192; d += 4) {
            float4 k4 = *(const float4*)(kr + d);
            s += k4.x*qv[d] + k4.y*qv[d+1] + k4.z*qv[d+2] + k4.w*qv[d+3];
        }
        s *= SCALE_C;
        Sv[t] = s;
        lm = fmaxf(lm, s);
    }
    red[tid] = lm; __syncthreads();
    for (int s2 = 128; s2 > 0; s2 >>= 1) {
        if (tid < s2) red[tid] = fmaxf(red[tid], red[tid + s2]);
        __syncthreads();
    }
    const float m = red[0];
    __syncthreads();
    float ls = 0.f;
    for (int t = tid; t < 3137; t += 256) { float e = expf(Sv[t] - m); Sv[t] = e; ls += e; }
    red[tid] = ls; __syncthreads();
    for (int s2 = 128; s2 > 0; s2 >>= 1) {
        if (tid < s2) red[tid] += red[tid + s2];
        __syncthreads();
    }
    const float inv = 1.f / red[0];
    if (tid < 192) {
        float o = 0.f;
        const float* vp = Pv_ + tid;
        for (int t = 0; t < 3137; t++) o += Sv[t] * vp[(size_t)t*2304];
        g_U[((size_t)b*17 + 0)*2304 + h*192 + tid] = o * inv;
    }
}

// ---------------------------------------------------------------------------
// xi=0 scores: S[bh][i][j] = SCALE * dot(Aq row i, Av row j), 195x195, K=192
// grid (7,7,96), 32x32 tiles, 2x2 per thread.
// ---------------------------------------------------------------------------
__global__ void __launch_bounds__(256) s0_k() {
    const int bh = blockIdx.z;
    const int b = bh / 12, h = bh % 12;
    const int i0 = blockIdx.y * 32, j0 = blockIdx.x * 32;
    __shared__ float Qs[16][33], Ks[16][33];
    const int tid = threadIdx.x;
    const int tx = tid & 15, ty = tid >> 4;
    const float* Abase = g_Aq + (size_t)b*195*2304 + h*192;
    const float* Bbase = g_Av + (size_t)b*195*2304 + h*192;
    float acc00 = 0.f, acc01 = 0.f, acc10 = 0.f, acc11 = 0.f;
    const int r = tid >> 3;          // 0..31
    const int c = (tid & 7) * 2;     // 0..14
    for (int k0 = 0; k0 < 192; k0 += 16) {
        int qi = i0 + r;
        float2 qv = make_float2(0.f, 0.f);
        if (qi < 195) qv = *(const float2*)(Abase + (size_t)qi*2304 + k0 + c);
        Qs[c][r] = qv.x; Qs[c+1][r] = qv.y;
        int kj = j0 + r;
        float2 kv = make_float2(0.f, 0.f);
        if (kj < 195) kv = *(const float2*)(Bbase + (size_t)kj*2304 + k0 + c);
        Ks[c][r] = kv.x; Ks[c+1][r] = kv.y;
        __syncthreads();
#pragma unroll
        for (int kk = 0; kk < 16; kk++) {
            float a0 = Qs[kk][ty*2], a1 = Qs[kk][ty*2+1];
            float b0 = Ks[kk][tx*2], b1 = Ks[kk][tx*2+1];
            acc00 += a0*b0; acc01 += a0*b1; acc10 += a1*b0; acc11 += a1*b1;
        }
        __syncthreads();
    }
    float* Sp = g_S + (size_t)bh*195*195;
    int ii = i0 + ty*2, jj = j0 + tx*2;
    if (ii < 195) {
        if (jj   < 195) Sp[(size_t)ii*195 + jj  ] = acc00 * SCALE_C;
        if (jj+1 < 195) Sp[(size_t)ii*195 + jj+1] = acc01 * SCALE_C;
    }
    if (ii+1 < 195) {
        if (jj   < 195) Sp[(size_t)(ii+1)*195 + jj  ] = acc10 * SCALE_C;
        if (jj+1 < 195) Sp[(size_t)(ii+1)*195 + jj+1] = acc11 * SCALE_C;
    }
}

// ---------------------------------------------------------------------------
// xi=0 softmax + key-weight accumulation + w@V.  Key row 0 has multiplicity 2
// (appears at key positions 0 and 195); query row 0 has multiplicity 2.
// ---------------------------------------------------------------------------
__global__ void __launch_bounds__(256) soft0_k() {
    const int bh = blockIdx.x;
    const int b = bh / 12, h = bh % 12;
    const float* S = g_S + (size_t)bh*195*195;
    __shared__ float wk_s[195];
    const int tid = threadIdx.x;
    if (tid < 195) wk_s[tid] = 0.f;
    __syncthreads();
    const int warp = tid >> 5, lane = tid & 31;
    for (int q = warp; q < 195; q += 8) {
        const float* Sq = S + (size_t)q*195;
        float m = -1e30f;
        for (int k = lane; k < 195; k += 32) m = fmaxf(m, Sq[k]);
        for (int o = 16; o; o >>= 1) m = fmaxf(m, __shfl_xor_sync(0xFFFFFFFFu, m, o));
        float sum = 0.f;
        for (int k = lane; k < 195; k += 32) sum += expf(Sq[k] - m);
        if (lane == 0) sum += expf(Sq[0] - m);      // duplicate key 0
        for (int o = 16; o; o >>= 1) sum += __shfl_xor_sync(0xFFFFFFFFu, sum, o);
        const float inv = 1.f / sum;
        const float mult = (q == 0) ? 2.f : 1.f;
        for (int k = lane; k < 195; k += 32) {
            float w = expf(Sq[k] - m) * inv * mult;
            if (k == 0) w *= 2.f;                   // duplicate key 0 weight
            atomicAdd(&wk_s[k], w);
        }
    }
    __syncthreads();
    if (tid < 192) {
        const float* V = g_Ak + (size_t)b*195*2304 + h*192 + tid;
        float o = 0.f;
        for (int k = 0; k < 195; k++) o += wk_s[k] * V[(size_t)k*2304];
        g_U[((size_t)b*17 + 1)*2304 + h*192 + tid] = o;
    }
}

// ---------------------------------------------------------------------------
// xi=1..15: keys = rows xi..xi+15 (16 keys, no dup); queries = all 195 rows,
// row xi with multiplicity 2.  grid (15, 12, 8).
// ---------------------------------------------------------------------------
__global__ void __launch_bounds__(256) attn2x_k() {
    const int xi = blockIdx.x + 1;
    const int h = blockIdx.y, b = blockIdx.z;
    __shared__ float Ksm[16][192];
    __shared__ float Vsm[16][192];
    __shared__ float wk[16];
    const int tid = threadIdx.x;
    for (int idx = tid; idx < 16*192; idx += 256) {
        int j = idx / 192, d = idx - j*192;
        size_t ro = ((size_t)(b*195 + xi + j))*2304 + h*192 + d;
        Ksm[j][d] = g_Av[ro];
        Vsm[j][d] = g_Ak[ro];
    }
    if (tid < 16) wk[tid] = 0.f;
    __syncthreads();
    const int q = tid;
    if (q < 195) {
        const float* Arow = g_Aq + ((size_t)(b*195 + q))*2304 + h*192;
        float s[16];
#pragma unroll
        for (int j = 0; j < 16; j++) s[j] = 0.f;
        for (int d = 0; d < 192; d += 4) {
            float4 qv = *(const float4*)(Arow + d);
#pragma unroll
            for (int j = 0; j < 16; j++)
                s[j] += qv.x*Ksm[j][d] + qv.y*Ksm[j][d+1] + qv.z*Ksm[j][d+2] + qv.w*Ksm[j][d+3];
        }
        float m = -1e30f;
#pragma unroll
        for (int j = 0; j < 16; j++) { s[j] *= SCALE_C; m = fmaxf(m, s[j]); }
        float sum = 0.f;
#pragma unroll
        for (int j = 0; j < 16; j++) { s[j] = expf(s[j] - m); sum += s[j]; }
        const float w = ((q == xi) ? 2.f : 1.f) / sum;
#pragma unroll
        for (int j = 0; j < 16; j++) atomicAdd(&wk[j], s[j] * w);
    }
    __syncthreads();
    if (tid < 192) {
        float o = 0.f;
#pragma unroll
        for (int j = 0; j < 16; j++) o += wk[j] * Vsm[j][tid];
        g_U[((size_t)b*17 + xi + 1)*2304 + h*192 + tid] = o;
    }
}

// ---------------------------------------------------------------------------
// scatter: out[b][s][:] = Ou[b][ s==0 ? 0 : 1+(s-1)%16 ][:]
// ---------------------------------------------------------------------------
__global__ void scatter_k(float* __restrict__ out) {
    size_t idx = (size_t)blockIdx.x * 256 + threadIdx.x;
    const size_t total = (size_t)8 * 3137 * 768;
    if (idx >= total) return;
    int b = (int)(idx / (3137*768));
    int r = (int)(idx % (3137*768));
    int s = r / 768, d = r - s*768;
    int row = (s == 0) ? 0 : 1 + (s - 1) % 16;
    out[idx] = g_Ou[((size_t)b*17 + row)*768 + d];
}

// ---------------------------------------------------------------------------
extern "C" void kernel_launch(void* const* d_in, const int* in_sizes, int n_in,
                              void* d_out, int out_size) {
    const float* x  = (const float*)d_in[0];
    const float* Wq = (const float*)d_in[1];
    const float* bq = (const float*)d_in[2];
    const float* Wk = (const float*)d_in[3];
    const float* bk = (const float*)d_in[4];
    const float* Wv = (const float*)d_in[5];
    const float* bv = (const float*)d_in[6];
    const float* Wt = (const float*)d_in[7];
    const float* bt = (const float*)d_in[8];
    const float* Wf = (const float*)d_in[9];
    const float* bf = (const float*)d_in[10];
    float* out = (float*)d_out;

    float *Pq, *Pk, *Pv, *tmp, *ti, *Aq, *Ak, *Av, *U, *Ou;
    cudaGetSymbolAddress((void**)&Pq,  g_Pq);
    cudaGetSymbolAddress((void**)&Pk,  g_Pk);
    cudaGetSymbolAddress((void**)&Pv,  g_Pv);
    cudaGetSymbolAddress((void**)&tmp, g_tmp);
    cudaGetSymbolAddress((void**)&ti,  g_ti);
    cudaGetSymbolAddress((void**)&Aq,  g_Aq);
    cudaGetSymbolAddress((void**)&Ak,  g_Ak);
    cudaGetSymbolAddress((void**)&Av,  g_Av);
    cudaGetSymbolAddress((void**)&U,   g_U);
    cudaGetSymbolAddress((void**)&Ou,  g_Ou);

    // rope tables
    rope_init_k<<<(3136*32 + 255)/256, 256>>>();

    // projections of full x: 25096 x 2304, K=768
    {
        dim3 grid(2304/128, (25096 + 127)/128);
        sgemm_k<<<grid, 256>>>(x, Wq, bq, Pq, 25096, 2304, 768);
        sgemm_k<<<grid, 256>>>(x, Wk, bk, Pk, 25096, 2304, 768);
        sgemm_k<<<grid, 256>>>(x, Wv, bv, Pv, 25096, 2304, 768);
    }

    // grouped frame attention -> tmp (1560 x 2304)
    grattn_k<<<dim3(195, 12, 8), 256>>>();

    // ti = tmp @ Wt + bt : 1560 x 768, K=2304
    sgemm_k<<<dim3(768/128, (1560 + 127)/128), 256>>>(tmp, Wt, bt, ti, 1560, 768, 2304);

    // Aq/Ak/Av = ti @ W? + b? : 1560 x 2304, K=768
    {
        dim3 grid(2304/128, (1560 + 127)/128);
        sgemm_k<<<grid, 256>>>(ti, Wq, bq, Aq, 1560, 2304, 768);
        sgemm_k<<<grid, 256>>>(ti, Wk, bk, Ak, 1560, 2304, 768);
        sgemm_k<<<grid, 256>>>(ti, Wv, bv, Av, 1560, 2304, 768);
    }

    // cls attention -> U row 0
    cls_k<<<dim3(12, 8), 256>>>();

    // xi = 0 attention -> U row 1
    s0_k<<<dim3(7, 7, 96), 256>>>();
    soft0_k<<<96, 256>>>();

    // xi = 1..15 -> U rows 2..16
    attn2x_k<<<dim3(15, 12, 8), 256>>>();

    // Ou = U @ Wf + bf : 136 x 768, K=2304
    sgemm64_k<<<dim3(768/64, (136 + 63)/64), 256>>>(U, Wf, bf, Ou, 136, 768, 2304);

    // broadcast to output
    scatter_k<<<(int)(((size_t)8*3137*768 + 255)/256), 256>>>(out);
}

// round 9
// speedup vs baseline: 1.9184x; 1.9184x over previous
#include <cuda_runtime.h>
#include <cuda_bf16.h>
#include <math.h>
#include <cstdint>

// ---------------------------------------------------------------------------
// dividedSpaceTimeAttention  (B=8, NH=12, DIM=768, NP=196, NF=16, DH=64)
// Round 5: tcgen05 unavailable (harness PTX targets compute_103, not 103a).
// Large GEMMs on mma.sync.m16n8k16 bf16 (HMMA) with 3xbf16 split precision,
// cp.async double-buffered 128x128x64 tiles, fp32 epilogue + bias.
// ---------------------------------------------------------------------------

#define SCALE_C (1.0f/96.0f)

// ------------------------- scratch (device globals) ------------------------
__device__ float g_Pq[57821184];          // 8*3137*2304
__device__ float g_Pk[57821184];
__device__ float g_Pv[57821184];
__device__ float g_tmp[8*195*2304];
__device__ float g_ti [8*195*768];
__device__ float g_Aq [8*195*2304];
__device__ float g_Ak [8*195*2304];
__device__ float g_Av [8*195*2304];
__device__ float g_S  [96*195*195];
__device__ float g_U  [8*17*2304];
__device__ float g_Ou [8*17*768];
__device__ float g_cos[3136*32];
__device__ float g_sin[3136*32];

// bf16 hi/lo operands (16B-aligned for cp.async)
__device__ __align__(256) __nv_bfloat16 g_xh [25096*768];
__device__ __align__(256) __nv_bfloat16 g_xl [25096*768];
__device__ __align__(256) __nv_bfloat16 g_Wqh[2304*768], g_Wql[2304*768];
__device__ __align__(256) __nv_bfloat16 g_Wkh[2304*768], g_Wkl[2304*768];
__device__ __align__(256) __nv_bfloat16 g_Wvh[2304*768], g_Wvl[2304*768];
__device__ __align__(256) __nv_bfloat16 g_Wth[768*2304], g_Wtl[768*2304];
__device__ __align__(256) __nv_bfloat16 g_th [1560*2304], g_tl [1560*2304];
__device__ __align__(256) __nv_bfloat16 g_tih[1560*768],  g_til[1560*768];

// ------------------------- helpers ---------------------------
__device__ __forceinline__ uint32_t smem_to_u32(const void* p) {
    uint32_t a;
    asm("{ .reg .u64 t; cvta.to.shared.u64 t, %1; cvt.u32.u64 %0, t; }"
        : "=r"(a) : "l"(p));
    return a;
}
#define CP_ASYNC16(dst, src) \
    asm volatile("cp.async.cg.shared.global [%0], [%1], 16;" :: "r"(dst), "l"(src))
#define CP_COMMIT() asm volatile("cp.async.commit_group;")

__device__ __forceinline__ void ldmatrix_x4(uint32_t* r, uint32_t addr) {
    asm volatile("ldmatrix.sync.aligned.m8n8.x4.shared.b16 {%0,%1,%2,%3}, [%4];"
        : "=r"(r[0]), "=r"(r[1]), "=r"(r[2]), "=r"(r[3]) : "r"(addr));
}
__device__ __forceinline__ void mma16816(float* c, const uint32_t* a, const uint32_t* b) {
    asm volatile("mma.sync.aligned.m16n8k16.row.col.f32.bf16.bf16.f32 "
        "{%0,%1,%2,%3}, {%4,%5,%6,%7}, {%8,%9}, {%0,%1,%2,%3};"
        : "+f"(c[0]), "+f"(c[1]), "+f"(c[2]), "+f"(c[3])
        : "r"(a[0]), "r"(a[1]), "r"(a[2]), "r"(a[3]), "r"(b[0]), "r"(b[1]));
}

// ---------------------------------------------------------------------------
// hgemm: C[M,N] = A[M,K] @ Bt[N,K]^T + bias, 3xbf16 split (hi/lo).
// grid (N/128, ceil(M/128)), 256 threads, dyn smem = 64 KB (2 x (16K A + 16K B)).
// ---------------------------------------------------------------------------
__global__ void __launch_bounds__(256) hgemm_k(
    const __nv_bfloat16* __restrict__ Ah, const __nv_bfloat16* __restrict__ Al,
    const __nv_bfloat16* __restrict__ Bh, const __nv_bfloat16* __restrict__ Bl,
    const float* __restrict__ bias, float* __restrict__ C,
    int M, int N, int K)
{
    extern __shared__ char smem[];
    const uint32_t sb = smem_to_u32(smem);
    const int tid = threadIdx.x;
    const int wid = tid >> 5, lane = tid & 31;
    const int bm = blockIdx.y * 128, bn = blockIdx.x * 128;
    const int wm = (wid >> 2) * 64;   // warp m offset: 0 or 64
    const int wn = (wid & 3) * 32;    // warp n offset: 0..96

    float acc[4][4][4];
#pragma unroll
    for (int i = 0; i < 4; i++)
#pragma unroll
        for (int j = 0; j < 4; j++)
#pragma unroll
            for (int r = 0; r < 4; r++) acc[i][j][r] = 0.f;

    const int KC = K >> 6;      // 64-wide k chunks per phase
    const int G = 3 * KC;       // 3 split phases

    const int lrow = tid >> 1;          // 0..127
    const int lc0 = (tid & 1) * 4;      // 16B-granule base (0 or 4)

    // --- issue loads for chunk g into buffer g&1 ---
    auto ISSUE = [&](int g) {
        const int phase = g / KC;
        const int k0 = (g - phase * KC) << 6;
        const __nv_bfloat16* Ag = (phase == 2) ? Al : Ah;
        const __nv_bfloat16* Bg = (phase == 1) ? Bl : Bh;
        const uint32_t abase = sb + (g & 1) * 32768;
        int ga = bm + lrow; if (ga >= M) ga = M - 1;   // clamp (rows >= M unused)
        const __nv_bfloat16* ap = Ag + (size_t)ga * K + k0 + lc0 * 8;
        const __nv_bfloat16* bp = Bg + (size_t)(bn + lrow) * K + k0 + lc0 * 8;
#pragma unroll
        for (int j = 0; j < 4; j++) {
            const uint32_t sw = (uint32_t)(lrow * 128 + (((lc0 + j) ^ (lrow & 7)) << 4));
            CP_ASYNC16(abase + sw, ap + j * 8);
            CP_ASYNC16(abase + 16384 + sw, bp + j * 8);
        }
        CP_COMMIT();
    };

    ISSUE(0);
    for (int g = 0; g < G; g++) {
        if (g + 1 < G) {
            ISSUE(g + 1);
            asm volatile("cp.async.wait_group 1;");
        } else {
            asm volatile("cp.async.wait_group 0;");
        }
        __syncthreads();
        const uint32_t abase = sb + (g & 1) * 32768;
        const uint32_t bbase = abase + 16384;
#pragma unroll
        for (int ks = 0; ks < 4; ks++) {
            uint32_t af[4][4], bfr[2][4];
#pragma unroll
            for (int mf = 0; mf < 4; mf++) {
                const int row = wm + mf * 16 + (lane & 15);
                const int c16 = ks * 2 + (lane >> 4);
                ldmatrix_x4(af[mf], abase + row * 128 + ((c16 ^ (row & 7)) << 4));
            }
#pragma unroll
            for (int nh = 0; nh < 2; nh++) {
                const int row = wn + nh * 16 + (lane & 7) + ((lane & 16) >> 1);
                const int c16 = ks * 2 + ((lane >> 3) & 1);
                ldmatrix_x4(bfr[nh], bbase + row * 128 + ((c16 ^ (row & 7)) << 4));
            }
#pragma unroll
            for (int mf = 0; mf < 4; mf++)
#pragma unroll
                for (int nf = 0; nf < 4; nf++)
                    mma16816(acc[mf][nf], af[mf], bfr[nf >> 1] + (nf & 1) * 2);
        }
        __syncthreads();
    }

    // epilogue
    const int r0 = lane >> 2;
    const int c0 = (lane & 3) * 2;
#pragma unroll
    for (int mf = 0; mf < 4; mf++) {
        const int row0 = bm + wm + mf * 16 + r0;
#pragma unroll
        for (int half = 0; half < 2; half++) {
            const int row = row0 + half * 8;
            if (row < M) {
                float* Cr = C + (size_t)row * N + bn + wn;
                const float* bp = bias + bn + wn;
#pragma unroll
                for (int nf = 0; nf < 4; nf++) {
                    const int col = nf * 8 + c0;
                    Cr[col]     = acc[mf][nf][half * 2 + 0] + bp[col];
                    Cr[col + 1] = acc[mf][nf][half * 2 + 1] + bp[col + 1];
                }
            }
        }
    }
}

// ---------------------------------------------------------------------------
// conversions
// ---------------------------------------------------------------------------
__global__ void conv_k(const float* __restrict__ s,
                       __nv_bfloat16* __restrict__ h, __nv_bfloat16* __restrict__ l,
                       int n) {
    int i = blockIdx.x * 256 + threadIdx.x;
    if (i >= n) return;
    float v = s[i];
    __nv_bfloat16 hv = __float2bfloat16(v);
    h[i] = hv;
    l[i] = __float2bfloat16(v - __bfloat162float(hv));
}

// W[K,N] -> Th/Tl[N,K] (transpose + split)
__global__ void wconv_k(const float* __restrict__ W,
                        __nv_bfloat16* __restrict__ Th, __nv_bfloat16* __restrict__ Tl,
                        int K, int N) {
    __shared__ float tile[32][33];
    const int k0 = blockIdx.x * 32, n0 = blockIdx.y * 32;
    const int tx = threadIdx.x, ty = threadIdx.y;
    for (int r = ty; r < 32; r += 8) {
        int k = k0 + r, n = n0 + tx;
        tile[r][tx] = (k < K && n < N) ? W[(size_t)k * N + n] : 0.f;
    }
    __syncthreads();
    for (int r = ty; r < 32; r += 8) {
        int n = n0 + r, k = k0 + tx;
        if (n < N && k < K) {
            float v = tile[tx][r];
            __nv_bfloat16 hv = __float2bfloat16(v);
            Th[(size_t)n * K + k] = hv;
            Tl[(size_t)n * K + k] = __float2bfloat16(v - __bfloat162float(hv));
        }
    }
}

// ---------------------------------------------------------------------------
__global__ void rope_init_k() {
    int idx = blockIdx.x * 256 + threadIdx.x;
    if (idx >= 3136*32) return;
    int s = idx >> 5, i = idx & 31;
    float e = (float)(2*i) / 64.f;
    float invf = 1.f / powf(10000.f, e);
    float ang = (float)s * invf;
    g_cos[idx] = (float)cos((double)ang);
    g_sin[idx] = (float)sin((double)ang);
}

// small fp32 GEMM (final 136-row): 64x64 tile, 4x4/thread
__global__ void __launch_bounds__(256) sgemm64_k(
    const float* __restrict__ A, const float* __restrict__ B,
    const float* __restrict__ bias, float* __restrict__ C,
    int M, int N, int K)
{
    __shared__ float As[8][64];
    __shared__ float Bs[8][64];
    const int bm = blockIdx.y * 64, bn = blockIdx.x * 64;
    const int tid = threadIdx.x;
    const int tx = tid & 15, ty = tid >> 4;
    const int arow = tid >> 2, acol = (tid & 3) * 2;
    const int brow = tid >> 5, bcol = (tid & 31) * 2;
    float acc[4][4];
#pragma unroll
    for (int i = 0; i < 4; i++)
#pragma unroll
        for (int j = 0; j < 4; j++) acc[i][j] = 0.f;
    const bool arow_ok = (bm + arow) < M;
    for (int k0 = 0; k0 < K; k0 += 8) {
        float2 av = make_float2(0.f, 0.f);
        if (arow_ok) av = *(const float2*)(A + (size_t)(bm + arow) * K + k0 + acol);
        As[acol][arow] = av.x;  As[acol + 1][arow] = av.y;
        float2 bv = *(const float2*)(B + (size_t)(k0 + brow) * N + bn + bcol);
        Bs[brow][bcol] = bv.x;  Bs[brow][bcol + 1] = bv.y;
        __syncthreads();
#pragma unroll
        for (int kk = 0; kk < 8; kk++) {
            float ar[4], br[4];
#pragma unroll
            for (int i = 0; i < 4; i++) ar[i] = As[kk][ty * 4 + i];
#pragma unroll
            for (int j = 0; j < 4; j++) br[j] = Bs[kk][tx * 4 + j];
#pragma unroll
            for (int i = 0; i < 4; i++)
#pragma unroll
                for (int j = 0; j < 4; j++)
                    acc[i][j] += ar[i] * br[j];
        }
        __syncthreads();
    }
#pragma unroll
    for (int i = 0; i < 4; i++) {
        int m = bm + ty * 4 + i;
        if (m < M)
#pragma unroll
            for (int j = 0; j < 4; j++)
                C[(size_t)m * N + bn + tx * 4 + j] = acc[i][j] + bias[bn + tx * 4 + j];
    }
}

// ---------------------------------------------------------------------------
// Grouped frame-attention
// ---------------------------------------------------------------------------
#define GA 193
__global__ void __launch_bounds__(256) grattn_k() {
    const int p = blockIdx.x + 1;
    const int h = blockIdx.y;
    const int b = blockIdx.z;
    __shared__ float qs[16*GA], ks[16*GA], vs[16*GA];
    __shared__ float S[256], wg[16];
    const int tid = threadIdx.x;

    for (int idx = tid; idx < 16*192; idx += 256) {
        int f = idx / 192, d = idx - f * 192;
        size_t off = ((size_t)(b * 3137 + 1 + f * 196 + p)) * 2304 + h * 192 + d;
        qs[f*GA + d] = g_Pq[off];
        ks[f*GA + d] = g_Pv[off];
        vs[f*GA + d] = g_Pk[off];
    }
    __syncthreads();
    for (int idx = tid; idx < 16*32; idx += 256) {
        int f = idx >> 5, i = idx & 31;
        int s = f * 196 + p;
        float c = g_cos[s*32 + i], sn = g_sin[s*32 + i];
        float a0 = qs[f*GA + 2*i], a1 = qs[f*GA + 2*i + 1];
        qs[f*GA + 2*i]     = a0 * c - a1 * sn;
        qs[f*GA + 2*i + 1] = a1 * c + a0 * sn;
        float b0 = ks[f*GA + 2*i], b1 = ks[f*GA + 2*i + 1];
        ks[f*GA + 2*i]     = b0 * c - b1 * sn;
        ks[f*GA + 2*i + 1] = b1 * c + b0 * sn;
    }
    __syncthreads();
    {
        int f = tid >> 4, g = tid & 15;
        const float* qp = qs + f * GA;
        const float* kp = ks + g * GA;
        float s = 0.f;
#pragma unroll 8
        for (int d = 0; d < 192; d++) s += qp[d] * kp[d];
        S[tid] = s * SCALE_C;
    }
    __syncthreads();
    if (tid < 16) {
        float m = -1e30f;
        for (int g = 0; g < 16; g++) m = fmaxf(m, S[tid*16 + g]);
        float sum = 0.f;
        for (int g = 0; g < 16; g++) { float e = expf(S[tid*16 + g] - m); S[tid*16 + g] = e; sum += e; }
        float inv = 1.f / sum;
        for (int g = 0; g < 16; g++) S[tid*16 + g] *= inv;
    }
    __syncthreads();
    if (tid < 16) {
        float a = 0.f;
        for (int f = 0; f < 16; f++) a += S[f*16 + tid];
        wg[tid] = a;
    }
    __syncthreads();
    if (tid < 192) {
        float o = 0.f;
#pragma unroll
        for (int g = 0; g < 16; g++) o += wg[g] * vs[g*GA + tid];
        g_tmp[((size_t)(b * 195 + (p - 1))) * 2304 + h * 192 + tid] = o;
    }
}

// ---------------------------------------------------------------------------
// CLS attention
// ---------------------------------------------------------------------------
__global__ void __launch_bounds__(256) cls_k() {
    const int h = blockIdx.x, b = blockIdx.y;
    __shared__ float qv[192];
    __shared__ float Sv[3137];
    __shared__ float red[256];
    const int tid = threadIdx.x;
    const float* Pq_ = g_Pq + (size_t)b*3137*2304 + h*192;
    const float* Pk_ = g_Pk + (size_t)b*3137*2304 + h*192;
    const float* Pv_ = g_Pv + (size_t)b*3137*2304 + h*192;
    if (tid < 192) qv[tid] = Pq_[tid];
    __syncthreads();
    float lm = -1e30f;
    for (int t = tid; t < 3137; t += 256) {
        const float* kr = Pk_ + (size_t)t*2304;
        float s = 0.f;
        for (int d = 0; d < 192; d += 4) {
            float4 k4 = *(const float4*)(kr + d);
            s += k4.x*qv[d] + k4.y*qv[d+1] + k4.z*qv[d+2] + k4.w*qv[d+3];
        }
        s *= SCALE_C;
        Sv[t] = s;
        lm = fmaxf(lm, s);
    }
    red[tid] = lm; __syncthreads();
    for (int s2 = 128; s2 > 0; s2 >>= 1) {
        if (tid < s2) red[tid] = fmaxf(red[tid], red[tid + s2]);
        __syncthreads();
    }
    const float m = red[0];
    __syncthreads();
    float ls = 0.f;
    for (int t = tid; t < 3137; t += 256) { float e = expf(Sv[t] - m); Sv[t] = e; ls += e; }
    red[tid] = ls; __syncthreads();
    for (int s2 = 128; s2 > 0; s2 >>= 1) {
        if (tid < s2) red[tid] += red[tid + s2];
        __syncthreads();
    }
    const float inv = 1.f / red[0];
    if (tid < 192) {
        float o = 0.f;
        const float* vp = Pv_ + tid;
        for (int t = 0; t < 3137; t++) o += Sv[t] * vp[(size_t)t*2304];
        g_U[((size_t)b*17 + 0)*2304 + h*192 + tid] = o * inv;
    }
}

// ---------------------------------------------------------------------------
// xi=0 scores
// ---------------------------------------------------------------------------
__global__ void __launch_bounds__(256) s0_k() {
    const int bh = blockIdx.z;
    const int b = bh / 12, h = bh % 12;
    const int i0 = blockIdx.y * 32, j0 = blockIdx.x * 32;
    __shared__ float Qs[16][33], Ks[16][33];
    const int tid = threadIdx.x;
    const int tx = tid & 15, ty = tid >> 4;
    const float* Abase = g_Aq + (size_t)b*195*2304 + h*192;
    const float* Bbase = g_Av + (size_t)b*195*2304 + h*192;
    float acc00 = 0.f, acc01 = 0.f, acc10 = 0.f, acc11 = 0.f;
    const int r = tid >> 3;
    const int c = (tid & 7) * 2;
    for (int k0 = 0; k0 < 192; k0 += 16) {
        int qi = i0 + r;
        float2 qv = make_float2(0.f, 0.f);
        if (qi < 195) qv = *(const float2*)(Abase + (size_t)qi*2304 + k0 + c);
        Qs[c][r] = qv.x; Qs[c+1][r] = qv.y;
        int kj = j0 + r;
        float2 kv = make_float2(0.f, 0.f);
        if (kj < 195) kv = *(const float2*)(Bbase + (size_t)kj*2304 + k0 + c);
        Ks[c][r] = kv.x; Ks[c+1][r] = kv.y;
        __syncthreads();
#pragma unroll
        for (int kk = 0; kk < 16; kk++) {
            float a0 = Qs[kk][ty*2], a1 = Qs[kk][ty*2+1];
            float b0 = Ks[kk][tx*2], b1 = Ks[kk][tx*2+1];
            acc00 += a0*b0; acc01 += a0*b1; acc10 += a1*b0; acc11 += a1*b1;
        }
        __syncthreads();
    }
    float* Sp = g_S + (size_t)bh*195*195;
    int ii = i0 + ty*2, jj = j0 + tx*2;
    if (ii < 195) {
        if (jj   < 195) Sp[(size_t)ii*195 + jj  ] = acc00 * SCALE_C;
        if (jj+1 < 195) Sp[(size_t)ii*195 + jj+1] = acc01 * SCALE_C;
    }
    if (ii+1 < 195) {
        if (jj   < 195) Sp[(size_t)(ii+1)*195 + jj  ] = acc10 * SCALE_C;
        if (jj+1 < 195) Sp[(size_t)(ii+1)*195 + jj+1] = acc11 * SCALE_C;
    }
}

// ---------------------------------------------------------------------------
// xi=0 softmax + w@V
// ---------------------------------------------------------------------------
__global__ void __launch_bounds__(256) soft0_k() {
    const int bh = blockIdx.x;
    const int b = bh / 12, h = bh % 12;
    const float* S = g_S + (size_t)bh*195*195;
    __shared__ float wk_s[195];
    const int tid = threadIdx.x;
    if (tid < 195) wk_s[tid] = 0.f;
    __syncthreads();
    const int warp = tid >> 5, lane = tid & 31;
    for (int q = warp; q < 195; q += 8) {
        const float* Sq = S + (size_t)q*195;
        float m = -1e30f;
        for (int k = lane; k < 195; k += 32) m = fmaxf(m, Sq[k]);
        for (int o = 16; o; o >>= 1) m = fmaxf(m, __shfl_xor_sync(0xFFFFFFFFu, m, o));
        float sum = 0.f;
        for (int k = lane; k < 195; k += 32) sum += expf(Sq[k] - m);
        if (lane == 0) sum += expf(Sq[0] - m);
        for (int o = 16; o; o >>= 1) sum += __shfl_xor_sync(0xFFFFFFFFu, sum, o);
        const float inv = 1.f / sum;
        const float mult = (q == 0) ? 2.f : 1.f;
        for (int k = lane; k < 195; k += 32) {
            float w = expf(Sq[k] - m) * inv * mult;
            if (k == 0) w *= 2.f;
            atomicAdd(&wk_s[k], w);
        }
    }
    __syncthreads();
    if (tid < 192) {
        const float* V = g_Ak + (size_t)b*195*2304 + h*192 + tid;
        float o = 0.f;
        for (int k = 0; k < 195; k++) o += wk_s[k] * V[(size_t)k*2304];
        g_U[((size_t)b*17 + 1)*2304 + h*192 + tid] = o;
    }
}

// ---------------------------------------------------------------------------
// xi=1..15
// ---------------------------------------------------------------------------
__global__ void __launch_bounds__(256) attn2x_k() {
    const int xi = blockIdx.x + 1;
    const int h = blockIdx.y, b = blockIdx.z;
    __shared__ float Ksm[16][192];
    __shared__ float Vsm[16][192];
    __shared__ float wk[16];
    const int tid = threadIdx.x;
    for (int idx = tid; idx < 16*192; idx += 256) {
        int j = idx / 192, d = idx - j*192;
        size_t ro = ((size_t)(b*195 + xi + j))*2304 + h*192 + d;
        Ksm[j][d] = g_Av[ro];
        Vsm[j][d] = g_Ak[ro];
    }
    if (tid < 16) wk[tid] = 0.f;
    __syncthreads();
    const int q = tid;
    if (q < 195) {
        const float* Arow = g_Aq + ((size_t)(b*195 + q))*2304 + h*192;
        float s[16];
#pragma unroll
        for (int j = 0; j < 16; j++) s[j] = 0.f;
        for (int d = 0; d < 192; d += 4) {
            float4 qv = *(const float4*)(Arow + d);
#pragma unroll
            for (int j = 0; j < 16; j++)
                s[j] += qv.x*Ksm[j][d] + qv.y*Ksm[j][d+1] + qv.z*Ksm[j][d+2] + qv.w*Ksm[j][d+3];
        }
        float m = -1e30f;
#pragma unroll
        for (int j = 0; j < 16; j++) { s[j] *= SCALE_C; m = fmaxf(m, s[j]); }
        float sum = 0.f;
#pragma unroll
        for (int j = 0; j < 16; j++) { s[j] = expf(s[j] - m); sum += s[j]; }
        const float w = ((q == xi) ? 2.f : 1.f) / sum;
#pragma unroll
        for (int j = 0; j < 16; j++) atomicAdd(&wk[j], s[j] * w);
    }
    __syncthreads();
    if (tid < 192) {
        float o = 0.f;
#pragma unroll
        for (int j = 0; j < 16; j++) o += wk[j] * Vsm[j][tid];
        g_U[((size_t)b*17 + xi + 1)*2304 + h*192 + tid] = o;
    }
}

// ---------------------------------------------------------------------------
__global__ void scatter_k(float* __restrict__ out) {
    size_t idx = (size_t)blockIdx.x * 256 + threadIdx.x;
    const size_t total = (size_t)8 * 3137 * 768;
    if (idx >= total) return;
    int b = (int)(idx / (3137*768));
    int r = (int)(idx % (3137*768));
    int s = r / 768, d = r - s*768;
    int row = (s == 0) ? 0 : 1 + (s - 1) % 16;
    out[idx] = g_Ou[((size_t)b*17 + row)*768 + d];
}

// ---------------------------------------------------------------------------
extern "C" void kernel_launch(void* const* d_in, const int* in_sizes, int n_in,
                              void* d_out, int out_size) {
    const float* x  = (const float*)d_in[0];
    const float* Wq = (const float*)d_in[1];
    const float* bq = (const float*)d_in[2];
    const float* Wk = (const float*)d_in[3];
    const float* bk = (const float*)d_in[4];
    const float* Wv = (const float*)d_in[5];
    const float* bv = (const float*)d_in[6];
    const float* Wt = (const float*)d_in[7];
    const float* bt = (const float*)d_in[8];
    const float* Wf = (const float*)d_in[9];
    const float* bf = (const float*)d_in[10];
    float* out = (float*)d_out;

    float *Pq, *Pk, *Pv, *tmp, *ti, *Aq, *Ak, *Av, *U, *Ou;
    cudaGetSymbolAddress((void**)&Pq,  g_Pq);
    cudaGetSymbolAddress((void**)&Pk,  g_Pk);
    cudaGetSymbolAddress((void**)&Pv,  g_Pv);
    cudaGetSymbolAddress((void**)&tmp, g_tmp);
    cudaGetSymbolAddress((void**)&ti,  g_ti);
    cudaGetSymbolAddress((void**)&Aq,  g_Aq);
    cudaGetSymbolAddress((void**)&Ak,  g_Ak);
    cudaGetSymbolAddress((void**)&Av,  g_Av);
    cudaGetSymbolAddress((void**)&U,   g_U);
    cudaGetSymbolAddress((void**)&Ou,  g_Ou);

    __nv_bfloat16 *xh, *xl, *Wqh, *Wql, *Wkh, *Wkl, *Wvh, *Wvl, *Wth, *Wtl;
    __nv_bfloat16 *th, *tl, *tih, *til;
    cudaGetSymbolAddress((void**)&xh,  g_xh);
    cudaGetSymbolAddress((void**)&xl,  g_xl);
    cudaGetSymbolAddress((void**)&Wqh, g_Wqh);
    cudaGetSymbolAddress((void**)&Wql, g_Wql);
    cudaGetSymbolAddress((void**)&Wkh, g_Wkh);
    cudaGetSymbolAddress((void**)&Wkl, g_Wkl);
    cudaGetSymbolAddress((void**)&Wvh, g_Wvh);
    cudaGetSymbolAddress((void**)&Wvl, g_Wvl);
    cudaGetSymbolAddress((void**)&Wth, g_Wth);
    cudaGetSymbolAddress((void**)&Wtl, g_Wtl);
    cudaGetSymbolAddress((void**)&th,  g_th);
    cudaGetSymbolAddress((void**)&tl,  g_tl);
    cudaGetSymbolAddress((void**)&tih, g_tih);
    cudaGetSymbolAddress((void**)&til, g_til);

    const int HG_SMEM = 65536;
    cudaFuncSetAttribute(hgemm_k, cudaFuncAttributeMaxDynamicSharedMemorySize, HG_SMEM);

    rope_init_k<<<(3136*32 + 255)/256, 256>>>();

    // convert inputs + weights to hi/lo bf16
    conv_k<<<(25096*768 + 255)/256, 256>>>(x, xh, xl, 25096*768);
    {
        dim3 wb(32, 8);
        dim3 wg(768/32, 2304/32);
        wconv_k<<<wg, wb>>>(Wq, Wqh, Wql, 768, 2304);
        wconv_k<<<wg, wb>>>(Wk, Wkh, Wkl, 768, 2304);
        wconv_k<<<wg, wb>>>(Wv, Wvh, Wvl, 768, 2304);
        dim3 wg2(2304/32, 768/32);
        wconv_k<<<wg2, wb>>>(Wt, Wth, Wtl, 2304, 768);
    }

    // projections of full x: 25096 x 2304, K=768 (HMMA)
    {
        dim3 grid(2304/128, (25096 + 127)/128);
        hgemm_k<<<grid, 256, HG_SMEM>>>(xh, xl, Wqh, Wql, bq, Pq, 25096, 2304, 768);
        hgemm_k<<<grid, 256, HG_SMEM>>>(xh, xl, Wkh, Wkl, bk, Pk, 25096, 2304, 768);
        hgemm_k<<<grid, 256, HG_SMEM>>>(xh, xl, Wvh, Wvl, bv, Pv, 25096, 2304, 768);
    }

    // grouped frame attention -> tmp (1560 x 2304)
    grattn_k<<<dim3(195, 12, 8), 256>>>();

    // ti = tmp @ Wt + bt : 1560 x 768, K=2304
    conv_k<<<(1560*2304 + 255)/256, 256>>>(tmp, th, tl, 1560*2304);
    hgemm_k<<<dim3(768/128, (1560 + 127)/128), 256, HG_SMEM>>>(
        th, tl, Wth, Wtl, bt, ti, 1560, 768, 2304);

    // Aq/Ak/Av = ti @ W? + b? : 1560 x 2304, K=768
    conv_k<<<(1560*768 + 255)/256, 256>>>(ti, tih, til, 1560*768);
    {
        dim3 grid(2304/128, (1560 + 127)/128);
        hgemm_k<<<grid, 256, HG_SMEM>>>(tih, til, Wqh, Wql, bq, Aq, 1560, 2304, 768);
        hgemm_k<<<grid, 256, HG_SMEM>>>(tih, til, Wkh, Wkl, bk, Ak, 1560, 2304, 768);
        hgemm_k<<<grid, 256, HG_SMEM>>>(tih, til, Wvh, Wvl, bv, Av, 1560, 2304, 768);
    }

    // cls attention -> U row 0
    cls_k<<<dim3(12, 8), 256>>>();

    // xi = 0 attention -> U row 1
    s0_k<<<dim3(7, 7, 96), 256>>>();
    soft0_k<<<96, 256>>>();

    // xi = 1..15 -> U rows 2..16
    attn2x_k<<<dim3(15, 12, 8), 256>>>();

    // Ou = U @ Wf + bf : 136 x 768, K=2304 (tiny, fp32)
    sgemm64_k<<<dim3(768/64, (136 + 63)/64), 256>>>(U, Wf, bf, Ou, 136, 768, 2304);

    // broadcast to output
    scatter_k<<<(int)(((size_t)8*3137*768 + 255)/256), 256>>>(out);
}

// round 11
// speedup vs baseline: 2.0751x; 1.0817x over previous
#include <cuda_runtime.h>
#include <cuda_bf16.h>
#include <math.h>
#include <cstdint>

// ---------------------------------------------------------------------------
// dividedSpaceTimeAttention  (B=8, NH=12, DIM=768, NP=196, NF=16, DH=64)
// Round 9: fused-split HMMA GEMM — Ah/Al/Bh/Bl tiles loaded once per k-chunk,
// all three split products issued per load (1.5x less tile traffic, 3x fewer
// syncs). cls_k parallelized to 512 threads.
// ---------------------------------------------------------------------------

#define SCALE_C (1.0f/96.0f)

// ------------------------- scratch (device globals) ------------------------
__device__ float g_Pq[57821184];          // 8*3137*2304
__device__ float g_Pk[57821184];
__device__ float g_Pv[57821184];
__device__ float g_tmp[8*195*2304];
__device__ float g_ti [8*195*768];
__device__ float g_Aq [8*195*2304];
__device__ float g_Ak [8*195*2304];
__device__ float g_Av [8*195*2304];
__device__ float g_S  [96*195*195];
__device__ float g_U  [8*17*2304];
__device__ float g_Ou [8*17*768];
__device__ float g_cos[3136*32];
__device__ float g_sin[3136*32];

// bf16 hi/lo operands (aligned for cp.async)
__device__ __align__(256) __nv_bfloat16 g_xh [25096*768];
__device__ __align__(256) __nv_bfloat16 g_xl [25096*768];
__device__ __align__(256) __nv_bfloat16 g_Wqh[2304*768], g_Wql[2304*768];
__device__ __align__(256) __nv_bfloat16 g_Wkh[2304*768], g_Wkl[2304*768];
__device__ __align__(256) __nv_bfloat16 g_Wvh[2304*768], g_Wvl[2304*768];
__device__ __align__(256) __nv_bfloat16 g_Wth[768*2304], g_Wtl[768*2304];
__device__ __align__(256) __nv_bfloat16 g_th [1560*2304], g_tl [1560*2304];
__device__ __align__(256) __nv_bfloat16 g_tih[1560*768],  g_til[1560*768];

// ------------------------- helpers ---------------------------
__device__ __forceinline__ uint32_t smem_to_u32(const void* p) {
    uint32_t a;
    asm("{ .reg .u64 t; cvta.to.shared.u64 t, %1; cvt.u32.u64 %0, t; }"
        : "=r"(a) : "l"(p));
    return a;
}
#define CP_ASYNC16(dst, src) \
    asm volatile("cp.async.cg.shared.global [%0], [%1], 16;" :: "r"(dst), "l"(src))
#define CP_COMMIT() asm volatile("cp.async.commit_group;")

__device__ __forceinline__ void ldmatrix_x4(uint32_t* r, uint32_t addr) {
    asm volatile("ldmatrix.sync.aligned.m8n8.x4.shared.b16 {%0,%1,%2,%3}, [%4];"
        : "=r"(r[0]), "=r"(r[1]), "=r"(r[2]), "=r"(r[3]) : "r"(addr));
}
__device__ __forceinline__ void mma16816(float* c, const uint32_t* a, const uint32_t* b) {
    asm volatile("mma.sync.aligned.m16n8k16.row.col.f32.bf16.bf16.f32 "
        "{%0,%1,%2,%3}, {%4,%5,%6,%7}, {%8,%9}, {%0,%1,%2,%3};"
        : "+f"(c[0]), "+f"(c[1]), "+f"(c[2]), "+f"(c[3])
        : "r"(a[0]), "r"(a[1]), "r"(a[2]), "r"(a[3]), "r"(b[0]), "r"(b[1]));
}

// ---------------------------------------------------------------------------
// hgemm (fused split): C[M,N] = (Ah+Al)(Bh+Bl)^T + bias, dropping Al*Bl.
// Per 64-wide k-chunk, load Ah/Al/Bh/Bl tiles once, issue AhBh + AlBh + AhBl.
// grid (N/128, ceil(M/128)), 256 threads, dyn smem = 128 KB (2 x 64 KB stage).
// Stage layout: [Ah 16K][Al 16K][Bh 16K][Bl 16K]
// ---------------------------------------------------------------------------
__global__ void __launch_bounds__(256, 1) hgemm_k(
    const __nv_bfloat16* __restrict__ Ah, const __nv_bfloat16* __restrict__ Al,
    const __nv_bfloat16* __restrict__ Bh, const __nv_bfloat16* __restrict__ Bl,
    const float* __restrict__ bias, float* __restrict__ C,
    int M, int N, int K)
{
    extern __shared__ char smem[];
    const uint32_t sb = smem_to_u32(smem);
    const int tid = threadIdx.x;
    const int wid = tid >> 5, lane = tid & 31;
    const int bm = blockIdx.y * 128, bn = blockIdx.x * 128;
    const int wm = (wid >> 2) * 64;   // warp m offset: 0 or 64
    const int wn = (wid & 3) * 32;    // warp n offset: 0..96

    float acc[4][4][4];
#pragma unroll
    for (int i = 0; i < 4; i++)
#pragma unroll
        for (int j = 0; j < 4; j++)
#pragma unroll
            for (int r = 0; r < 4; r++) acc[i][j][r] = 0.f;

    const int G = K >> 6;               // 64-wide k-chunks
    const int lrow = tid >> 1;          // 0..127
    const int lc0 = (tid & 1) * 4;      // 16B-granule base (0 or 4)

    auto ISSUE = [&](int g) {
        const int k0 = g << 6;
        const uint32_t base = sb + (g & 1) * 65536;
        int ga = bm + lrow; if (ga >= M) ga = M - 1;   // clamp (extra rows unused)
        const size_t aoff = (size_t)ga * K + k0 + lc0 * 8;
        const size_t boff = (size_t)(bn + lrow) * K + k0 + lc0 * 8;
        const __nv_bfloat16* ahp = Ah + aoff;
        const __nv_bfloat16* alp = Al + aoff;
        const __nv_bfloat16* bhp = Bh + boff;
        const __nv_bfloat16* blp = Bl + boff;
#pragma unroll
        for (int j = 0; j < 4; j++) {
            const uint32_t sw = (uint32_t)(lrow * 128 + (((lc0 + j) ^ (lrow & 7)) << 4));
            CP_ASYNC16(base + sw,         ahp + j * 8);
            CP_ASYNC16(base + 16384 + sw, alp + j * 8);
            CP_ASYNC16(base + 32768 + sw, bhp + j * 8);
            CP_ASYNC16(base + 49152 + sw, blp + j * 8);
        }
        CP_COMMIT();
    };

    ISSUE(0);
    for (int g = 0; g < G; g++) {
        if (g + 1 < G) {
            ISSUE(g + 1);
            asm volatile("cp.async.wait_group 1;");
        } else {
            asm volatile("cp.async.wait_group 0;");
        }
        __syncthreads();
        const uint32_t base = sb + (g & 1) * 65536;
#pragma unroll
        for (int ks = 0; ks < 4; ks++) {
            uint32_t ah[4][4], al[4][4], bb[2][4];
            // A fragment addresses
#pragma unroll
            for (int mf = 0; mf < 4; mf++) {
                const int row = wm + mf * 16 + (lane & 15);
                const int c16 = ks * 2 + (lane >> 4);
                const uint32_t off = row * 128 + ((c16 ^ (row & 7)) << 4);
                ldmatrix_x4(ah[mf], base + off);
                ldmatrix_x4(al[mf], base + 16384 + off);
            }
            // B hi fragments
#pragma unroll
            for (int nh = 0; nh < 2; nh++) {
                const int row = wn + nh * 16 + (lane & 7) + ((lane & 16) >> 1);
                const int c16 = ks * 2 + ((lane >> 3) & 1);
                ldmatrix_x4(bb[nh], base + 32768 + row * 128 + ((c16 ^ (row & 7)) << 4));
            }
            // Ah*Bh and Al*Bh
#pragma unroll
            for (int mf = 0; mf < 4; mf++)
#pragma unroll
                for (int nf = 0; nf < 4; nf++)
                    mma16816(acc[mf][nf], ah[mf], bb[nf >> 1] + (nf & 1) * 2);
#pragma unroll
            for (int mf = 0; mf < 4; mf++)
#pragma unroll
                for (int nf = 0; nf < 4; nf++)
                    mma16816(acc[mf][nf], al[mf], bb[nf >> 1] + (nf & 1) * 2);
            // B lo fragments (reuse bb regs), Ah*Bl
#pragma unroll
            for (int nh = 0; nh < 2; nh++) {
                const int row = wn + nh * 16 + (lane & 7) + ((lane & 16) >> 1);
                const int c16 = ks * 2 + ((lane >> 3) & 1);
                ldmatrix_x4(bb[nh], base + 49152 + row * 128 + ((c16 ^ (row & 7)) << 4));
            }
#pragma unroll
            for (int mf = 0; mf < 4; mf++)
#pragma unroll
                for (int nf = 0; nf < 4; nf++)
                    mma16816(acc[mf][nf], ah[mf], bb[nf >> 1] + (nf & 1) * 2);
        }
        __syncthreads();
    }

    // epilogue
    const int r0 = lane >> 2;
    const int c0 = (lane & 3) * 2;
#pragma unroll
    for (int mf = 0; mf < 4; mf++) {
        const int row0 = bm + wm + mf * 16 + r0;
#pragma unroll
        for (int half = 0; half < 2; half++) {
            const int row = row0 + half * 8;
            if (row < M) {
                float* Cr = C + (size_t)row * N + bn + wn;
                const float* bp = bias + bn + wn;
#pragma unroll
                for (int nf = 0; nf < 4; nf++) {
                    const int col = nf * 8 + c0;
                    Cr[col]     = acc[mf][nf][half * 2 + 0] + bp[col];
                    Cr[col + 1] = acc[mf][nf][half * 2 + 1] + bp[col + 1];
                }
            }
        }
    }
}

// ---------------------------------------------------------------------------
// conversions
// ---------------------------------------------------------------------------
__global__ void conv_k(const float* __restrict__ s,
                       __nv_bfloat16* __restrict__ h, __nv_bfloat16* __restrict__ l,
                       int n) {
    int i = blockIdx.x * 256 + threadIdx.x;
    if (i >= n) return;
    float v = s[i];
    __nv_bfloat16 hv = __float2bfloat16(v);
    h[i] = hv;
    l[i] = __float2bfloat16(v - __bfloat162float(hv));
}

// W[K,N] -> Th/Tl[N,K] (transpose + split)
__global__ void wconv_k(const float* __restrict__ W,
                        __nv_bfloat16* __restrict__ Th, __nv_bfloat16* __restrict__ Tl,
                        int K, int N) {
    __shared__ float tile[32][33];
    const int k0 = blockIdx.x * 32, n0 = blockIdx.y * 32;
    const int tx = threadIdx.x, ty = threadIdx.y;
    for (int r = ty; r < 32; r += 8) {
        int k = k0 + r, n = n0 + tx;
        tile[r][tx] = (k < K && n < N) ? W[(size_t)k * N + n] : 0.f;
    }
    __syncthreads();
    for (int r = ty; r < 32; r += 8) {
        int n = n0 + r, k = k0 + tx;
        if (n < N && k < K) {
            float v = tile[tx][r];
            __nv_bfloat16 hv = __float2bfloat16(v);
            Th[(size_t)n * K + k] = hv;
            Tl[(size_t)n * K + k] = __float2bfloat16(v - __bfloat162float(hv));
        }
    }
}

// ---------------------------------------------------------------------------
__global__ void rope_init_k() {
    int idx = blockIdx.x * 256 + threadIdx.x;
    if (idx >= 3136*32) return;
    int s = idx >> 5, i = idx & 31;
    float e = (float)(2*i) / 64.f;
    float invf = 1.f / powf(10000.f, e);
    float ang = (float)s * invf;
    g_cos[idx] = (float)cos((double)ang);
    g_sin[idx] = (float)sin((double)ang);
}

// small fp32 GEMM (final 136-row): 64x64 tile, 4x4/thread
__global__ void __launch_bounds__(256) sgemm64_k(
    const float* __restrict__ A, const float* __restrict__ B,
    const float* __restrict__ bias, float* __restrict__ C,
    int M, int N, int K)
{
    __shared__ float As[8][64];
    __shared__ float Bs[8][64];
    const int bm = blockIdx.y * 64, bn = blockIdx.x * 64;
    const int tid = threadIdx.x;
    const int tx = tid & 15, ty = tid >> 4;
    const int arow = tid >> 2, acol = (tid & 3) * 2;
    const int brow = tid >> 5, bcol = (tid & 31) * 2;
    float acc[4][4];
#pragma unroll
    for (int i = 0; i < 4; i++)
#pragma unroll
        for (int j = 0; j < 4; j++) acc[i][j] = 0.f;
    const bool arow_ok = (bm + arow) < M;
    for (int k0 = 0; k0 < K; k0 += 8) {
        float2 av = make_float2(0.f, 0.f);
        if (arow_ok) av = *(const float2*)(A + (size_t)(bm + arow) * K + k0 + acol);
        As[acol][arow] = av.x;  As[acol + 1][arow] = av.y;
        float2 bv = *(const float2*)(B + (size_t)(k0 + brow) * N + bn + bcol);
        Bs[brow][bcol] = bv.x;  Bs[brow][bcol + 1] = bv.y;
        __syncthreads();
#pragma unroll
        for (int kk = 0; kk < 8; kk++) {
            float ar[4], br[4];
#pragma unroll
            for (int i = 0; i < 4; i++) ar[i] = As[kk][ty * 4 + i];
#pragma unroll
            for (int j = 0; j < 4; j++) br[j] = Bs[kk][tx * 4 + j];
#pragma unroll
            for (int i = 0; i < 4; i++)
#pragma unroll
                for (int j = 0; j < 4; j++)
                    acc[i][j] += ar[i] * br[j];
        }
        __syncthreads();
    }
#pragma unroll
    for (int i = 0; i < 4; i++) {
        int m = bm + ty * 4 + i;
        if (m < M)
#pragma unroll
            for (int j = 0; j < 4; j++)
                C[(size_t)m * N + bn + tx * 4 + j] = acc[i][j] + bias[bn + tx * 4 + j];
    }
}

// ---------------------------------------------------------------------------
// Grouped frame-attention
// ---------------------------------------------------------------------------
#define GA 193
__global__ void __launch_bounds__(256) grattn_k() {
    const int p = blockIdx.x + 1;
    const int h = blockIdx.y;
    const int b = blockIdx.z;
    __shared__ float qs[16*GA], ks[16*GA], vs[16*GA];
    __shared__ float S[256], wg[16];
    const int tid = threadIdx.x;

    for (int idx = tid; idx < 16*192; idx += 256) {
        int f = idx / 192, d = idx - f * 192;
        size_t off = ((size_t)(b * 3137 + 1 + f * 196 + p)) * 2304 + h * 192 + d;
        qs[f*GA + d] = g_Pq[off];
        ks[f*GA + d] = g_Pv[off];
        vs[f*GA + d] = g_Pk[off];
    }
    __syncthreads();
    for (int idx = tid; idx < 16*32; idx += 256) {
        int f = idx >> 5, i = idx & 31;
        int s = f * 196 + p;
        float c = g_cos[s*32 + i], sn = g_sin[s*32 + i];
        float a0 = qs[f*GA + 2*i], a1 = qs[f*GA + 2*i + 1];
        qs[f*GA + 2*i]     = a0 * c - a1 * sn;
        qs[f*GA + 2*i + 1] = a1 * c + a0 * sn;
        float b0 = ks[f*GA + 2*i], b1 = ks[f*GA + 2*i + 1];
        ks[f*GA + 2*i]     = b0 * c - b1 * sn;
        ks[f*GA + 2*i + 1] = b1 * c + b0 * sn;
    }
    __syncthreads();
    {
        int f = tid >> 4, g = tid & 15;
        const float* qp = qs + f * GA;
        const float* kp = ks + g * GA;
        float s = 0.f;
#pragma unroll 8
        for (int d = 0; d < 192; d++) s += qp[d] * kp[d];
        S[tid] = s * SCALE_C;
    }
    __syncthreads();
    if (tid < 16) {
        float m = -1e30f;
        for (int g = 0; g < 16; g++) m = fmaxf(m, S[tid*16 + g]);
        float sum = 0.f;
        for (int g = 0; g < 16; g++) { float e = expf(S[tid*16 + g] - m); S[tid*16 + g] = e; sum += e; }
        float inv = 1.f / sum;
        for (int g = 0; g < 16; g++) S[tid*16 + g] *= inv;
    }
    __syncthreads();
    if (tid < 16) {
        float a = 0.f;
        for (int f = 0; f < 16; f++) a += S[f*16 + tid];
        wg[tid] = a;
    }
    __syncthreads();
    if (tid < 192) {
        float o = 0.f;
#pragma unroll
        for (int g = 0; g < 16; g++) o += wg[g] * vs[g*GA + tid];
        g_tmp[((size_t)(b * 195 + (p - 1))) * 2304 + h * 192 + tid] = o;
    }
}

// ---------------------------------------------------------------------------
// CLS attention: 512 threads, warp-parallel w@V
// ---------------------------------------------------------------------------
__global__ void __launch_bounds__(512) cls_k() {
    const int h = blockIdx.x, b = blockIdx.y;
    __shared__ float qv[192];
    __shared__ float Sv[3137];
    __shared__ float red[512];
    __shared__ float red2[16][192];
    const int tid = threadIdx.x;
    const int warp = tid >> 5, lane = tid & 31;
    const float* Pq_ = g_Pq + (size_t)b*3137*2304 + h*192;
    const float* Pk_ = g_Pk + (size_t)b*3137*2304 + h*192;
    const float* Pv_ = g_Pv + (size_t)b*3137*2304 + h*192;
    if (tid < 192) qv[tid] = Pq_[tid];
    __syncthreads();
    float lm = -1e30f;
    for (int t = tid; t < 3137; t += 512) {
        const float* kr = Pk_ + (size_t)t*2304;
        float s = 0.f;
        for (int d = 0; d < 192; d += 4) {
            float4 k4 = *(const float4*)(kr + d);
            s += k4.x*qv[d] + k4.y*qv[d+1] + k4.z*qv[d+2] + k4.w*qv[d+3];
        }
        s *= SCALE_C;
        Sv[t] = s;
        lm = fmaxf(lm, s);
    }
    red[tid] = lm; __syncthreads();
    for (int s2 = 256; s2 > 0; s2 >>= 1) {
        if (tid < s2) red[tid] = fmaxf(red[tid], red[tid + s2]);
        __syncthreads();
    }
    const float m = red[0];
    __syncthreads();
    float ls = 0.f;
    for (int t = tid; t < 3137; t += 512) { float e = expf(Sv[t] - m); Sv[t] = e; ls += e; }
    red[tid] = ls; __syncthreads();
    for (int s2 = 256; s2 > 0; s2 >>= 1) {
        if (tid < s2) red[tid] += red[tid + s2];
        __syncthreads();
    }
    const float inv = 1.f / red[0];
    // w@V: warp w handles keys t = w, w+16, ...; lane owns dims i*32+lane
    float o[6];
#pragma unroll
    for (int i = 0; i < 6; i++) o[i] = 0.f;
    for (int t = warp; t < 3137; t += 16) {
        const float w = Sv[t];
        const float* vr = Pv_ + (size_t)t*2304;
#pragma unroll
        for (int i = 0; i < 6; i++) o[i] += w * vr[i*32 + lane];
    }
#pragma unroll
    for (int i = 0; i < 6; i++) red2[warp][i*32 + lane] = o[i];
    __syncthreads();
    if (tid < 192) {
        float s = 0.f;
#pragma unroll
        for (int w = 0; w < 16; w++) s += red2[w][tid];
        g_U[((size_t)b*17 + 0)*2304 + h*192 + tid] = s * inv;
    }
}

// ---------------------------------------------------------------------------
// xi=0 scores
// ---------------------------------------------------------------------------
__global__ void __launch_bounds__(256) s0_k() {
    const int bh = blockIdx.z;
    const int b = bh / 12, h = bh % 12;
    const int i0 = blockIdx.y * 32, j0 = blockIdx.x * 32;
    __shared__ float Qs[16][33], Ks[16][33];
    const int tid = threadIdx.x;
    const int tx = tid & 15, ty = tid >> 4;
    const float* Abase = g_Aq + (size_t)b*195*2304 + h*192;
    const float* Bbase = g_Av + (size_t)b*195*2304 + h*192;
    float acc00 = 0.f, acc01 = 0.f, acc10 = 0.f, acc11 = 0.f;
    const int r = tid >> 3;
    const int c = (tid & 7) * 2;
    for (int k0 = 0; k0 < 192; k0 += 16) {
        int qi = i0 + r;
        float2 qv = make_float2(0.f, 0.f);
        if (qi < 195) qv = *(const float2*)(Abase + (size_t)qi*2304 + k0 + c);
        Qs[c][r] = qv.x; Qs[c+1][r] = qv.y;
        int kj = j0 + r;
        float2 kv = make_float2(0.f, 0.f);
        if (kj < 195) kv = *(const float2*)(Bbase + (size_t)kj*2304 + k0 + c);
        Ks[c][r] = kv.x; Ks[c+1][r] = kv.y;
        __syncthreads();
#pragma unroll
        for (int kk = 0; kk < 16; kk++) {
            float a0 = Qs[kk][ty*2], a1 = Qs[kk][ty*2+1];
            float b0 = Ks[kk][tx*2], b1 = Ks[kk][tx*2+1];
            acc00 += a0*b0; acc01 += a0*b1; acc10 += a1*b0; acc11 += a1*b1;
        }
        __syncthreads();
    }
    float* Sp = g_S + (size_t)bh*195*195;
    int ii = i0 + ty*2, jj = j0 + tx*2;
    if (ii < 195) {
        if (jj   < 195) Sp[(size_t)ii*195 + jj  ] = acc00 * SCALE_C;
        if (jj+1 < 195) Sp[(size_t)ii*195 + jj+1] = acc01 * SCALE_C;
    }
    if (ii+1 < 195) {
        if (jj   < 195) Sp[(size_t)(ii+1)*195 + jj  ] = acc10 * SCALE_C;
        if (jj+1 < 195) Sp[(size_t)(ii+1)*195 + jj+1] = acc11 * SCALE_C;
    }
}

// ---------------------------------------------------------------------------
// xi=0 softmax + w@V
// ---------------------------------------------------------------------------
__global__ void __launch_bounds__(256) soft0_k() {
    const int bh = blockIdx.x;
    const int b = bh / 12, h = bh % 12;
    const float* S = g_S + (size_t)bh*195*195;
    __shared__ float wk_s[195];
    const int tid = threadIdx.x;
    if (tid < 195) wk_s[tid] = 0.f;
    __syncthreads();
    const int warp = tid >> 5, lane = tid & 31;
    for (int q = warp; q < 195; q += 8) {
        const float* Sq = S + (size_t)q*195;
        float m = -1e30f;
        for (int k = lane; k < 195; k += 32) m = fmaxf(m, Sq[k]);
        for (int o = 16; o; o >>= 1) m = fmaxf(m, __shfl_xor_sync(0xFFFFFFFFu, m, o));
        float sum = 0.f;
        for (int k = lane; k < 195; k += 32) sum += expf(Sq[k] - m);
        if (lane == 0) sum += expf(Sq[0] - m);
        for (int o = 16; o; o >>= 1) sum += __shfl_xor_sync(0xFFFFFFFFu, sum, o);
        const float inv = 1.f / sum;
        const float mult = (q == 0) ? 2.f : 1.f;
        for (int k = lane; k < 195; k += 32) {
            float w = expf(Sq[k] - m) * inv * mult;
            if (k == 0) w *= 2.f;
            atomicAdd(&wk_s[k], w);
        }
    }
    __syncthreads();
    if (tid < 192) {
        const float* V = g_Ak + (size_t)b*195*2304 + h*192 + tid;
        float o = 0.f;
        for (int k = 0; k < 195; k++) o += wk_s[k] * V[(size_t)k*2304];
        g_U[((size_t)b*17 + 1)*2304 + h*192 + tid] = o;
    }
}

// ---------------------------------------------------------------------------
// xi=1..15
// ---------------------------------------------------------------------------
__global__ void __launch_bounds__(256) attn2x_k() {
    const int xi = blockIdx.x + 1;
    const int h = blockIdx.y, b = blockIdx.z;
    __shared__ float Ksm[16][192];
    __shared__ float Vsm[16][192];
    __shared__ float wk[16];
    const int tid = threadIdx.x;
    for (int idx = tid; idx < 16*192; idx += 256) {
        int j = idx / 192, d = idx - j*192;
        size_t ro = ((size_t)(b*195 + xi + j))*2304 + h*192 + d;
        Ksm[j][d] = g_Av[ro];
        Vsm[j][d] = g_Ak[ro];
    }
    if (tid < 16) wk[tid] = 0.f;
    __syncthreads();
    const int q = tid;
    if (q < 195) {
        const float* Arow = g_Aq + ((size_t)(b*195 + q))*2304 + h*192;
        float s[16];
#pragma unroll
        for (int j = 0; j < 16; j++) s[j] = 0.f;
        for (int d = 0; d < 192; d += 4) {
            float4 qv = *(const float4*)(Arow + d);
#pragma unroll
            for (int j = 0; j < 16; j++)
                s[j] += qv.x*Ksm[j][d] + qv.y*Ksm[j][d+1] + qv.z*Ksm[j][d+2] + qv.w*Ksm[j][d+3];
        }
        float m = -1e30f;
#pragma unroll
        for (int j = 0; j < 16; j++) { s[j] *= SCALE_C; m = fmaxf(m, s[j]); }
        float sum = 0.f;
#pragma unroll
        for (int j = 0; j < 16; j++) { s[j] = expf(s[j] - m); sum += s[j]; }
        const float w = ((q == xi) ? 2.f : 1.f) / sum;
#pragma unroll
        for (int j = 0; j < 16; j++) atomicAdd(&wk[j], s[j] * w);
    }
    __syncthreads();
    if (tid < 192) {
        float o = 0.f;
#pragma unroll
        for (int j = 0; j < 16; j++) o += wk[j] * Vsm[j][tid];
        g_U[((size_t)b*17 + xi + 1)*2304 + h*192 + tid] = o;
    }
}

// ---------------------------------------------------------------------------
__global__ void scatter_k(float* __restrict__ out) {
    size_t idx = (size_t)blockIdx.x * 256 + threadIdx.x;
    const size_t total = (size_t)8 * 3137 * 768;
    if (idx >= total) return;
    int b = (int)(idx / (3137*768));
    int r = (int)(idx % (3137*768));
    int s = r / 768, d = r - s*768;
    int row = (s == 0) ? 0 : 1 + (s - 1) % 16;
    out[idx] = g_Ou[((size_t)b*17 + row)*768 + d];
}

// ---------------------------------------------------------------------------
extern "C" void kernel_launch(void* const* d_in, const int* in_sizes, int n_in,
                              void* d_out, int out_size) {
    const float* x  = (const float*)d_in[0];
    const float* Wq = (const float*)d_in[1];
    const float* bq = (const float*)d_in[2];
    const float* Wk = (const float*)d_in[3];
    const float* bk = (const float*)d_in[4];
    const float* Wv = (const float*)d_in[5];
    const float* bv = (const float*)d_in[6];
    const float* Wt = (const float*)d_in[7];
    const float* bt = (const float*)d_in[8];
    const float* Wf = (const float*)d_in[9];
    const float* bf = (const float*)d_in[10];
    float* out = (float*)d_out;

    float *Pq, *Pk, *Pv, *tmp, *ti, *Aq, *Ak, *Av, *U, *Ou;
    cudaGetSymbolAddress((void**)&Pq,  g_Pq);
    cudaGetSymbolAddress((void**)&Pk,  g_Pk);
    cudaGetSymbolAddress((void**)&Pv,  g_Pv);
    cudaGetSymbolAddress((void**)&tmp, g_tmp);
    cudaGetSymbolAddress((void**)&ti,  g_ti);
    cudaGetSymbolAddress((void**)&Aq,  g_Aq);
    cudaGetSymbolAddress((void**)&Ak,  g_Ak);
    cudaGetSymbolAddress((void**)&Av,  g_Av);
    cudaGetSymbolAddress((void**)&U,   g_U);
    cudaGetSymbolAddress((void**)&Ou,  g_Ou);

    __nv_bfloat16 *xh, *xl, *Wqh, *Wql, *Wkh, *Wkl, *Wvh, *Wvl, *Wth, *Wtl;
    __nv_bfloat16 *th, *tl, *tih, *til;
    cudaGetSymbolAddress((void**)&xh,  g_xh);
    cudaGetSymbolAddress((void**)&xl,  g_xl);
    cudaGetSymbolAddress((void**)&Wqh, g_Wqh);
    cudaGetSymbolAddress((void**)&Wql, g_Wql);
    cudaGetSymbolAddress((void**)&Wkh, g_Wkh);
    cudaGetSymbolAddress((void**)&Wkl, g_Wkl);
    cudaGetSymbolAddress((void**)&Wvh, g_Wvh);
    cudaGetSymbolAddress((void**)&Wvl, g_Wvl);
    cudaGetSymbolAddress((void**)&Wth, g_Wth);
    cudaGetSymbolAddress((void**)&Wtl, g_Wtl);
    cudaGetSymbolAddress((void**)&th,  g_th);
    cudaGetSymbolAddress((void**)&tl,  g_tl);
    cudaGetSymbolAddress((void**)&tih, g_tih);
    cudaGetSymbolAddress((void**)&til, g_til);

    const int HG_SMEM = 131072;   // 2 stages x 64 KB
    cudaFuncSetAttribute(hgemm_k, cudaFuncAttributeMaxDynamicSharedMemorySize, HG_SMEM);

    rope_init_k<<<(3136*32 + 255)/256, 256>>>();

    // convert inputs + weights to hi/lo bf16
    conv_k<<<(25096*768 + 255)/256, 256>>>(x, xh, xl, 25096*768);
    {
        dim3 wb(32, 8);
        dim3 wg(768/32, 2304/32);
        wconv_k<<<wg, wb>>>(Wq, Wqh, Wql, 768, 2304);
        wconv_k<<<wg, wb>>>(Wk, Wkh, Wkl, 768, 2304);
        wconv_k<<<wg, wb>>>(Wv, Wvh, Wvl, 768, 2304);
        dim3 wg2(2304/32, 768/32);
        wconv_k<<<wg2, wb>>>(Wt, Wth, Wtl, 2304, 768);
    }

    // projections of full x: 25096 x 2304, K=768 (fused-split HMMA)
    {
        dim3 grid(2304/128, (25096 + 127)/128);
        hgemm_k<<<grid, 256, HG_SMEM>>>(xh, xl, Wqh, Wql, bq, Pq, 25096, 2304, 768);
        hgemm_k<<<grid, 256, HG_SMEM>>>(xh, xl, Wkh, Wkl, bk, Pk, 25096, 2304, 768);
        hgemm_k<<<grid, 256, HG_SMEM>>>(xh, xl, Wvh, Wvl, bv, Pv, 25096, 2304, 768);
    }

    // grouped frame attention -> tmp (1560 x 2304)
    grattn_k<<<dim3(195, 12, 8), 256>>>();

    // ti = tmp @ Wt + bt : 1560 x 768, K=2304
    conv_k<<<(1560*2304 + 255)/256, 256>>>(tmp, th, tl, 1560*2304);
    hgemm_k<<<dim3(768/128, (1560 + 127)/128), 256, HG_SMEM>>>(
        th, tl, Wth, Wtl, bt, ti, 1560, 768, 2304);

    // Aq/Ak/Av = ti @ W? + b? : 1560 x 2304, K=768
    conv_k<<<(1560*768 + 255)/256, 256>>>(ti, tih, til, 1560*768);
    {
        dim3 grid(2304/128, (1560 + 127)/128);
        hgemm_k<<<grid, 256, HG_SMEM>>>(tih, til, Wqh, Wql, bq, Aq, 1560, 2304, 768);
        hgemm_k<<<grid, 256, HG_SMEM>>>(tih, til, Wkh, Wkl, bk, Ak, 1560, 2304, 768);
        hgemm_k<<<grid, 256, HG_SMEM>>>(tih, til, Wvh, Wvl, bv, Av, 1560, 2304, 768);
    }

    // cls attention -> U row 0
    cls_k<<<dim3(12, 8), 512>>>();

    // xi = 0 attention -> U row 1
    s0_k<<<dim3(7, 7, 96), 256>>>();
    soft0_k<<<96, 256>>>();

    // xi = 1..15 -> U rows 2..16
    attn2x_k<<<dim3(15, 12, 8), 256>>>();

    // Ou = U @ Wf + bf : 136 x 768, K=2304 (tiny, fp32)
    sgemm64_k<<<dim3(768/64, (136 + 63)/64), 256>>>(U, Wf, bf, Ou, 136, 768, 2304);

    // broadcast to output
    scatter_k<<<(int)(((size_t)8*3137*768 + 255)/256), 256>>>(out);
}

// round 13
// speedup vs baseline: 2.8394x; 1.3683x over previous
#include <cuda_runtime.h>
#include <cuda_fp16.h>
#include <math.h>
#include <cstdint>

// ---------------------------------------------------------------------------
// dividedSpaceTimeAttention  (B=8, NH=12, DIM=768, NP=196, NF=16, DH=64)
// Round 11: 2-term fp16 split (A=Ah+Al fp16, B single fp16) -> MMA count x2/3,
// 48KB stages -> 2 CTAs/SM, QKV fused into one launch over concat weights.
// ---------------------------------------------------------------------------

#define SCALE_C (1.0f/96.0f)

// ------------------------- scratch (device globals) ------------------------
__device__ float g_Pq[57821184];          // 8*3137*2304
__device__ float g_Pk[57821184];
__device__ float g_Pv[57821184];
__device__ float g_tmp[8*195*2304];
__device__ float g_ti [8*195*768];
__device__ float g_Aq [8*195*2304];
__device__ float g_Ak [8*195*2304];
__device__ float g_Av [8*195*2304];
__device__ float g_S  [96*195*195];
__device__ float g_U  [8*17*2304];
__device__ float g_Ou [8*17*768];
__device__ float g_cos[3136*32];
__device__ float g_sin[3136*32];

// fp16 operands (aligned for cp.async)
__device__ __align__(256) __half g_xh [25096*768];
__device__ __align__(256) __half g_xl [25096*768];
__device__ __align__(256) __half g_Wall[6912*768];     // [Wq^T; Wk^T; Wv^T]
__device__ __align__(256) __half g_Wth[768*2304];      // Wt^T
__device__ __align__(256) __half g_th [1560*2304], g_tl [1560*2304];
__device__ __align__(256) __half g_tih[1560*768],  g_til[1560*768];

// ------------------------- helpers ---------------------------
__device__ __forceinline__ uint32_t smem_to_u32(const void* p) {
    uint32_t a;
    asm("{ .reg .u64 t; cvta.to.shared.u64 t, %1; cvt.u32.u64 %0, t; }"
        : "=r"(a) : "l"(p));
    return a;
}
#define CP_ASYNC16(dst, src) \
    asm volatile("cp.async.cg.shared.global [%0], [%1], 16;" :: "r"(dst), "l"(src))
#define CP_COMMIT() asm volatile("cp.async.commit_group;")

__device__ __forceinline__ void ldmatrix_x4(uint32_t* r, uint32_t addr) {
    asm volatile("ldmatrix.sync.aligned.m8n8.x4.shared.b16 {%0,%1,%2,%3}, [%4];"
        : "=r"(r[0]), "=r"(r[1]), "=r"(r[2]), "=r"(r[3]) : "r"(addr));
}
__device__ __forceinline__ void mma16816(float* c, const uint32_t* a, const uint32_t* b) {
    asm volatile("mma.sync.aligned.m16n8k16.row.col.f32.f16.f16.f32 "
        "{%0,%1,%2,%3}, {%4,%5,%6,%7}, {%8,%9}, {%0,%1,%2,%3};"
        : "+f"(c[0]), "+f"(c[1]), "+f"(c[2]), "+f"(c[3])
        : "r"(a[0]), "r"(a[1]), "r"(a[2]), "r"(a[3]), "r"(b[0]), "r"(b[1]));
}

// ---------------------------------------------------------------------------
// fused QKV hgemm: for sel in {0,1,2}: C_sel[M,2304] = (Ah+Al)@Wsel^T + b_sel
// W is [6912][K] = concat of the three transposed weights.
// grid (54, ceil(M/128)), 256 threads, dyn smem = 96 KB (2 x 48 KB stage).
// Stage layout: [Ah 16K][Al 16K][B 16K]
// ---------------------------------------------------------------------------
__global__ void __launch_bounds__(256, 2) hgemm3_k(
    const __half* __restrict__ Ah, const __half* __restrict__ Al,
    const __half* __restrict__ W,
    const float* __restrict__ b0, const float* __restrict__ b1, const float* __restrict__ b2,
    float* __restrict__ C0, float* __restrict__ C1, float* __restrict__ C2,
    int M, int K)
{
    extern __shared__ char smem[];
    const uint32_t sb = smem_to_u32(smem);
    const int tid = threadIdx.x;
    const int wid = tid >> 5, lane = tid & 31;
    const int sel = blockIdx.x / 18;
    const int bn = (blockIdx.x % 18) * 128;
    const int bm = blockIdx.y * 128;
    const int wm = (wid >> 2) * 64;
    const int wn = (wid & 3) * 32;
    const float* bias = (sel == 0) ? b0 : ((sel == 1) ? b1 : b2);
    float* C = (sel == 0) ? C0 : ((sel == 1) ? C1 : C2);
    const int brow0 = sel * 2304 + bn;

    float acc[4][4][4];
#pragma unroll
    for (int i = 0; i < 4; i++)
#pragma unroll
        for (int j = 0; j < 4; j++)
#pragma unroll
            for (int r = 0; r < 4; r++) acc[i][j][r] = 0.f;

    const int G = K >> 6;
    const int lrow = tid >> 1;
    const int lc0 = (tid & 1) * 4;

    auto ISSUE = [&](int g) {
        const int k0 = g << 6;
        const uint32_t base = sb + (g & 1) * 49152;
        int ga = bm + lrow; if (ga >= M) ga = M - 1;
        const size_t aoff = (size_t)ga * K + k0 + lc0 * 8;
        const __half* ahp = Ah + aoff;
        const __half* alp = Al + aoff;
        const __half* bp  = W + (size_t)(brow0 + lrow) * K + k0 + lc0 * 8;
#pragma unroll
        for (int j = 0; j < 4; j++) {
            const uint32_t sw = (uint32_t)(lrow * 128 + (((lc0 + j) ^ (lrow & 7)) << 4));
            CP_ASYNC16(base + sw,         ahp + j * 8);
            CP_ASYNC16(base + 16384 + sw, alp + j * 8);
            CP_ASYNC16(base + 32768 + sw, bp  + j * 8);
        }
        CP_COMMIT();
    };

    ISSUE(0);
    for (int g = 0; g < G; g++) {
        if (g + 1 < G) {
            ISSUE(g + 1);
            asm volatile("cp.async.wait_group 1;");
        } else {
            asm volatile("cp.async.wait_group 0;");
        }
        __syncthreads();
        const uint32_t base = sb + (g & 1) * 49152;
#pragma unroll
        for (int ks = 0; ks < 4; ks++) {
            uint32_t ah[4][4], al[4][4], bb[2][4];
#pragma unroll
            for (int mf = 0; mf < 4; mf++) {
                const int row = wm + mf * 16 + (lane & 15);
                const int c16 = ks * 2 + (lane >> 4);
                const uint32_t off = row * 128 + ((c16 ^ (row & 7)) << 4);
                ldmatrix_x4(ah[mf], base + off);
                ldmatrix_x4(al[mf], base + 16384 + off);
            }
#pragma unroll
            for (int nh = 0; nh < 2; nh++) {
                const int row = wn + nh * 16 + (lane & 7) + ((lane & 16) >> 1);
                const int c16 = ks * 2 + ((lane >> 3) & 1);
                ldmatrix_x4(bb[nh], base + 32768 + row * 128 + ((c16 ^ (row & 7)) << 4));
            }
#pragma unroll
            for (int mf = 0; mf < 4; mf++)
#pragma unroll
                for (int nf = 0; nf < 4; nf++)
                    mma16816(acc[mf][nf], ah[mf], bb[nf >> 1] + (nf & 1) * 2);
#pragma unroll
            for (int mf = 0; mf < 4; mf++)
#pragma unroll
                for (int nf = 0; nf < 4; nf++)
                    mma16816(acc[mf][nf], al[mf], bb[nf >> 1] + (nf & 1) * 2);
        }
        __syncthreads();
    }

    const int r0 = lane >> 2;
    const int c0 = (lane & 3) * 2;
#pragma unroll
    for (int mf = 0; mf < 4; mf++) {
        const int row0 = bm + wm + mf * 16 + r0;
#pragma unroll
        for (int half = 0; half < 2; half++) {
            const int row = row0 + half * 8;
            if (row < M) {
                float* Cr = C + (size_t)row * 2304 + bn + wn;
                const float* bp = bias + bn + wn;
#pragma unroll
                for (int nf = 0; nf < 4; nf++) {
                    const int col = nf * 8 + c0;
                    Cr[col]     = acc[mf][nf][half * 2 + 0] + bp[col];
                    Cr[col + 1] = acc[mf][nf][half * 2 + 1] + bp[col + 1];
                }
            }
        }
    }
}

// ---------------------------------------------------------------------------
// generic 2-term hgemm: C[M,N] = (Ah+Al) @ Bt[N,K]^T + bias
// ---------------------------------------------------------------------------
__global__ void __launch_bounds__(256, 2) hgemm_k(
    const __half* __restrict__ Ah, const __half* __restrict__ Al,
    const __half* __restrict__ Bt,
    const float* __restrict__ bias, float* __restrict__ C,
    int M, int N, int K)
{
    extern __shared__ char smem[];
    const uint32_t sb = smem_to_u32(smem);
    const int tid = threadIdx.x;
    const int wid = tid >> 5, lane = tid & 31;
    const int bm = blockIdx.y * 128, bn = blockIdx.x * 128;
    const int wm = (wid >> 2) * 64;
    const int wn = (wid & 3) * 32;

    float acc[4][4][4];
#pragma unroll
    for (int i = 0; i < 4; i++)
#pragma unroll
        for (int j = 0; j < 4; j++)
#pragma unroll
            for (int r = 0; r < 4; r++) acc[i][j][r] = 0.f;

    const int G = K >> 6;
    const int lrow = tid >> 1;
    const int lc0 = (tid & 1) * 4;

    auto ISSUE = [&](int g) {
        const int k0 = g << 6;
        const uint32_t base = sb + (g & 1) * 49152;
        int ga = bm + lrow; if (ga >= M) ga = M - 1;
        const size_t aoff = (size_t)ga * K + k0 + lc0 * 8;
        const __half* ahp = Ah + aoff;
        const __half* alp = Al + aoff;
        const __half* bp  = Bt + (size_t)(bn + lrow) * K + k0 + lc0 * 8;
#pragma unroll
        for (int j = 0; j < 4; j++) {
            const uint32_t sw = (uint32_t)(lrow * 128 + (((lc0 + j) ^ (lrow & 7)) << 4));
            CP_ASYNC16(base + sw,         ahp + j * 8);
            CP_ASYNC16(base + 16384 + sw, alp + j * 8);
            CP_ASYNC16(base + 32768 + sw, bp  + j * 8);
        }
        CP_COMMIT();
    };

    ISSUE(0);
    for (int g = 0; g < G; g++) {
        if (g + 1 < G) {
            ISSUE(g + 1);
            asm volatile("cp.async.wait_group 1;");
        } else {
            asm volatile("cp.async.wait_group 0;");
        }
        __syncthreads();
        const uint32_t base = sb + (g & 1) * 49152;
#pragma unroll
        for (int ks = 0; ks < 4; ks++) {
            uint32_t ah[4][4], al[4][4], bb[2][4];
#pragma unroll
            for (int mf = 0; mf < 4; mf++) {
                const int row = wm + mf * 16 + (lane & 15);
                const int c16 = ks * 2 + (lane >> 4);
                const uint32_t off = row * 128 + ((c16 ^ (row & 7)) << 4);
                ldmatrix_x4(ah[mf], base + off);
                ldmatrix_x4(al[mf], base + 16384 + off);
            }
#pragma unroll
            for (int nh = 0; nh < 2; nh++) {
                const int row = wn + nh * 16 + (lane & 7) + ((lane & 16) >> 1);
                const int c16 = ks * 2 + ((lane >> 3) & 1);
                ldmatrix_x4(bb[nh], base + 32768 + row * 128 + ((c16 ^ (row & 7)) << 4));
            }
#pragma unroll
            for (int mf = 0; mf < 4; mf++)
#pragma unroll
                for (int nf = 0; nf < 4; nf++)
                    mma16816(acc[mf][nf], ah[mf], bb[nf >> 1] + (nf & 1) * 2);
#pragma unroll
            for (int mf = 0; mf < 4; mf++)
#pragma unroll
                for (int nf = 0; nf < 4; nf++)
                    mma16816(acc[mf][nf], al[mf], bb[nf >> 1] + (nf & 1) * 2);
        }
        __syncthreads();
    }

    const int r0 = lane >> 2;
    const int c0 = (lane & 3) * 2;
#pragma unroll
    for (int mf = 0; mf < 4; mf++) {
        const int row0 = bm + wm + mf * 16 + r0;
#pragma unroll
        for (int half = 0; half < 2; half++) {
            const int row = row0 + half * 8;
            if (row < M) {
                float* Cr = C + (size_t)row * N + bn + wn;
                const float* bp = bias + bn + wn;
#pragma unroll
                for (int nf = 0; nf < 4; nf++) {
                    const int col = nf * 8 + c0;
                    Cr[col]     = acc[mf][nf][half * 2 + 0] + bp[col];
                    Cr[col + 1] = acc[mf][nf][half * 2 + 1] + bp[col + 1];
                }
            }
        }
    }
}

// ---------------------------------------------------------------------------
// conversions: fp32 -> fp16 hi/lo
// ---------------------------------------------------------------------------
__global__ void conv_k(const float* __restrict__ s,
                       __half* __restrict__ h, __half* __restrict__ l, int n) {
    int i = blockIdx.x * 256 + threadIdx.x;
    if (i >= n) return;
    float v = s[i];
    __half hv = __float2half_rn(v);
    h[i] = hv;
    l[i] = __float2half_rn(v - __half2float(hv));
}

// W[K,N] -> T[N,K] (transpose, single fp16)
__global__ void wconvh_k(const float* __restrict__ W, __half* __restrict__ T,
                         int K, int N) {
    __shared__ float tile[32][33];
    const int k0 = blockIdx.x * 32, n0 = blockIdx.y * 32;
    const int tx = threadIdx.x, ty = threadIdx.y;
    for (int r = ty; r < 32; r += 8) {
        int k = k0 + r, n = n0 + tx;
        tile[r][tx] = (k < K && n < N) ? W[(size_t)k * N + n] : 0.f;
    }
    __syncthreads();
    for (int r = ty; r < 32; r += 8) {
        int n = n0 + r, k = k0 + tx;
        if (n < N && k < K)
            T[(size_t)n * K + k] = __float2half_rn(tile[tx][r]);
    }
}

// ---------------------------------------------------------------------------
__global__ void rope_init_k() {
    int idx = blockIdx.x * 256 + threadIdx.x;
    if (idx >= 3136*32) return;
    int s = idx >> 5, i = idx & 31;
    float e = (float)(2*i) / 64.f;
    float invf = 1.f / powf(10000.f, e);
    float ang = (float)s * invf;
    g_cos[idx] = (float)cos((double)ang);
    g_sin[idx] = (float)sin((double)ang);
}

// small fp32 GEMM (final 136-row): 64x64 tile, 4x4/thread
__global__ void __launch_bounds__(256) sgemm64_k(
    const float* __restrict__ A, const float* __restrict__ B,
    const float* __restrict__ bias, float* __restrict__ C,
    int M, int N, int K)
{
    __shared__ float As[8][64];
    __shared__ float Bs[8][64];
    const int bm = blockIdx.y * 64, bn = blockIdx.x * 64;
    const int tid = threadIdx.x;
    const int tx = tid & 15, ty = tid >> 4;
    const int arow = tid >> 2, acol = (tid & 3) * 2;
    const int brow = tid >> 5, bcol = (tid & 31) * 2;
    float acc[4][4];
#pragma unroll
    for (int i = 0; i < 4; i++)
#pragma unroll
        for (int j = 0; j < 4; j++) acc[i][j] = 0.f;
    const bool arow_ok = (bm + arow) < M;
    for (int k0 = 0; k0 < K; k0 += 8) {
        float2 av = make_float2(0.f, 0.f);
        if (arow_ok) av = *(const float2*)(A + (size_t)(bm + arow) * K + k0 + acol);
        As[acol][arow] = av.x;  As[acol + 1][arow] = av.y;
        float2 bv = *(const float2*)(B + (size_t)(k0 + brow) * N + bn + bcol);
        Bs[brow][bcol] = bv.x;  Bs[brow][bcol + 1] = bv.y;
        __syncthreads();
#pragma unroll
        for (int kk = 0; kk < 8; kk++) {
            float ar[4], br[4];
#pragma unroll
            for (int i = 0; i < 4; i++) ar[i] = As[kk][ty * 4 + i];
#pragma unroll
            for (int j = 0; j < 4; j++) br[j] = Bs[kk][tx * 4 + j];
#pragma unroll
            for (int i = 0; i < 4; i++)
#pragma unroll
                for (int j = 0; j < 4; j++)
                    acc[i][j] += ar[i] * br[j];
        }
        __syncthreads();
    }
#pragma unroll
    for (int i = 0; i < 4; i++) {
        int m = bm + ty * 4 + i;
        if (m < M)
#pragma unroll
            for (int j = 0; j < 4; j++)
                C[(size_t)m * N + bn + tx * 4 + j] = acc[i][j] + bias[bn + tx * 4 + j];
    }
}

// ---------------------------------------------------------------------------
// Grouped frame-attention
// ---------------------------------------------------------------------------
#define GA 193
__global__ void __launch_bounds__(256) grattn_k() {
    const int p = blockIdx.x + 1;
    const int h = blockIdx.y;
    const int b = blockIdx.z;
    __shared__ float qs[16*GA], ks[16*GA], vs[16*GA];
    __shared__ float S[256], wg[16];
    const int tid = threadIdx.x;

    for (int idx = tid; idx < 16*192; idx += 256) {
        int f = idx / 192, d = idx - f * 192;
        size_t off = ((size_t)(b * 3137 + 1 + f * 196 + p)) * 2304 + h * 192 + d;
        qs[f*GA + d] = g_Pq[off];
        ks[f*GA + d] = g_Pv[off];
        vs[f*GA + d] = g_Pk[off];
    }
    __syncthreads();
    for (int idx = tid; idx < 16*32; idx += 256) {
        int f = idx >> 5, i = idx & 31;
        int s = f * 196 + p;
        float c = g_cos[s*32 + i], sn = g_sin[s*32 + i];
        float a0 = qs[f*GA + 2*i], a1 = qs[f*GA + 2*i + 1];
        qs[f*GA + 2*i]     = a0 * c - a1 * sn;
        qs[f*GA + 2*i + 1] = a1 * c + a0 * sn;
        float b0 = ks[f*GA + 2*i], b1 = ks[f*GA + 2*i + 1];
        ks[f*GA + 2*i]     = b0 * c - b1 * sn;
        ks[f*GA + 2*i + 1] = b1 * c + b0 * sn;
    }
    __syncthreads();
    {
        int f = tid >> 4, g = tid & 15;
        const float* qp = qs + f * GA;
        const float* kp = ks + g * GA;
        float s = 0.f;
#pragma unroll 8
        for (int d = 0; d < 192; d++) s += qp[d] * kp[d];
        S[tid] = s * SCALE_C;
    }
    __syncthreads();
    if (tid < 16) {
        float m = -1e30f;
        for (int g = 0; g < 16; g++) m = fmaxf(m, S[tid*16 + g]);
        float sum = 0.f;
        for (int g = 0; g < 16; g++) { float e = expf(S[tid*16 + g] - m); S[tid*16 + g] = e; sum += e; }
        float inv = 1.f / sum;
        for (int g = 0; g < 16; g++) S[tid*16 + g] *= inv;
    }
    __syncthreads();
    if (tid < 16) {
        float a = 0.f;
        for (int f = 0; f < 16; f++) a += S[f*16 + tid];
        wg[tid] = a;
    }
    __syncthreads();
    if (tid < 192) {
        float o = 0.f;
#pragma unroll
        for (int g = 0; g < 16; g++) o += wg[g] * vs[g*GA + tid];
        g_tmp[((size_t)(b * 195 + (p - 1))) * 2304 + h * 192 + tid] = o;
    }
}

// ---------------------------------------------------------------------------
// CLS attention: 512 threads, warp-parallel w@V
// ---------------------------------------------------------------------------
__global__ void __launch_bounds__(512) cls_k() {
    const int h = blockIdx.x, b = blockIdx.y;
    __shared__ float qv[192];
    __shared__ float Sv[3137];
    __shared__ float red[512];
    __shared__ float red2[16][192];
    const int tid = threadIdx.x;
    const int warp = tid >> 5, lane = tid & 31;
    const float* Pq_ = g_Pq + (size_t)b*3137*2304 + h*192;
    const float* Pk_ = g_Pk + (size_t)b*3137*2304 + h*192;
    const float* Pv_ = g_Pv + (size_t)b*3137*2304 + h*192;
    if (tid < 192) qv[tid] = Pq_[tid];
    __syncthreads();
    float lm = -1e30f;
    for (int t = tid; t < 3137; t += 512) {
        const float* kr = Pk_ + (size_t)t*2304;
        float s = 0.f;
        for (int d = 0; d < 192; d += 4) {
            float4 k4 = *(const float4*)(kr + d);
            s += k4.x*qv[d] + k4.y*qv[d+1] + k4.z*qv[d+2] + k4.w*qv[d+3];
        }
        s *= SCALE_C;
        Sv[t] = s;
        lm = fmaxf(lm, s);
    }
    red[tid] = lm; __syncthreads();
    for (int s2 = 256; s2 > 0; s2 >>= 1) {
        if (tid < s2) red[tid] = fmaxf(red[tid], red[tid + s2]);
        __syncthreads();
    }
    const float m = red[0];
    __syncthreads();
    float ls = 0.f;
    for (int t = tid; t < 3137; t += 512) { float e = expf(Sv[t] - m); Sv[t] = e; ls += e; }
    red[tid] = ls; __syncthreads();
    for (int s2 = 256; s2 > 0; s2 >>= 1) {
        if (tid < s2) red[tid] += red[tid + s2];
        __syncthreads();
    }
    const float inv = 1.f / red[0];
    float o[6];
#pragma unroll
    for (int i = 0; i < 6; i++) o[i] = 0.f;
    for (int t = warp; t < 3137; t += 16) {
        const float w = Sv[t];
        const float* vr = Pv_ + (size_t)t*2304;
#pragma unroll
        for (int i = 0; i < 6; i++) o[i] += w * vr[i*32 + lane];
    }
#pragma unroll
    for (int i = 0; i < 6; i++) red2[warp][i*32 + lane] = o[i];
    __syncthreads();
    if (tid < 192) {
        float s = 0.f;
#pragma unroll
        for (int w = 0; w < 16; w++) s += red2[w][tid];
        g_U[((size_t)b*17 + 0)*2304 + h*192 + tid] = s * inv;
    }
}

// ---------------------------------------------------------------------------
// xi=0 scores
// ---------------------------------------------------------------------------
__global__ void __launch_bounds__(256) s0_k() {
    const int bh = blockIdx.z;
    const int b = bh / 12, h = bh % 12;
    const int i0 = blockIdx.y * 32, j0 = blockIdx.x * 32;
    __shared__ float Qs[16][33], Ks[16][33];
    const int tid = threadIdx.x;
    const int tx = tid & 15, ty = tid >> 4;
    const float* Abase = g_Aq + (size_t)b*195*2304 + h*192;
    const float* Bbase = g_Av + (size_t)b*195*2304 + h*192;
    float acc00 = 0.f, acc01 = 0.f, acc10 = 0.f, acc11 = 0.f;
    const int r = tid >> 3;
    const int c = (tid & 7) * 2;
    for (int k0 = 0; k0 < 192; k0 += 16) {
        int qi = i0 + r;
        float2 qv = make_float2(0.f, 0.f);
        if (qi < 195) qv = *(const float2*)(Abase + (size_t)qi*2304 + k0 + c);
        Qs[c][r] = qv.x; Qs[c+1][r] = qv.y;
        int kj = j0 + r;
        float2 kv = make_float2(0.f, 0.f);
        if (kj < 195) kv = *(const float2*)(Bbase + (size_t)kj*2304 + k0 + c);
        Ks[c][r] = kv.x; Ks[c+1][r] = kv.y;
        __syncthreads();
#pragma unroll
        for (int kk = 0; kk < 16; kk++) {
            float a0 = Qs[kk][ty*2], a1 = Qs[kk][ty*2+1];
            float b0 = Ks[kk][tx*2], b1 = Ks[kk][tx*2+1];
            acc00 += a0*b0; acc01 += a0*b1; acc10 += a1*b0; acc11 += a1*b1;
        }
        __syncthreads();
    }
    float* Sp = g_S + (size_t)bh*195*195;
    int ii = i0 + ty*2, jj = j0 + tx*2;
    if (ii < 195) {
        if (jj   < 195) Sp[(size_t)ii*195 + jj  ] = acc00 * SCALE_C;
        if (jj+1 < 195) Sp[(size_t)ii*195 + jj+1] = acc01 * SCALE_C;
    }
    if (ii+1 < 195) {
        if (jj   < 195) Sp[(size_t)(ii+1)*195 + jj  ] = acc10 * SCALE_C;
        if (jj+1 < 195) Sp[(size_t)(ii+1)*195 + jj+1] = acc11 * SCALE_C;
    }
}

// ---------------------------------------------------------------------------
// xi=0 softmax + w@V
// ---------------------------------------------------------------------------
__global__ void __launch_bounds__(256) soft0_k() {
    const int bh = blockIdx.x;
    const int b = bh / 12, h = bh % 12;
    const float* S = g_S + (size_t)bh*195*195;
    __shared__ float wk_s[195];
    const int tid = threadIdx.x;
    if (tid < 195) wk_s[tid] = 0.f;
    __syncthreads();
    const int warp = tid >> 5, lane = tid & 31;
    for (int q = warp; q < 195; q += 8) {
        const float* Sq = S + (size_t)q*195;
        float m = -1e30f;
        for (int k = lane; k < 195; k += 32) m = fmaxf(m, Sq[k]);
        for (int o = 16; o; o >>= 1) m = fmaxf(m, __shfl_xor_sync(0xFFFFFFFFu, m, o));
        float sum = 0.f;
        for (int k = lane; k < 195; k += 32) sum += expf(Sq[k] - m);
        if (lane == 0) sum += expf(Sq[0] - m);
        for (int o = 16; o; o >>= 1) sum += __shfl_xor_sync(0xFFFFFFFFu, sum, o);
        const float inv = 1.f / sum;
        const float mult = (q == 0) ? 2.f : 1.f;
        for (int k = lane; k < 195; k += 32) {
            float w = expf(Sq[k] - m) * inv * mult;
            if (k == 0) w *= 2.f;
            atomicAdd(&wk_s[k], w);
        }
    }
    __syncthreads();
    if (tid < 192) {
        const float* V = g_Ak + (size_t)b*195*2304 + h*192 + tid;
        float o = 0.f;
        for (int k = 0; k < 195; k++) o += wk_s[k] * V[(size_t)k*2304];
        g_U[((size_t)b*17 + 1)*2304 + h*192 + tid] = o;
    }
}

// ---------------------------------------------------------------------------
// xi=1..15
// ---------------------------------------------------------------------------
__global__ void __launch_bounds__(256) attn2x_k() {
    const int xi = blockIdx.x + 1;
    const int h = blockIdx.y, b = blockIdx.z;
    __shared__ float Ksm[16][192];
    __shared__ float Vsm[16][192];
    __shared__ float wk[16];
    const int tid = threadIdx.x;
    for (int idx = tid; idx < 16*192; idx += 256) {
        int j = idx / 192, d = idx - j*192;
        size_t ro = ((size_t)(b*195 + xi + j))*2304 + h*192 + d;
        Ksm[j][d] = g_Av[ro];
        Vsm[j][d] = g_Ak[ro];
    }
    if (tid < 16) wk[tid] = 0.f;
    __syncthreads();
    const int q = tid;
    if (q < 195) {
        const float* Arow = g_Aq + ((size_t)(b*195 + q))*2304 + h*192;
        float s[16];
#pragma unroll
        for (int j = 0; j < 16; j++) s[j] = 0.f;
        for (int d = 0; d < 192; d += 4) {
            float4 qv = *(const float4*)(Arow + d);
#pragma unroll
            for (int j = 0; j < 16; j++)
                s[j] += qv.x*Ksm[j][d] + qv.y*Ksm[j][d+1] + qv.z*Ksm[j][d+2] + qv.w*Ksm[j][d+3];
        }
        float m = -1e30f;
#pragma unroll
        for (int j = 0; j < 16; j++) { s[j] *= SCALE_C; m = fmaxf(m, s[j]); }
        float sum = 0.f;
#pragma unroll
        for (int j = 0; j < 16; j++) { s[j] = expf(s[j] - m); sum += s[j]; }
        const float w = ((q == xi) ? 2.f : 1.f) / sum;
#pragma unroll
        for (int j = 0; j < 16; j++) atomicAdd(&wk[j], s[j] * w);
    }
    __syncthreads();
    if (tid < 192) {
        float o = 0.f;
#pragma unroll
        for (int j = 0; j < 16; j++) o += wk[j] * Vsm[j][tid];
        g_U[((size_t)b*17 + xi + 1)*2304 + h*192 + tid] = o;
    }
}

// ---------------------------------------------------------------------------
__global__ void scatter_k(float* __restrict__ out) {
    size_t idx = (size_t)blockIdx.x * 256 + threadIdx.x;
    const size_t total = (size_t)8 * 3137 * 768;
    if (idx >= total) return;
    int b = (int)(idx / (3137*768));
    int r = (int)(idx % (3137*768));
    int s = r / 768, d = r - s*768;
    int row = (s == 0) ? 0 : 1 + (s - 1) % 16;
    out[idx] = g_Ou[((size_t)b*17 + row)*768 + d];
}

// ---------------------------------------------------------------------------
extern "C" void kernel_launch(void* const* d_in, const int* in_sizes, int n_in,
                              void* d_out, int out_size) {
    const float* x  = (const float*)d_in[0];
    const float* Wq = (const float*)d_in[1];
    const float* bq = (const float*)d_in[2];
    const float* Wk = (const float*)d_in[3];
    const float* bk = (const float*)d_in[4];
    const float* Wv = (const float*)d_in[5];
    const float* bv = (const float*)d_in[6];
    const float* Wt = (const float*)d_in[7];
    const float* bt = (const float*)d_in[8];
    const float* Wf = (const float*)d_in[9];
    const float* bf = (const float*)d_in[10];
    float* out = (float*)d_out;

    float *Pq, *Pk, *Pv, *tmp, *ti, *Aq, *Ak, *Av, *U, *Ou;
    cudaGetSymbolAddress((void**)&Pq,  g_Pq);
    cudaGetSymbolAddress((void**)&Pk,  g_Pk);
    cudaGetSymbolAddress((void**)&Pv,  g_Pv);
    cudaGetSymbolAddress((void**)&tmp, g_tmp);
    cudaGetSymbolAddress((void**)&ti,  g_ti);
    cudaGetSymbolAddress((void**)&Aq,  g_Aq);
    cudaGetSymbolAddress((void**)&Ak,  g_Ak);
    cudaGetSymbolAddress((void**)&Av,  g_Av);
    cudaGetSymbolAddress((void**)&U,   g_U);
    cudaGetSymbolAddress((void**)&Ou,  g_Ou);

    __half *xh, *xl, *Wall, *Wth, *th, *tl, *tih, *til;
    cudaGetSymbolAddress((void**)&xh,   g_xh);
    cudaGetSymbolAddress((void**)&xl,   g_xl);
    cudaGetSymbolAddress((void**)&Wall, g_Wall);
    cudaGetSymbolAddress((void**)&Wth,  g_Wth);
    cudaGetSymbolAddress((void**)&th,   g_th);
    cudaGetSymbolAddress((void**)&tl,   g_tl);
    cudaGetSymbolAddress((void**)&tih,  g_tih);
    cudaGetSymbolAddress((void**)&til,  g_til);

    const int HG_SMEM = 98304;   // 2 stages x 48 KB
    cudaFuncSetAttribute(hgemm3_k, cudaFuncAttributeMaxDynamicSharedMemorySize, HG_SMEM);
    cudaFuncSetAttribute(hgemm_k,  cudaFuncAttributeMaxDynamicSharedMemorySize, HG_SMEM);

    rope_init_k<<<(3136*32 + 255)/256, 256>>>();

    // convert x to fp16 hi/lo; weights to single fp16 (transposed, concat QKV)
    conv_k<<<(25096*768 + 255)/256, 256>>>(x, xh, xl, 25096*768);
    {
        dim3 wb(32, 8);
        dim3 wg(768/32, 2304/32);
        wconvh_k<<<wg, wb>>>(Wq, Wall,              768, 2304);
        wconvh_k<<<wg, wb>>>(Wk, Wall + 2304*768,   768, 2304);
        wconvh_k<<<wg, wb>>>(Wv, Wall + 4608*768,   768, 2304);
        dim3 wg2(2304/32, 768/32);
        wconvh_k<<<wg2, wb>>>(Wt, Wth, 2304, 768);
    }

    // fused QKV projections of x: 25096 x (3x2304), K=768
    hgemm3_k<<<dim3(54, (25096 + 127)/128), 256, HG_SMEM>>>(
        xh, xl, Wall, bq, bk, bv, Pq, Pk, Pv, 25096, 768);

    // grouped frame attention -> tmp (1560 x 2304)
    grattn_k<<<dim3(195, 12, 8), 256>>>();

    // ti = tmp @ Wt + bt : 1560 x 768, K=2304
    conv_k<<<(1560*2304 + 255)/256, 256>>>(tmp, th, tl, 1560*2304);
    hgemm_k<<<dim3(768/128, (1560 + 127)/128), 256, HG_SMEM>>>(
        th, tl, Wth, bt, ti, 1560, 768, 2304);

    // fused QKV on ti: 1560 x (3x2304), K=768
    conv_k<<<(1560*768 + 255)/256, 256>>>(ti, tih, til, 1560*768);
    hgemm3_k<<<dim3(54, (1560 + 127)/128), 256, HG_SMEM>>>(
        tih, til, Wall, bq, bk, bv, Aq, Ak, Av, 1560, 768);

    // cls attention -> U row 0
    cls_k<<<dim3(12, 8), 512>>>();

    // xi = 0 attention -> U row 1
    s0_k<<<dim3(7, 7, 96), 256>>>();
    soft0_k<<<96, 256>>>();

    // xi = 1..15 -> U rows 2..16
    attn2x_k<<<dim3(15, 12, 8), 256>>>();

    // Ou = U @ Wf + bf : 136 x 768, K=2304 (tiny, fp32)
    sgemm64_k<<<dim3(768/64, (136 + 63)/64), 256>>>(U, Wf, bf, Ou, 136, 768, 2304);

    // broadcast to output
    scatter_k<<<(int)(((size_t)8*3137*768 + 255)/256), 256>>>(out);
}

// round 14
// speedup vs baseline: 3.2284x; 1.1370x over previous
#include <cuda_runtime.h>
#include <cuda_fp16.h>
#include <math.h>
#include <cstdint>

// ---------------------------------------------------------------------------
// dividedSpaceTimeAttention  (B=8, NH=12, DIM=768, NP=196, NF=16, DH=64)
// Round 13: QKV-x GEMM single-term fp16 (HMMA-issue-bound -> halve MMA count);
// small GEMMs keep 2-term split. grattn score loop vectorized (LDS.128).
// ---------------------------------------------------------------------------

#define SCALE_C (1.0f/96.0f)

// ------------------------- scratch (device globals) ------------------------
__device__ float g_Pq[57821184];          // 8*3137*2304
__device__ float g_Pk[57821184];
__device__ float g_Pv[57821184];
__device__ float g_tmp[8*195*2304];
__device__ float g_ti [8*195*768];
__device__ float g_Aq [8*195*2304];
__device__ float g_Ak [8*195*2304];
__device__ float g_Av [8*195*2304];
__device__ float g_S  [96*195*195];
__device__ float g_U  [8*17*2304];
__device__ float g_Ou [8*17*768];
__device__ float g_cos[3136*32];
__device__ float g_sin[3136*32];

// fp16 operands (aligned for cp.async)
__device__ __align__(256) __half g_xh [25096*768];
__device__ __align__(256) __half g_Wall[6912*768];     // [Wq^T; Wk^T; Wv^T]
__device__ __align__(256) __half g_Wth[768*2304];      // Wt^T
__device__ __align__(256) __half g_th [1560*2304], g_tl [1560*2304];
__device__ __align__(256) __half g_tih[1560*768],  g_til[1560*768];

// ------------------------- helpers ---------------------------
__device__ __forceinline__ uint32_t smem_to_u32(const void* p) {
    uint32_t a;
    asm("{ .reg .u64 t; cvta.to.shared.u64 t, %1; cvt.u32.u64 %0, t; }"
        : "=r"(a) : "l"(p));
    return a;
}
#define CP_ASYNC16(dst, src) \
    asm volatile("cp.async.cg.shared.global [%0], [%1], 16;" :: "r"(dst), "l"(src))
#define CP_COMMIT() asm volatile("cp.async.commit_group;")

__device__ __forceinline__ void ldmatrix_x4(uint32_t* r, uint32_t addr) {
    asm volatile("ldmatrix.sync.aligned.m8n8.x4.shared.b16 {%0,%1,%2,%3}, [%4];"
        : "=r"(r[0]), "=r"(r[1]), "=r"(r[2]), "=r"(r[3]) : "r"(addr));
}
__device__ __forceinline__ void mma16816(float* c, const uint32_t* a, const uint32_t* b) {
    asm volatile("mma.sync.aligned.m16n8k16.row.col.f32.f16.f16.f32 "
        "{%0,%1,%2,%3}, {%4,%5,%6,%7}, {%8,%9}, {%0,%1,%2,%3};"
        : "+f"(c[0]), "+f"(c[1]), "+f"(c[2]), "+f"(c[3])
        : "r"(a[0]), "r"(a[1]), "r"(a[2]), "r"(a[3]), "r"(b[0]), "r"(b[1]));
}

// ---------------------------------------------------------------------------
// single-term fused QKV hgemm: C_sel[M,2304] = A@Wsel^T + b_sel, sel = bx/18
// W is [6912][K]. grid (54, ceil(M/128)), 256 threads, smem 64KB (2 x 32KB).
// Stage layout: [A 16K][B 16K]
// ---------------------------------------------------------------------------
__global__ void __launch_bounds__(256, 2) hgemm3s_k(
    const __half* __restrict__ A, const __half* __restrict__ W,
    const float* __restrict__ b0, const float* __restrict__ b1, const float* __restrict__ b2,
    float* __restrict__ C0, float* __restrict__ C1, float* __restrict__ C2,
    int M, int K)
{
    extern __shared__ char smem[];
    const uint32_t sb = smem_to_u32(smem);
    const int tid = threadIdx.x;
    const int wid = tid >> 5, lane = tid & 31;
    const int sel = blockIdx.x / 18;
    const int bn = (blockIdx.x % 18) * 128;
    const int bm = blockIdx.y * 128;
    const int wm = (wid >> 2) * 64;
    const int wn = (wid & 3) * 32;
    const float* bias = (sel == 0) ? b0 : ((sel == 1) ? b1 : b2);
    float* C = (sel == 0) ? C0 : ((sel == 1) ? C1 : C2);
    const int brow0 = sel * 2304 + bn;

    float acc[4][4][4];
#pragma unroll
    for (int i = 0; i < 4; i++)
#pragma unroll
        for (int j = 0; j < 4; j++)
#pragma unroll
            for (int r = 0; r < 4; r++) acc[i][j][r] = 0.f;

    const int G = K >> 6;
    const int lrow = tid >> 1;
    const int lc0 = (tid & 1) * 4;

    auto ISSUE = [&](int g) {
        const int k0 = g << 6;
        const uint32_t base = sb + (g & 1) * 32768;
        int ga = bm + lrow; if (ga >= M) ga = M - 1;
        const __half* ap = A + (size_t)ga * K + k0 + lc0 * 8;
        const __half* bp = W + (size_t)(brow0 + lrow) * K + k0 + lc0 * 8;
#pragma unroll
        for (int j = 0; j < 4; j++) {
            const uint32_t sw = (uint32_t)(lrow * 128 + (((lc0 + j) ^ (lrow & 7)) << 4));
            CP_ASYNC16(base + sw,         ap + j * 8);
            CP_ASYNC16(base + 16384 + sw, bp + j * 8);
        }
        CP_COMMIT();
    };

    ISSUE(0);
    for (int g = 0; g < G; g++) {
        if (g + 1 < G) {
            ISSUE(g + 1);
            asm volatile("cp.async.wait_group 1;");
        } else {
            asm volatile("cp.async.wait_group 0;");
        }
        __syncthreads();
        const uint32_t base = sb + (g & 1) * 32768;
#pragma unroll
        for (int ks = 0; ks < 4; ks++) {
            uint32_t af[4][4], bb[2][4];
#pragma unroll
            for (int mf = 0; mf < 4; mf++) {
                const int row = wm + mf * 16 + (lane & 15);
                const int c16 = ks * 2 + (lane >> 4);
                ldmatrix_x4(af[mf], base + row * 128 + ((c16 ^ (row & 7)) << 4));
            }
#pragma unroll
            for (int nh = 0; nh < 2; nh++) {
                const int row = wn + nh * 16 + (lane & 7) + ((lane & 16) >> 1);
                const int c16 = ks * 2 + ((lane >> 3) & 1);
                ldmatrix_x4(bb[nh], base + 16384 + row * 128 + ((c16 ^ (row & 7)) << 4));
            }
#pragma unroll
            for (int mf = 0; mf < 4; mf++)
#pragma unroll
                for (int nf = 0; nf < 4; nf++)
                    mma16816(acc[mf][nf], af[mf], bb[nf >> 1] + (nf & 1) * 2);
        }
        __syncthreads();
    }

    const int r0 = lane >> 2;
    const int c0 = (lane & 3) * 2;
#pragma unroll
    for (int mf = 0; mf < 4; mf++) {
        const int row0 = bm + wm + mf * 16 + r0;
#pragma unroll
        for (int half = 0; half < 2; half++) {
            const int row = row0 + half * 8;
            if (row < M) {
                float* Cr = C + (size_t)row * 2304 + bn + wn;
                const float* bp = bias + bn + wn;
#pragma unroll
                for (int nf = 0; nf < 4; nf++) {
                    const int col = nf * 8 + c0;
                    Cr[col]     = acc[mf][nf][half * 2 + 0] + bp[col];
                    Cr[col + 1] = acc[mf][nf][half * 2 + 1] + bp[col + 1];
                }
            }
        }
    }
}

// ---------------------------------------------------------------------------
// generic 2-term hgemm: C[M,N] = (Ah+Al) @ Bt[N,K]^T + bias  (small GEMMs)
// ---------------------------------------------------------------------------
__global__ void __launch_bounds__(256, 2) hgemm_k(
    const __half* __restrict__ Ah, const __half* __restrict__ Al,
    const __half* __restrict__ Bt,
    const float* __restrict__ bias, float* __restrict__ C,
    int M, int N, int K)
{
    extern __shared__ char smem[];
    const uint32_t sb = smem_to_u32(smem);
    const int tid = threadIdx.x;
    const int wid = tid >> 5, lane = tid & 31;
    const int bm = blockIdx.y * 128, bn = blockIdx.x * 128;
    const int wm = (wid >> 2) * 64;
    const int wn = (wid & 3) * 32;

    float acc[4][4][4];
#pragma unroll
    for (int i = 0; i < 4; i++)
#pragma unroll
        for (int j = 0; j < 4; j++)
#pragma unroll
            for (int r = 0; r < 4; r++) acc[i][j][r] = 0.f;

    const int G = K >> 6;
    const int lrow = tid >> 1;
    const int lc0 = (tid & 1) * 4;

    auto ISSUE = [&](int g) {
        const int k0 = g << 6;
        const uint32_t base = sb + (g & 1) * 49152;
        int ga = bm + lrow; if (ga >= M) ga = M - 1;
        const size_t aoff = (size_t)ga * K + k0 + lc0 * 8;
        const __half* ahp = Ah + aoff;
        const __half* alp = Al + aoff;
        const __half* bp  = Bt + (size_t)(bn + lrow) * K + k0 + lc0 * 8;
#pragma unroll
        for (int j = 0; j < 4; j++) {
            const uint32_t sw = (uint32_t)(lrow * 128 + (((lc0 + j) ^ (lrow & 7)) << 4));
            CP_ASYNC16(base + sw,         ahp + j * 8);
            CP_ASYNC16(base + 16384 + sw, alp + j * 8);
            CP_ASYNC16(base + 32768 + sw, bp  + j * 8);
        }
        CP_COMMIT();
    };

    ISSUE(0);
    for (int g = 0; g < G; g++) {
        if (g + 1 < G) {
            ISSUE(g + 1);
            asm volatile("cp.async.wait_group 1;");
        } else {
            asm volatile("cp.async.wait_group 0;");
        }
        __syncthreads();
        const uint32_t base = sb + (g & 1) * 49152;
#pragma unroll
        for (int ks = 0; ks < 4; ks++) {
            uint32_t ah[4][4], al[4][4], bb[2][4];
#pragma unroll
            for (int mf = 0; mf < 4; mf++) {
                const int row = wm + mf * 16 + (lane & 15);
                const int c16 = ks * 2 + (lane >> 4);
                const uint32_t off = row * 128 + ((c16 ^ (row & 7)) << 4);
                ldmatrix_x4(ah[mf], base + off);
                ldmatrix_x4(al[mf], base + 16384 + off);
            }
#pragma unroll
            for (int nh = 0; nh < 2; nh++) {
                const int row = wn + nh * 16 + (lane & 7) + ((lane & 16) >> 1);
                const int c16 = ks * 2 + ((lane >> 3) & 1);
                ldmatrix_x4(bb[nh], base + 32768 + row * 128 + ((c16 ^ (row & 7)) << 4));
            }
#pragma unroll
            for (int mf = 0; mf < 4; mf++)
#pragma unroll
                for (int nf = 0; nf < 4; nf++)
                    mma16816(acc[mf][nf], ah[mf], bb[nf >> 1] + (nf & 1) * 2);
#pragma unroll
            for (int mf = 0; mf < 4; mf++)
#pragma unroll
                for (int nf = 0; nf < 4; nf++)
                    mma16816(acc[mf][nf], al[mf], bb[nf >> 1] + (nf & 1) * 2);
        }
        __syncthreads();
    }

    const int r0 = lane >> 2;
    const int c0 = (lane & 3) * 2;
#pragma unroll
    for (int mf = 0; mf < 4; mf++) {
        const int row0 = bm + wm + mf * 16 + r0;
#pragma unroll
        for (int half = 0; half < 2; half++) {
            const int row = row0 + half * 8;
            if (row < M) {
                float* Cr = C + (size_t)row * N + bn + wn;
                const float* bp = bias + bn + wn;
#pragma unroll
                for (int nf = 0; nf < 4; nf++) {
                    const int col = nf * 8 + c0;
                    Cr[col]     = acc[mf][nf][half * 2 + 0] + bp[col];
                    Cr[col + 1] = acc[mf][nf][half * 2 + 1] + bp[col + 1];
                }
            }
        }
    }
}

// ---------------------------------------------------------------------------
// conversions
// ---------------------------------------------------------------------------
__global__ void convh_k(const float* __restrict__ s, __half* __restrict__ h, int n) {
    int i = blockIdx.x * 256 + threadIdx.x;
    if (i >= n) return;
    h[i] = __float2half_rn(s[i]);
}
__global__ void conv_k(const float* __restrict__ s,
                       __half* __restrict__ h, __half* __restrict__ l, int n) {
    int i = blockIdx.x * 256 + threadIdx.x;
    if (i >= n) return;
    float v = s[i];
    __half hv = __float2half_rn(v);
    h[i] = hv;
    l[i] = __float2half_rn(v - __half2float(hv));
}

// W[K,N] -> T[N,K] (transpose, single fp16)
__global__ void wconvh_k(const float* __restrict__ W, __half* __restrict__ T,
                         int K, int N) {
    __shared__ float tile[32][33];
    const int k0 = blockIdx.x * 32, n0 = blockIdx.y * 32;
    const int tx = threadIdx.x, ty = threadIdx.y;
    for (int r = ty; r < 32; r += 8) {
        int k = k0 + r, n = n0 + tx;
        tile[r][tx] = (k < K && n < N) ? W[(size_t)k * N + n] : 0.f;
    }
    __syncthreads();
    for (int r = ty; r < 32; r += 8) {
        int n = n0 + r, k = k0 + tx;
        if (n < N && k < K)
            T[(size_t)n * K + k] = __float2half_rn(tile[tx][r]);
    }
}

// ---------------------------------------------------------------------------
__global__ void rope_init_k() {
    int idx = blockIdx.x * 256 + threadIdx.x;
    if (idx >= 3136*32) return;
    int s = idx >> 5, i = idx & 31;
    float e = (float)(2*i) / 64.f;
    float invf = 1.f / powf(10000.f, e);
    float ang = (float)s * invf;
    g_cos[idx] = (float)cos((double)ang);
    g_sin[idx] = (float)sin((double)ang);
}

// small fp32 GEMM (final 136-row): 64x64 tile, 4x4/thread
__global__ void __launch_bounds__(256) sgemm64_k(
    const float* __restrict__ A, const float* __restrict__ B,
    const float* __restrict__ bias, float* __restrict__ C,
    int M, int N, int K)
{
    __shared__ float As[8][64];
    __shared__ float Bs[8][64];
    const int bm = blockIdx.y * 64, bn = blockIdx.x * 64;
    const int tid = threadIdx.x;
    const int tx = tid & 15, ty = tid >> 4;
    const int arow = tid >> 2, acol = (tid & 3) * 2;
    const int brow = tid >> 5, bcol = (tid & 31) * 2;
    float acc[4][4];
#pragma unroll
    for (int i = 0; i < 4; i++)
#pragma unroll
        for (int j = 0; j < 4; j++) acc[i][j] = 0.f;
    const bool arow_ok = (bm + arow) < M;
    for (int k0 = 0; k0 < K; k0 += 8) {
        float2 av = make_float2(0.f, 0.f);
        if (arow_ok) av = *(const float2*)(A + (size_t)(bm + arow) * K + k0 + acol);
        As[acol][arow] = av.x;  As[acol + 1][arow] = av.y;
        float2 bv = *(const float2*)(B + (size_t)(k0 + brow) * N + bn + bcol);
        Bs[brow][bcol] = bv.x;  Bs[brow][bcol + 1] = bv.y;
        __syncthreads();
#pragma unroll
        for (int kk = 0; kk < 8; kk++) {
            float ar[4], br[4];
#pragma unroll
            for (int i = 0; i < 4; i++) ar[i] = As[kk][ty * 4 + i];
#pragma unroll
            for (int j = 0; j < 4; j++) br[j] = Bs[kk][tx * 4 + j];
#pragma unroll
            for (int i = 0; i < 4; i++)
#pragma unroll
                for (int j = 0; j < 4; j++)
                    acc[i][j] += ar[i] * br[j];
        }
        __syncthreads();
    }
#pragma unroll
    for (int i = 0; i < 4; i++) {
        int m = bm + ty * 4 + i;
        if (m < M)
#pragma unroll
            for (int j = 0; j < 4; j++)
                C[(size_t)m * N + bn + tx * 4 + j] = acc[i][j] + bias[bn + tx * 4 + j];
    }
}

// ---------------------------------------------------------------------------
// Grouped frame-attention (GA=196: float4-aligned, conflict-free LDS.128)
// ---------------------------------------------------------------------------
#define GA 196
__global__ void __launch_bounds__(256) grattn_k() {
    const int p = blockIdx.x + 1;
    const int h = blockIdx.y;
    const int b = blockIdx.z;
    __shared__ float qs[16*GA], ks[16*GA], vs[16*GA];
    __shared__ float S[256], wg[16];
    const int tid = threadIdx.x;

    for (int idx = tid; idx < 16*192; idx += 256) {
        int f = idx / 192, d = idx - f * 192;
        size_t off = ((size_t)(b * 3137 + 1 + f * 196 + p)) * 2304 + h * 192 + d;
        qs[f*GA + d] = g_Pq[off];
        ks[f*GA + d] = g_Pv[off];
        vs[f*GA + d] = g_Pk[off];
    }
    __syncthreads();
    for (int idx = tid; idx < 16*32; idx += 256) {
        int f = idx >> 5, i = idx & 31;
        int s = f * 196 + p;
        float c = g_cos[s*32 + i], sn = g_sin[s*32 + i];
        float a0 = qs[f*GA + 2*i], a1 = qs[f*GA + 2*i + 1];
        qs[f*GA + 2*i]     = a0 * c - a1 * sn;
        qs[f*GA + 2*i + 1] = a1 * c + a0 * sn;
        float b0 = ks[f*GA + 2*i], b1 = ks[f*GA + 2*i + 1];
        ks[f*GA + 2*i]     = b0 * c - b1 * sn;
        ks[f*GA + 2*i + 1] = b1 * c + b0 * sn;
    }
    __syncthreads();
    {
        int f = tid >> 4, g = tid & 15;
        const float* qp = qs + f * GA;
        const float* kp = ks + g * GA;
        float s = 0.f;
#pragma unroll
        for (int d = 0; d < 192; d += 4) {
            float4 a = *(const float4*)(qp + d);
            float4 bv = *(const float4*)(kp + d);
            s += a.x*bv.x + a.y*bv.y + a.z*bv.z + a.w*bv.w;
        }
        S[tid] = s * SCALE_C;
    }
    __syncthreads();
    if (tid < 16) {
        float m = -1e30f;
        for (int g = 0; g < 16; g++) m = fmaxf(m, S[tid*16 + g]);
        float sum = 0.f;
        for (int g = 0; g < 16; g++) { float e = expf(S[tid*16 + g] - m); S[tid*16 + g] = e; sum += e; }
        float inv = 1.f / sum;
        for (int g = 0; g < 16; g++) S[tid*16 + g] *= inv;
    }
    __syncthreads();
    if (tid < 16) {
        float a = 0.f;
        for (int f = 0; f < 16; f++) a += S[f*16 + tid];
        wg[tid] = a;
    }
    __syncthreads();
    if (tid < 192) {
        float o = 0.f;
#pragma unroll
        for (int g = 0; g < 16; g++) o += wg[g] * vs[g*GA + tid];
        g_tmp[((size_t)(b * 195 + (p - 1))) * 2304 + h * 192 + tid] = o;
    }
}

// ---------------------------------------------------------------------------
// CLS attention: 512 threads, warp-parallel w@V
// ---------------------------------------------------------------------------
__global__ void __launch_bounds__(512) cls_k() {
    const int h = blockIdx.x, b = blockIdx.y;
    __shared__ float qv[192];
    __shared__ float Sv[3137];
    __shared__ float red[512];
    __shared__ float red2[16][192];
    const int tid = threadIdx.x;
    const int warp = tid >> 5, lane = tid & 31;
    const float* Pq_ = g_Pq + (size_t)b*3137*2304 + h*192;
    const float* Pk_ = g_Pk + (size_t)b*3137*2304 + h*192;
    const float* Pv_ = g_Pv + (size_t)b*3137*2304 + h*192;
    if (tid < 192) qv[tid] = Pq_[tid];
    __syncthreads();
    float lm = -1e30f;
    for (int t = tid; t < 3137; t += 512) {
        const float* kr = Pk_ + (size_t)t*2304;
        float s = 0.f;
        for (int d = 0; d < 192; d += 4) {
            float4 k4 = *(const float4*)(kr + d);
            s += k4.x*qv[d] + k4.y*qv[d+1] + k4.z*qv[d+2] + k4.w*qv[d+3];
        }
        s *= SCALE_C;
        Sv[t] = s;
        lm = fmaxf(lm, s);
    }
    red[tid] = lm; __syncthreads();
    for (int s2 = 256; s2 > 0; s2 >>= 1) {
        if (tid < s2) red[tid] = fmaxf(red[tid], red[tid + s2]);
        __syncthreads();
    }
    const float m = red[0];
    __syncthreads();
    float ls = 0.f;
    for (int t = tid; t < 3137; t += 512) { float e = expf(Sv[t] - m); Sv[t] = e; ls += e; }
    red[tid] = ls; __syncthreads();
    for (int s2 = 256; s2 > 0; s2 >>= 1) {
        if (tid < s2) red[tid] += red[tid + s2];
        __syncthreads();
    }
    const float inv = 1.f / red[0];
    float o[6];
#pragma unroll
    for (int i = 0; i < 6; i++) o[i] = 0.f;
    for (int t = warp; t < 3137; t += 16) {
        const float w = Sv[t];
        const float* vr = Pv_ + (size_t)t*2304;
#pragma unroll
        for (int i = 0; i < 6; i++) o[i] += w * vr[i*32 + lane];
    }
#pragma unroll
    for (int i = 0; i < 6; i++) red2[warp][i*32 + lane] = o[i];
    __syncthreads();
    if (tid < 192) {
        float s = 0.f;
#pragma unroll
        for (int w = 0; w < 16; w++) s += red2[w][tid];
        g_U[((size_t)b*17 + 0)*2304 + h*192 + tid] = s * inv;
    }
}

// ---------------------------------------------------------------------------
// xi=0 scores
// ---------------------------------------------------------------------------
__global__ void __launch_bounds__(256) s0_k() {
    const int bh = blockIdx.z;
    const int b = bh / 12, h = bh % 12;
    const int i0 = blockIdx.y * 32, j0 = blockIdx.x * 32;
    __shared__ float Qs[16][33], Ks[16][33];
    const int tid = threadIdx.x;
    const int tx = tid & 15, ty = tid >> 4;
    const float* Abase = g_Aq + (size_t)b*195*2304 + h*192;
    const float* Bbase = g_Av + (size_t)b*195*2304 + h*192;
    float acc00 = 0.f, acc01 = 0.f, acc10 = 0.f, acc11 = 0.f;
    const int r = tid >> 3;
    const int c = (tid & 7) * 2;
    for (int k0 = 0; k0 < 192; k0 += 16) {
        int qi = i0 + r;
        float2 qv = make_float2(0.f, 0.f);
        if (qi < 195) qv = *(const float2*)(Abase + (size_t)qi*2304 + k0 + c);
        Qs[c][r] = qv.x; Qs[c+1][r] = qv.y;
        int kj = j0 + r;
        float2 kv = make_float2(0.f, 0.f);
        if (kj < 195) kv = *(const float2*)(Bbase + (size_t)kj*2304 + k0 + c);
        Ks[c][r] = kv.x; Ks[c+1][r] = kv.y;
        __syncthreads();
#pragma unroll
        for (int kk = 0; kk < 16; kk++) {
            float a0 = Qs[kk][ty*2], a1 = Qs[kk][ty*2+1];
            float b0 = Ks[kk][tx*2], b1 = Ks[kk][tx*2+1];
            acc00 += a0*b0; acc01 += a0*b1; acc10 += a1*b0; acc11 += a1*b1;
        }
        __syncthreads();
    }
    float* Sp = g_S + (size_t)bh*195*195;
    int ii = i0 + ty*2, jj = j0 + tx*2;
    if (ii < 195) {
        if (jj   < 195) Sp[(size_t)ii*195 + jj  ] = acc00 * SCALE_C;
        if (jj+1 < 195) Sp[(size_t)ii*195 + jj+1] = acc01 * SCALE_C;
    }
    if (ii+1 < 195) {
        if (jj   < 195) Sp[(size_t)(ii+1)*195 + jj  ] = acc10 * SCALE_C;
        if (jj+1 < 195) Sp[(size_t)(ii+1)*195 + jj+1] = acc11 * SCALE_C;
    }
}

// ---------------------------------------------------------------------------
// xi=0 softmax + w@V
// ---------------------------------------------------------------------------
__global__ void __launch_bounds__(256) soft0_k() {
    const int bh = blockIdx.x;
    const int b = bh / 12, h = bh % 12;
    const float* S = g_S + (size_t)bh*195*195;
    __shared__ float wk_s[195];
    const int tid = threadIdx.x;
    if (tid < 195) wk_s[tid] = 0.f;
    __syncthreads();
    const int warp = tid >> 5, lane = tid & 31;
    for (int q = warp; q < 195; q += 8) {
        const float* Sq = S + (size_t)q*195;
        float m = -1e30f;
        for (int k = lane; k < 195; k += 32) m = fmaxf(m, Sq[k]);
        for (int o = 16; o; o >>= 1) m = fmaxf(m, __shfl_xor_sync(0xFFFFFFFFu, m, o));
        float sum = 0.f;
        for (int k = lane; k < 195; k += 32) sum += expf(Sq[k] - m);
        if (lane == 0) sum += expf(Sq[0] - m);
        for (int o = 16; o; o >>= 1) sum += __shfl_xor_sync(0xFFFFFFFFu, sum, o);
        const float inv = 1.f / sum;
        const float mult = (q == 0) ? 2.f : 1.f;
        for (int k = lane; k < 195; k += 32) {
            float w = expf(Sq[k] - m) * inv * mult;
            if (k == 0) w *= 2.f;
            atomicAdd(&wk_s[k], w);
        }
    }
    __syncthreads();
    if (tid < 192) {
        const float* V = g_Ak + (size_t)b*195*2304 + h*192 + tid;
        float o = 0.f;
        for (int k = 0; k < 195; k++) o += wk_s[k] * V[(size_t)k*2304];
        g_U[((size_t)b*17 + 1)*2304 + h*192 + tid] = o;
    }
}

// ---------------------------------------------------------------------------
// xi=1..15
// ---------------------------------------------------------------------------
__global__ void __launch_bounds__(256) attn2x_k() {
    const int xi = blockIdx.x + 1;
    const int h = blockIdx.y, b = blockIdx.z;
    __shared__ float Ksm[16][192];
    __shared__ float Vsm[16][192];
    __shared__ float wk[16];
    const int tid = threadIdx.x;
    for (int idx = tid; idx < 16*192; idx += 256) {
        int j = idx / 192, d = idx - j*192;
        size_t ro = ((size_t)(b*195 + xi + j))*2304 + h*192 + d;
        Ksm[j][d] = g_Av[ro];
        Vsm[j][d] = g_Ak[ro];
    }
    if (tid < 16) wk[tid] = 0.f;
    __syncthreads();
    const int q = tid;
    if (q < 195) {
        const float* Arow = g_Aq + ((size_t)(b*195 + q))*2304 + h*192;
        float s[16];
#pragma unroll
        for (int j = 0; j < 16; j++) s[j] = 0.f;
        for (int d = 0; d < 192; d += 4) {
            float4 qv = *(const float4*)(Arow + d);
#pragma unroll
            for (int j = 0; j < 16; j++)
                s[j] += qv.x*Ksm[j][d] + qv.y*Ksm[j][d+1] + qv.z*Ksm[j][d+2] + qv.w*Ksm[j][d+3];
        }
        float m = -1e30f;
#pragma unroll
        for (int j = 0; j < 16; j++) { s[j] *= SCALE_C; m = fmaxf(m, s[j]); }
        float sum = 0.f;
#pragma unroll
        for (int j = 0; j < 16; j++) { s[j] = expf(s[j] - m); sum += s[j]; }
        const float w = ((q == xi) ? 2.f : 1.f) / sum;
#pragma unroll
        for (int j = 0; j < 16; j++) atomicAdd(&wk[j], s[j] * w);
    }
    __syncthreads();
    if (tid < 192) {
        float o = 0.f;
#pragma unroll
        for (int j = 0; j < 16; j++) o += wk[j] * Vsm[j][tid];
        g_U[((size_t)b*17 + xi + 1)*2304 + h*192 + tid] = o;
    }
}

// ---------------------------------------------------------------------------
__global__ void scatter_k(float* __restrict__ out) {
    size_t idx = (size_t)blockIdx.x * 256 + threadIdx.x;
    const size_t total = (size_t)8 * 3137 * 768;
    if (idx >= total) return;
    int b = (int)(idx / (3137*768));
    int r = (int)(idx % (3137*768));
    int s = r / 768, d = r - s*768;
    int row = (s == 0) ? 0 : 1 + (s - 1) % 16;
    out[idx] = g_Ou[((size_t)b*17 + row)*768 + d];
}

// ---------------------------------------------------------------------------
extern "C" void kernel_launch(void* const* d_in, const int* in_sizes, int n_in,
                              void* d_out, int out_size) {
    const float* x  = (const float*)d_in[0];
    const float* Wq = (const float*)d_in[1];
    const float* bq = (const float*)d_in[2];
    const float* Wk = (const float*)d_in[3];
    const float* bk = (const float*)d_in[4];
    const float* Wv = (const float*)d_in[5];
    const float* bv = (const float*)d_in[6];
    const float* Wt = (const float*)d_in[7];
    const float* bt = (const float*)d_in[8];
    const float* Wf = (const float*)d_in[9];
    const float* bf = (const float*)d_in[10];
    float* out = (float*)d_out;

    float *Pq, *Pk, *Pv, *tmp, *ti, *Aq, *Ak, *Av, *U, *Ou;
    cudaGetSymbolAddress((void**)&Pq,  g_Pq);
    cudaGetSymbolAddress((void**)&Pk,  g_Pk);
    cudaGetSymbolAddress((void**)&Pv,  g_Pv);
    cudaGetSymbolAddress((void**)&tmp, g_tmp);
    cudaGetSymbolAddress((void**)&ti,  g_ti);
    cudaGetSymbolAddress((void**)&Aq,  g_Aq);
    cudaGetSymbolAddress((void**)&Ak,  g_Ak);
    cudaGetSymbolAddress((void**)&Av,  g_Av);
    cudaGetSymbolAddress((void**)&U,   g_U);
    cudaGetSymbolAddress((void**)&Ou,  g_Ou);

    __half *xh, *Wall, *Wth, *th, *tl, *tih, *til;
    cudaGetSymbolAddress((void**)&xh,   g_xh);
    cudaGetSymbolAddress((void**)&Wall, g_Wall);
    cudaGetSymbolAddress((void**)&Wth,  g_Wth);
    cudaGetSymbolAddress((void**)&th,   g_th);
    cudaGetSymbolAddress((void**)&tl,   g_tl);
    cudaGetSymbolAddress((void**)&tih,  g_tih);
    cudaGetSymbolAddress((void**)&til,  g_til);

    const int HG3_SMEM = 65536;   // 2 stages x 32 KB (single-term)
    const int HG_SMEM  = 98304;   // 2 stages x 48 KB (2-term)
    cudaFuncSetAttribute(hgemm3s_k, cudaFuncAttributeMaxDynamicSharedMemorySize, HG3_SMEM);
    cudaFuncSetAttribute(hgemm_k,   cudaFuncAttributeMaxDynamicSharedMemorySize, HG_SMEM);

    rope_init_k<<<(3136*32 + 255)/256, 256>>>();

    // convert x to single fp16; weights to fp16 (transposed, concat QKV)
    convh_k<<<(25096*768 + 255)/256, 256>>>(x, xh, 25096*768);
    {
        dim3 wb(32, 8);
        dim3 wg(768/32, 2304/32);
        wconvh_k<<<wg, wb>>>(Wq, Wall,              768, 2304);
        wconvh_k<<<wg, wb>>>(Wk, Wall + 2304*768,   768, 2304);
        wconvh_k<<<wg, wb>>>(Wv, Wall + 4608*768,   768, 2304);
        dim3 wg2(2304/32, 768/32);
        wconvh_k<<<wg2, wb>>>(Wt, Wth, 2304, 768);
    }

    // fused QKV projections of x: 25096 x (3x2304), K=768, single-term
    hgemm3s_k<<<dim3(54, (25096 + 127)/128), 256, HG3_SMEM>>>(
        xh, Wall, bq, bk, bv, Pq, Pk, Pv, 25096, 768);

    // grouped frame attention -> tmp (1560 x 2304)
    grattn_k<<<dim3(195, 12, 8), 256>>>();

    // ti = tmp @ Wt + bt : 1560 x 768, K=2304 (2-term)
    conv_k<<<(1560*2304 + 255)/256, 256>>>(tmp, th, tl, 1560*2304);
    hgemm_k<<<dim3(768/128, (1560 + 127)/128), 256, HG_SMEM>>>(
        th, tl, Wth, bt, ti, 1560, 768, 2304);

    // QKV on ti: 1560 x 2304 x3, K=768 (2-term, three slices of Wall)
    conv_k<<<(1560*768 + 255)/256, 256>>>(ti, tih, til, 1560*768);
    {
        dim3 grid(18, (1560 + 127)/128);
        hgemm_k<<<grid, 256, HG_SMEM>>>(tih, til, Wall,            bq, Aq, 1560, 2304, 768);
        hgemm_k<<<grid, 256, HG_SMEM>>>(tih, til, Wall + 2304*768, bk, Ak, 1560, 2304, 768);
        hgemm_k<<<grid, 256, HG_SMEM>>>(tih, til, Wall + 4608*768, bv, Av, 1560, 2304, 768);
    }

    // cls attention -> U row 0
    cls_k<<<dim3(12, 8), 512>>>();

    // xi = 0 attention -> U row 1
    s0_k<<<dim3(7, 7, 96), 256>>>();
    soft0_k<<<96, 256>>>();

    // xi = 1..15 -> U rows 2..16
    attn2x_k<<<dim3(15, 12, 8), 256>>>();

    // Ou = U @ Wf + bf : 136 x 768, K=2304 (tiny, fp32)
    sgemm64_k<<<dim3(768/64, (136 + 63)/64), 256>>>(U, Wf, bf, Ou, 136, 768, 2304);

    // broadcast to output
    scatter_k<<<(int)(((size_t)8*3137*768 + 255)/256), 256>>>(out);
}

// round 15
// speedup vs baseline: 3.5641x; 1.1040x over previous
#include <cuda_runtime.h>
#include <cuda_fp16.h>
#include <math.h>
#include <cstdint>

// ---------------------------------------------------------------------------
// dividedSpaceTimeAttention  (B=8, NH=12, DIM=768, NP=196, NF=16, DH=64)
// Round 14: P buffers fp16 (halve store+read traffic), conversions fused into
// producer epilogues, QKV-ti single fused launch, 3-stage cp.async pipeline.
// ---------------------------------------------------------------------------

#define SCALE_C (1.0f/96.0f)

// ------------------------- scratch (device globals) ------------------------
__device__ __align__(256) __half g_Pqh[57821184];     // 8*3137*2304 fp16
__device__ __align__(256) __half g_Pkh[57821184];
__device__ __align__(256) __half g_Pvh[57821184];
__device__ float g_Aq [8*195*2304];
__device__ float g_Ak [8*195*2304];
__device__ float g_Av [8*195*2304];
__device__ float g_S  [96*195*195];
__device__ float g_U  [8*17*2304];
__device__ float g_Ou [8*17*768];
__device__ float g_cos[3136*32];
__device__ float g_sin[3136*32];

// fp16 operands
__device__ __align__(256) __half g_xh [25096*768];
__device__ __align__(256) __half g_Wall[6912*768];     // [Wq^T; Wk^T; Wv^T]
__device__ __align__(256) __half g_Wth[768*2304];      // Wt^T
__device__ __align__(256) __half g_th [1560*2304], g_tl [1560*2304];
__device__ __align__(256) __half g_tih[1560*768],  g_til[1560*768];

// ------------------------- helpers ---------------------------
__device__ __forceinline__ uint32_t smem_to_u32(const void* p) {
    uint32_t a;
    asm("{ .reg .u64 t; cvta.to.shared.u64 t, %1; cvt.u32.u64 %0, t; }"
        : "=r"(a) : "l"(p));
    return a;
}
#define CP_ASYNC16(dst, src) \
    asm volatile("cp.async.cg.shared.global [%0], [%1], 16;" :: "r"(dst), "l"(src))
#define CP_COMMIT() asm volatile("cp.async.commit_group;")

__device__ __forceinline__ void ldmatrix_x4(uint32_t* r, uint32_t addr) {
    asm volatile("ldmatrix.sync.aligned.m8n8.x4.shared.b16 {%0,%1,%2,%3}, [%4];"
        : "=r"(r[0]), "=r"(r[1]), "=r"(r[2]), "=r"(r[3]) : "r"(addr));
}
__device__ __forceinline__ void mma16816(float* c, const uint32_t* a, const uint32_t* b) {
    asm volatile("mma.sync.aligned.m16n8k16.row.col.f32.f16.f16.f32 "
        "{%0,%1,%2,%3}, {%4,%5,%6,%7}, {%8,%9}, {%0,%1,%2,%3};"
        : "+f"(c[0]), "+f"(c[1]), "+f"(c[2]), "+f"(c[3])
        : "r"(a[0]), "r"(a[1]), "r"(a[2]), "r"(a[3]), "r"(b[0]), "r"(b[1]));
}

// ---------------------------------------------------------------------------
// single-term fused QKV hgemm, fp16 OUTPUT: C_sel[M,2304] = A@Wsel^T + b_sel
// grid (54, ceil(M/128)), 256 threads, smem 96KB (3 x 32KB stage).
// ---------------------------------------------------------------------------
__global__ void __launch_bounds__(256, 2) hgemm3s_k(
    const __half* __restrict__ A, const __half* __restrict__ W,
    const float* __restrict__ b0, const float* __restrict__ b1, const float* __restrict__ b2,
    __half* __restrict__ C0, __half* __restrict__ C1, __half* __restrict__ C2,
    int M, int K)
{
    extern __shared__ char smem[];
    const uint32_t sb = smem_to_u32(smem);
    const int tid = threadIdx.x;
    const int wid = tid >> 5, lane = tid & 31;
    const int sel = blockIdx.x / 18;
    const int bn = (blockIdx.x % 18) * 128;
    const int bm = blockIdx.y * 128;
    const int wm = (wid >> 2) * 64;
    const int wn = (wid & 3) * 32;
    const float* bias = (sel == 0) ? b0 : ((sel == 1) ? b1 : b2);
    __half* C = (sel == 0) ? C0 : ((sel == 1) ? C1 : C2);
    const int brow0 = sel * 2304 + bn;

    float acc[4][4][4];
#pragma unroll
    for (int i = 0; i < 4; i++)
#pragma unroll
        for (int j = 0; j < 4; j++)
#pragma unroll
            for (int r = 0; r < 4; r++) acc[i][j][r] = 0.f;

    const int G = K >> 6;
    const int lrow = tid >> 1;
    const int lc0 = (tid & 1) * 4;

    auto ISSUE = [&](int g) {
        const int k0 = g << 6;
        const uint32_t base = sb + (g % 3) * 32768;
        int ga = bm + lrow; if (ga >= M) ga = M - 1;
        const __half* ap = A + (size_t)ga * K + k0 + lc0 * 8;
        const __half* bp = W + (size_t)(brow0 + lrow) * K + k0 + lc0 * 8;
#pragma unroll
        for (int j = 0; j < 4; j++) {
            const uint32_t sw = (uint32_t)(lrow * 128 + (((lc0 + j) ^ (lrow & 7)) << 4));
            CP_ASYNC16(base + sw,         ap + j * 8);
            CP_ASYNC16(base + 16384 + sw, bp + j * 8);
        }
        CP_COMMIT();
    };

    ISSUE(0);
    if (G > 1) ISSUE(1);
    for (int g = 0; g < G; g++) {
        if (g + 2 < G) {
            ISSUE(g + 2);
            asm volatile("cp.async.wait_group 2;");
        } else {
            asm volatile("cp.async.wait_group 0;");
        }
        __syncthreads();
        const uint32_t base = sb + (g % 3) * 32768;
#pragma unroll
        for (int ks = 0; ks < 4; ks++) {
            uint32_t af[4][4], bb[2][4];
#pragma unroll
            for (int mf = 0; mf < 4; mf++) {
                const int row = wm + mf * 16 + (lane & 15);
                const int c16 = ks * 2 + (lane >> 4);
                ldmatrix_x4(af[mf], base + row * 128 + ((c16 ^ (row & 7)) << 4));
            }
#pragma unroll
            for (int nh = 0; nh < 2; nh++) {
                const int row = wn + nh * 16 + (lane & 7) + ((lane & 16) >> 1);
                const int c16 = ks * 2 + ((lane >> 3) & 1);
                ldmatrix_x4(bb[nh], base + 16384 + row * 128 + ((c16 ^ (row & 7)) << 4));
            }
#pragma unroll
            for (int mf = 0; mf < 4; mf++)
#pragma unroll
                for (int nf = 0; nf < 4; nf++)
                    mma16816(acc[mf][nf], af[mf], bb[nf >> 1] + (nf & 1) * 2);
        }
        __syncthreads();
    }

    const int r0 = lane >> 2;
    const int c0 = (lane & 3) * 2;
#pragma unroll
    for (int mf = 0; mf < 4; mf++) {
        const int row0 = bm + wm + mf * 16 + r0;
#pragma unroll
        for (int half = 0; half < 2; half++) {
            const int row = row0 + half * 8;
            if (row < M) {
                __half* Cr = C + (size_t)row * 2304 + bn + wn;
                const float* bp = bias + bn + wn;
#pragma unroll
                for (int nf = 0; nf < 4; nf++) {
                    const int col = nf * 8 + c0;
                    float v0 = acc[mf][nf][half * 2 + 0] + bp[col];
                    float v1 = acc[mf][nf][half * 2 + 1] + bp[col + 1];
                    *(__half2*)(Cr + col) = __floats2half2_rn(v0, v1);
                }
            }
        }
    }
}

// ---------------------------------------------------------------------------
// 2-term fused QKV hgemm, fp32 OUTPUT: C_sel[M,2304] = (Ah+Al)@Wsel^T + b_sel
// grid (54, ceil(M/128)), smem 96KB (2 x 48KB stage).
// ---------------------------------------------------------------------------
__global__ void __launch_bounds__(256, 2) hgemm3_k(
    const __half* __restrict__ Ah, const __half* __restrict__ Al,
    const __half* __restrict__ W,
    const float* __restrict__ b0, const float* __restrict__ b1, const float* __restrict__ b2,
    float* __restrict__ C0, float* __restrict__ C1, float* __restrict__ C2,
    int M, int K)
{
    extern __shared__ char smem[];
    const uint32_t sb = smem_to_u32(smem);
    const int tid = threadIdx.x;
    const int wid = tid >> 5, lane = tid & 31;
    const int sel = blockIdx.x / 18;
    const int bn = (blockIdx.x % 18) * 128;
    const int bm = blockIdx.y * 128;
    const int wm = (wid >> 2) * 64;
    const int wn = (wid & 3) * 32;
    const float* bias = (sel == 0) ? b0 : ((sel == 1) ? b1 : b2);
    float* C = (sel == 0) ? C0 : ((sel == 1) ? C1 : C2);
    const int brow0 = sel * 2304 + bn;

    float acc[4][4][4];
#pragma unroll
    for (int i = 0; i < 4; i++)
#pragma unroll
        for (int j = 0; j < 4; j++)
#pragma unroll
            for (int r = 0; r < 4; r++) acc[i][j][r] = 0.f;

    const int G = K >> 6;
    const int lrow = tid >> 1;
    const int lc0 = (tid & 1) * 4;

    auto ISSUE = [&](int g) {
        const int k0 = g << 6;
        const uint32_t base = sb + (g & 1) * 49152;
        int ga = bm + lrow; if (ga >= M) ga = M - 1;
        const size_t aoff = (size_t)ga * K + k0 + lc0 * 8;
#pragma unroll
        for (int j = 0; j < 4; j++) {
            const uint32_t sw = (uint32_t)(lrow * 128 + (((lc0 + j) ^ (lrow & 7)) << 4));
            CP_ASYNC16(base + sw,         Ah + aoff + j * 8);
            CP_ASYNC16(base + 16384 + sw, Al + aoff + j * 8);
            CP_ASYNC16(base + 32768 + sw, W + (size_t)(brow0 + lrow) * K + k0 + lc0 * 8 + j * 8);
        }
        CP_COMMIT();
    };

    ISSUE(0);
    for (int g = 0; g < G; g++) {
        if (g + 1 < G) {
            ISSUE(g + 1);
            asm volatile("cp.async.wait_group 1;");
        } else {
            asm volatile("cp.async.wait_group 0;");
        }
        __syncthreads();
        const uint32_t base = sb + (g & 1) * 49152;
#pragma unroll
        for (int ks = 0; ks < 4; ks++) {
            uint32_t ah[4][4], al[4][4], bb[2][4];
#pragma unroll
            for (int mf = 0; mf < 4; mf++) {
                const int row = wm + mf * 16 + (lane & 15);
                const int c16 = ks * 2 + (lane >> 4);
                const uint32_t off = row * 128 + ((c16 ^ (row & 7)) << 4);
                ldmatrix_x4(ah[mf], base + off);
                ldmatrix_x4(al[mf], base + 16384 + off);
            }
#pragma unroll
            for (int nh = 0; nh < 2; nh++) {
                const int row = wn + nh * 16 + (lane & 7) + ((lane & 16) >> 1);
                const int c16 = ks * 2 + ((lane >> 3) & 1);
                ldmatrix_x4(bb[nh], base + 32768 + row * 128 + ((c16 ^ (row & 7)) << 4));
            }
#pragma unroll
            for (int mf = 0; mf < 4; mf++)
#pragma unroll
                for (int nf = 0; nf < 4; nf++)
                    mma16816(acc[mf][nf], ah[mf], bb[nf >> 1] + (nf & 1) * 2);
#pragma unroll
            for (int mf = 0; mf < 4; mf++)
#pragma unroll
                for (int nf = 0; nf < 4; nf++)
                    mma16816(acc[mf][nf], al[mf], bb[nf >> 1] + (nf & 1) * 2);
        }
        __syncthreads();
    }

    const int r0 = lane >> 2;
    const int c0 = (lane & 3) * 2;
#pragma unroll
    for (int mf = 0; mf < 4; mf++) {
        const int row0 = bm + wm + mf * 16 + r0;
#pragma unroll
        for (int half = 0; half < 2; half++) {
            const int row = row0 + half * 8;
            if (row < M) {
                float* Cr = C + (size_t)row * 2304 + bn + wn;
                const float* bp = bias + bn + wn;
#pragma unroll
                for (int nf = 0; nf < 4; nf++) {
                    const int col = nf * 8 + c0;
                    Cr[col]     = acc[mf][nf][half * 2 + 0] + bp[col];
                    Cr[col + 1] = acc[mf][nf][half * 2 + 1] + bp[col + 1];
                }
            }
        }
    }
}

// ---------------------------------------------------------------------------
// 2-term hgemm, hi/lo fp16 OUTPUT (for ti): Th/Tl = split((Ah+Al)@Bt^T + bias)
// ---------------------------------------------------------------------------
__global__ void __launch_bounds__(256, 2) hgemm_hl_k(
    const __half* __restrict__ Ah, const __half* __restrict__ Al,
    const __half* __restrict__ Bt,
    const float* __restrict__ bias,
    __half* __restrict__ Th, __half* __restrict__ Tl,
    int M, int N, int K)
{
    extern __shared__ char smem[];
    const uint32_t sb = smem_to_u32(smem);
    const int tid = threadIdx.x;
    const int wid = tid >> 5, lane = tid & 31;
    const int bm = blockIdx.y * 128, bn = blockIdx.x * 128;
    const int wm = (wid >> 2) * 64;
    const int wn = (wid & 3) * 32;

    float acc[4][4][4];
#pragma unroll
    for (int i = 0; i < 4; i++)
#pragma unroll
        for (int j = 0; j < 4; j++)
#pragma unroll
            for (int r = 0; r < 4; r++) acc[i][j][r] = 0.f;

    const int G = K >> 6;
    const int lrow = tid >> 1;
    const int lc0 = (tid & 1) * 4;

    auto ISSUE = [&](int g) {
        const int k0 = g << 6;
        const uint32_t base = sb + (g & 1) * 49152;
        int ga = bm + lrow; if (ga >= M) ga = M - 1;
        const size_t aoff = (size_t)ga * K + k0 + lc0 * 8;
#pragma unroll
        for (int j = 0; j < 4; j++) {
            const uint32_t sw = (uint32_t)(lrow * 128 + (((lc0 + j) ^ (lrow & 7)) << 4));
            CP_ASYNC16(base + sw,         Ah + aoff + j * 8);
            CP_ASYNC16(base + 16384 + sw, Al + aoff + j * 8);
            CP_ASYNC16(base + 32768 + sw, Bt + (size_t)(bn + lrow) * K + k0 + lc0 * 8 + j * 8);
        }
        CP_COMMIT();
    };

    ISSUE(0);
    for (int g = 0; g < G; g++) {
        if (g + 1 < G) {
            ISSUE(g + 1);
            asm volatile("cp.async.wait_group 1;");
        } else {
            asm volatile("cp.async.wait_group 0;");
        }
        __syncthreads();
        const uint32_t base = sb + (g & 1) * 49152;
#pragma unroll
        for (int ks = 0; ks < 4; ks++) {
            uint32_t ah[4][4], al[4][4], bb[2][4];
#pragma unroll
            for (int mf = 0; mf < 4; mf++) {
                const int row = wm + mf * 16 + (lane & 15);
                const int c16 = ks * 2 + (lane >> 4);
                const uint32_t off = row * 128 + ((c16 ^ (row & 7)) << 4);
                ldmatrix_x4(ah[mf], base + off);
                ldmatrix_x4(al[mf], base + 16384 + off);
            }
#pragma unroll
            for (int nh = 0; nh < 2; nh++) {
                const int row = wn + nh * 16 + (lane & 7) + ((lane & 16) >> 1);
                const int c16 = ks * 2 + ((lane >> 3) & 1);
                ldmatrix_x4(bb[nh], base + 32768 + row * 128 + ((c16 ^ (row & 7)) << 4));
            }
#pragma unroll
            for (int mf = 0; mf < 4; mf++)
#pragma unroll
                for (int nf = 0; nf < 4; nf++)
                    mma16816(acc[mf][nf], ah[mf], bb[nf >> 1] + (nf & 1) * 2);
#pragma unroll
            for (int mf = 0; mf < 4; mf++)
#pragma unroll
                for (int nf = 0; nf < 4; nf++)
                    mma16816(acc[mf][nf], al[mf], bb[nf >> 1] + (nf & 1) * 2);
        }
        __syncthreads();
    }

    const int r0 = lane >> 2;
    const int c0 = (lane & 3) * 2;
#pragma unroll
    for (int mf = 0; mf < 4; mf++) {
        const int row0 = bm + wm + mf * 16 + r0;
#pragma unroll
        for (int half = 0; half < 2; half++) {
            const int row = row0 + half * 8;
            if (row < M) {
                const float* bp = bias + bn + wn;
#pragma unroll
                for (int nf = 0; nf < 4; nf++) {
                    const int col = nf * 8 + c0;
                    float v0 = acc[mf][nf][half * 2 + 0] + bp[col];
                    float v1 = acc[mf][nf][half * 2 + 1] + bp[col + 1];
                    __half h0 = __float2half_rn(v0), h1 = __float2half_rn(v1);
                    size_t o = (size_t)row * N + bn + wn + col;
                    *(__half2*)(Th + o) = __halves2half2(h0, h1);
                    *(__half2*)(Tl + o) = __floats2half2_rn(v0 - __half2float(h0),
                                                            v1 - __half2float(h1));
                }
            }
        }
    }
}

// ---------------------------------------------------------------------------
// conversions
// ---------------------------------------------------------------------------
__global__ void convh_k(const float* __restrict__ s, __half* __restrict__ h, int n) {
    int i = blockIdx.x * 256 + threadIdx.x;
    if (i >= n) return;
    h[i] = __float2half_rn(s[i]);
}

// W[K,N] -> T[N,K] (transpose, single fp16)
__global__ void wconvh_k(const float* __restrict__ W, __half* __restrict__ T,
                         int K, int N) {
    __shared__ float tile[32][33];
    const int k0 = blockIdx.x * 32, n0 = blockIdx.y * 32;
    const int tx = threadIdx.x, ty = threadIdx.y;
    for (int r = ty; r < 32; r += 8) {
        int k = k0 + r, n = n0 + tx;
        tile[r][tx] = (k < K && n < N) ? W[(size_t)k * N + n] : 0.f;
    }
    __syncthreads();
    for (int r = ty; r < 32; r += 8) {
        int n = n0 + r, k = k0 + tx;
        if (n < N && k < K)
            T[(size_t)n * K + k] = __float2half_rn(tile[tx][r]);
    }
}

// ---------------------------------------------------------------------------
__global__ void rope_init_k() {
    int idx = blockIdx.x * 256 + threadIdx.x;
    if (idx >= 3136*32) return;
    int s = idx >> 5, i = idx & 31;
    float e = (float)(2*i) / 64.f;
    float invf = 1.f / powf(10000.f, e);
    float ang = (float)s * invf;
    g_cos[idx] = (float)cos((double)ang);
    g_sin[idx] = (float)sin((double)ang);
}

// small fp32 GEMM (final 136-row): 64x64 tile, 4x4/thread
__global__ void __launch_bounds__(256) sgemm64_k(
    const float* __restrict__ A, const float* __restrict__ B,
    const float* __restrict__ bias, float* __restrict__ C,
    int M, int N, int K)
{
    __shared__ float As[8][64];
    __shared__ float Bs[8][64];
    const int bm = blockIdx.y * 64, bn = blockIdx.x * 64;
    const int tid = threadIdx.x;
    const int tx = tid & 15, ty = tid >> 4;
    const int arow = tid >> 2, acol = (tid & 3) * 2;
    const int brow = tid >> 5, bcol = (tid & 31) * 2;
    float acc[4][4];
#pragma unroll
    for (int i = 0; i < 4; i++)
#pragma unroll
        for (int j = 0; j < 4; j++) acc[i][j] = 0.f;
    const bool arow_ok = (bm + arow) < M;
    for (int k0 = 0; k0 < K; k0 += 8) {
        float2 av = make_float2(0.f, 0.f);
        if (arow_ok) av = *(const float2*)(A + (size_t)(bm + arow) * K + k0 + acol);
        As[acol][arow] = av.x;  As[acol + 1][arow] = av.y;
        float2 bv = *(const float2*)(B + (size_t)(k0 + brow) * N + bn + bcol);
        Bs[brow][bcol] = bv.x;  Bs[brow][bcol + 1] = bv.y;
        __syncthreads();
#pragma unroll
        for (int kk = 0; kk < 8; kk++) {
            float ar[4], br[4];
#pragma unroll
            for (int i = 0; i < 4; i++) ar[i] = As[kk][ty * 4 + i];
#pragma unroll
            for (int j = 0; j < 4; j++) br[j] = Bs[kk][tx * 4 + j];
#pragma unroll
            for (int i = 0; i < 4; i++)
#pragma unroll
                for (int j = 0; j < 4; j++)
                    acc[i][j] += ar[i] * br[j];
        }
        __syncthreads();
    }
#pragma unroll
    for (int i = 0; i < 4; i++) {
        int m = bm + ty * 4 + i;
        if (m < M)
#pragma unroll
            for (int j = 0; j < 4; j++)
                C[(size_t)m * N + bn + tx * 4 + j] = acc[i][j] + bias[bn + tx * 4 + j];
    }
}

// ---------------------------------------------------------------------------
// Grouped frame-attention (fp16 P inputs); writes th/tl hi-lo split directly
// ---------------------------------------------------------------------------
#define GA 196
__global__ void __launch_bounds__(256) grattn_k() {
    const int p = blockIdx.x + 1;
    const int h = blockIdx.y;
    const int b = blockIdx.z;
    __shared__ float qs[16*GA], ks[16*GA], vs[16*GA];
    __shared__ float S[256], wg[16];
    const int tid = threadIdx.x;

    for (int idx = tid; idx < 16*96; idx += 256) {
        int f = idx / 96, d2 = (idx - f * 96) * 2;
        size_t off = ((size_t)(b * 3137 + 1 + f * 196 + p)) * 2304 + h * 192 + d2;
        float2 q2 = __half22float2(*(const __half2*)(g_Pqh + off));
        float2 k2 = __half22float2(*(const __half2*)(g_Pvh + off));
        float2 v2 = __half22float2(*(const __half2*)(g_Pkh + off));
        qs[f*GA + d2] = q2.x;  qs[f*GA + d2 + 1] = q2.y;
        ks[f*GA + d2] = k2.x;  ks[f*GA + d2 + 1] = k2.y;
        vs[f*GA + d2] = v2.x;  vs[f*GA + d2 + 1] = v2.y;
    }
    __syncthreads();
    for (int idx = tid; idx < 16*32; idx += 256) {
        int f = idx >> 5, i = idx & 31;
        int s = f * 196 + p;
        float c = g_cos[s*32 + i], sn = g_sin[s*32 + i];
        float a0 = qs[f*GA + 2*i], a1 = qs[f*GA + 2*i + 1];
        qs[f*GA + 2*i]     = a0 * c - a1 * sn;
        qs[f*GA + 2*i + 1] = a1 * c + a0 * sn;
        float b0 = ks[f*GA + 2*i], b1 = ks[f*GA + 2*i + 1];
        ks[f*GA + 2*i]     = b0 * c - b1 * sn;
        ks[f*GA + 2*i + 1] = b1 * c + b0 * sn;
    }
    __syncthreads();
    {
        int f = tid >> 4, g = tid & 15;
        const float* qp = qs + f * GA;
        const float* kp = ks + g * GA;
        float s = 0.f;
#pragma unroll
        for (int d = 0; d < 192; d += 4) {
            float4 a = *(const float4*)(qp + d);
            float4 bv = *(const float4*)(kp + d);
            s += a.x*bv.x + a.y*bv.y + a.z*bv.z + a.w*bv.w;
        }
        S[tid] = s * SCALE_C;
    }
    __syncthreads();
    if (tid < 16) {
        float m = -1e30f;
        for (int g = 0; g < 16; g++) m = fmaxf(m, S[tid*16 + g]);
        float sum = 0.f;
        for (int g = 0; g < 16; g++) { float e = expf(S[tid*16 + g] - m); S[tid*16 + g] = e; sum += e; }
        float inv = 1.f / sum;
        for (int g = 0; g < 16; g++) S[tid*16 + g] *= inv;
    }
    __syncthreads();
    if (tid < 16) {
        float a = 0.f;
        for (int f = 0; f < 16; f++) a += S[f*16 + tid];
        wg[tid] = a;
    }
    __syncthreads();
    if (tid < 192) {
        float o = 0.f;
#pragma unroll
        for (int g = 0; g < 16; g++) o += wg[g] * vs[g*GA + tid];
        size_t off = ((size_t)(b * 195 + (p - 1))) * 2304 + h * 192 + tid;
        __half hv = __float2half_rn(o);
        g_th[off] = hv;
        g_tl[off] = __float2half_rn(o - __half2float(hv));
    }
}

// ---------------------------------------------------------------------------
// CLS attention (fp16 P inputs): 512 threads, warp-parallel w@V
// ---------------------------------------------------------------------------
__global__ void __launch_bounds__(512) cls_k() {
    const int h = blockIdx.x, b = blockIdx.y;
    __shared__ float qv[192];
    __shared__ float Sv[3137];
    __shared__ float red[512];
    __shared__ float red2[16][192];
    const int tid = threadIdx.x;
    const int warp = tid >> 5, lane = tid & 31;
    const __half* Pq_ = g_Pqh + (size_t)b*3137*2304 + h*192;
    const __half* Pk_ = g_Pkh + (size_t)b*3137*2304 + h*192;
    const __half* Pv_ = g_Pvh + (size_t)b*3137*2304 + h*192;
    if (tid < 96) {
        float2 v = __half22float2(*(const __half2*)(Pq_ + tid * 2));
        qv[tid*2] = v.x;  qv[tid*2 + 1] = v.y;
    }
    __syncthreads();
    float lm = -1e30f;
    for (int t = tid; t < 3137; t += 512) {
        const __half* kr = Pk_ + (size_t)t*2304;
        float s = 0.f;
        for (int d = 0; d < 192; d += 8) {
            uint4 raw = *(const uint4*)(kr + d);
            const __half2* k2 = (const __half2*)&raw;
            float2 f0 = __half22float2(k2[0]);
            float2 f1 = __half22float2(k2[1]);
            float2 f2 = __half22float2(k2[2]);
            float2 f3 = __half22float2(k2[3]);
            s += f0.x*qv[d]   + f0.y*qv[d+1] + f1.x*qv[d+2] + f1.y*qv[d+3]
               + f2.x*qv[d+4] + f2.y*qv[d+5] + f3.x*qv[d+6] + f3.y*qv[d+7];
        }
        s *= SCALE_C;
        Sv[t] = s;
        lm = fmaxf(lm, s);
    }
    red[tid] = lm; __syncthreads();
    for (int s2 = 256; s2 > 0; s2 >>= 1) {
        if (tid < s2) red[tid] = fmaxf(red[tid], red[tid + s2]);
        __syncthreads();
    }
    const float m = red[0];
    __syncthreads();
    float ls = 0.f;
    for (int t = tid; t < 3137; t += 512) { float e = expf(Sv[t] - m); Sv[t] = e; ls += e; }
    red[tid] = ls; __syncthreads();
    for (int s2 = 256; s2 > 0; s2 >>= 1) {
        if (tid < s2) red[tid] += red[tid + s2];
        __syncthreads();
    }
    const float inv = 1.f / red[0];
    float o[6];
#pragma unroll
    for (int i = 0; i < 6; i++) o[i] = 0.f;
    for (int t = warp; t < 3137; t += 16) {
        const float w = Sv[t];
        const __half* vr = Pv_ + (size_t)t*2304;
#pragma unroll
        for (int i = 0; i < 6; i++) o[i] += w * __half2float(vr[i*32 + lane]);
    }
#pragma unroll
    for (int i = 0; i < 6; i++) red2[warp][i*32 + lane] = o[i];
    __syncthreads();
    if (tid < 192) {
        float s = 0.f;
#pragma unroll
        for (int w = 0; w < 16; w++) s += red2[w][tid];
        g_U[((size_t)b*17 + 0)*2304 + h*192 + tid] = s * inv;
    }
}

// ---------------------------------------------------------------------------
// xi=0 scores
// ---------------------------------------------------------------------------
__global__ void __launch_bounds__(256) s0_k() {
    const int bh = blockIdx.z;
    const int b = bh / 12, h = bh % 12;
    const int i0 = blockIdx.y * 32, j0 = blockIdx.x * 32;
    __shared__ float Qs[16][33], Ks[16][33];
    const int tid = threadIdx.x;
    const int tx = tid & 15, ty = tid >> 4;
    const float* Abase = g_Aq + (size_t)b*195*2304 + h*192;
    const float* Bbase = g_Av + (size_t)b*195*2304 + h*192;
    float acc00 = 0.f, acc01 = 0.f, acc10 = 0.f, acc11 = 0.f;
    const int r = tid >> 3;
    const int c = (tid & 7) * 2;
    for (int k0 = 0; k0 < 192; k0 += 16) {
        int qi = i0 + r;
        float2 qv = make_float2(0.f, 0.f);
        if (qi < 195) qv = *(const float2*)(Abase + (size_t)qi*2304 + k0 + c);
        Qs[c][r] = qv.x; Qs[c+1][r] = qv.y;
        int kj = j0 + r;
        float2 kv = make_float2(0.f, 0.f);
        if (kj < 195) kv = *(const float2*)(Bbase + (size_t)kj*2304 + k0 + c);
        Ks[c][r] = kv.x; Ks[c+1][r] = kv.y;
        __syncthreads();
#pragma unroll
        for (int kk = 0; kk < 16; kk++) {
            float a0 = Qs[kk][ty*2], a1 = Qs[kk][ty*2+1];
            float b0 = Ks[kk][tx*2], b1 = Ks[kk][tx*2+1];
            acc00 += a0*b0; acc01 += a0*b1; acc10 += a1*b0; acc11 += a1*b1;
        }
        __syncthreads();
    }
    float* Sp = g_S + (size_t)bh*195*195;
    int ii = i0 + ty*2, jj = j0 + tx*2;
    if (ii < 195) {
        if (jj   < 195) Sp[(size_t)ii*195 + jj  ] = acc00 * SCALE_C;
        if (jj+1 < 195) Sp[(size_t)ii*195 + jj+1] = acc01 * SCALE_C;
    }
    if (ii+1 < 195) {
        if (jj   < 195) Sp[(size_t)(ii+1)*195 + jj  ] = acc10 * SCALE_C;
        if (jj+1 < 195) Sp[(size_t)(ii+1)*195 + jj+1] = acc11 * SCALE_C;
    }
}

// ---------------------------------------------------------------------------
// xi=0 softmax + w@V
// ---------------------------------------------------------------------------
__global__ void __launch_bounds__(256) soft0_k() {
    const int bh = blockIdx.x;
    const int b = bh / 12, h = bh % 12;
    const float* S = g_S + (size_t)bh*195*195;
    __shared__ float wk_s[195];
    const int tid = threadIdx.x;
    if (tid < 195) wk_s[tid] = 0.f;
    __syncthreads();
    const int warp = tid >> 5, lane = tid & 31;
    for (int q = warp; q < 195; q += 8) {
        const float* Sq = S + (size_t)q*195;
        float m = -1e30f;
        for (int k = lane; k < 195; k += 32) m = fmaxf(m, Sq[k]);
        for (int o = 16; o; o >>= 1) m = fmaxf(m, __shfl_xor_sync(0xFFFFFFFFu, m, o));
        float sum = 0.f;
        for (int k = lane; k < 195; k += 32) sum += expf(Sq[k] - m);
        if (lane == 0) sum += expf(Sq[0] - m);
        for (int o = 16; o; o >>= 1) sum += __shfl_xor_sync(0xFFFFFFFFu, sum, o);
        const float inv = 1.f / sum;
        const float mult = (q == 0) ? 2.f : 1.f;
        for (int k = lane; k < 195; k += 32) {
            float w = expf(Sq[k] - m) * inv * mult;
            if (k == 0) w *= 2.f;
            atomicAdd(&wk_s[k], w);
        }
    }
    __syncthreads();
    if (tid < 192) {
        const float* V = g_Ak + (size_t)b*195*2304 + h*192 + tid;
        float o = 0.f;
        for (int k = 0; k < 195; k++) o += wk_s[k] * V[(size_t)k*2304];
        g_U[((size_t)b*17 + 1)*2304 + h*192 + tid] = o;
    }
}

// ---------------------------------------------------------------------------
// xi=1..15
// ---------------------------------------------------------------------------
__global__ void __launch_bounds__(256) attn2x_k() {
    const int xi = blockIdx.x + 1;
    const int h = blockIdx.y, b = blockIdx.z;
    __shared__ float Ksm[16][192];
    __shared__ float Vsm[16][192];
    __shared__ float wk[16];
    const int tid = threadIdx.x;
    for (int idx = tid; idx < 16*192; idx += 256) {
        int j = idx / 192, d = idx - j*192;
        size_t ro = ((size_t)(b*195 + xi + j))*2304 + h*192 + d;
        Ksm[j][d] = g_Av[ro];
        Vsm[j][d] = g_Ak[ro];
    }
    if (tid < 16) wk[tid] = 0.f;
    __syncthreads();
    const int q = tid;
    if (q < 195) {
        const float* Arow = g_Aq + ((size_t)(b*195 + q))*2304 + h*192;
        float s[16];
#pragma unroll
        for (int j = 0; j < 16; j++) s[j] = 0.f;
        for (int d = 0; d < 192; d += 4) {
            float4 qv = *(const float4*)(Arow + d);
#pragma unroll
            for (int j = 0; j < 16; j++)
                s[j] += qv.x*Ksm[j][d] + qv.y*Ksm[j][d+1] + qv.z*Ksm[j][d+2] + qv.w*Ksm[j][d+3];
        }
        float m = -1e30f;
#pragma unroll
        for (int j = 0; j < 16; j++) { s[j] *= SCALE_C; m = fmaxf(m, s[j]); }
        float sum = 0.f;
#pragma unroll
        for (int j = 0; j < 16; j++) { s[j] = expf(s[j] - m); sum += s[j]; }
        const float w = ((q == xi) ? 2.f : 1.f) / sum;
#pragma unroll
        for (int j = 0; j < 16; j++) atomicAdd(&wk[j], s[j] * w);
    }
    __syncthreads();
    if (tid < 192) {
        float o = 0.f;
#pragma unroll
        for (int j = 0; j < 16; j++) o += wk[j] * Vsm[j][tid];
        g_U[((size_t)b*17 + xi + 1)*2304 + h*192 + tid] = o;
    }
}

// ---------------------------------------------------------------------------
__global__ void scatter_k(float* __restrict__ out) {
    size_t idx = (size_t)blockIdx.x * 256 + threadIdx.x;
    const size_t total = (size_t)8 * 3137 * 768;
    if (idx >= total) return;
    int b = (int)(idx / (3137*768));
    int r = (int)(idx % (3137*768));
    int s = r / 768, d = r - s*768;
    int row = (s == 0) ? 0 : 1 + (s - 1) % 16;
    out[idx] = g_Ou[((size_t)b*17 + row)*768 + d];
}

// ---------------------------------------------------------------------------
extern "C" void kernel_launch(void* const* d_in, const int* in_sizes, int n_in,
                              void* d_out, int out_size) {
    const float* x  = (const float*)d_in[0];
    const float* Wq = (const float*)d_in[1];
    const float* bq = (const float*)d_in[2];
    const float* Wk = (const float*)d_in[3];
    const float* bk = (const float*)d_in[4];
    const float* Wv = (const float*)d_in[5];
    const float* bv = (const float*)d_in[6];
    const float* Wt = (const float*)d_in[7];
    const float* bt = (const float*)d_in[8];
    const float* Wf = (const float*)d_in[9];
    const float* bf = (const float*)d_in[10];
    float* out = (float*)d_out;

    float *Aq, *Ak, *Av, *U, *Ou;
    cudaGetSymbolAddress((void**)&Aq,  g_Aq);
    cudaGetSymbolAddress((void**)&Ak,  g_Ak);
    cudaGetSymbolAddress((void**)&Av,  g_Av);
    cudaGetSymbolAddress((void**)&U,   g_U);
    cudaGetSymbolAddress((void**)&Ou,  g_Ou);

    __half *Pq, *Pk, *Pv, *xh, *Wall, *Wth, *th, *tl, *tih, *til;
    cudaGetSymbolAddress((void**)&Pq,   g_Pqh);
    cudaGetSymbolAddress((void**)&Pk,   g_Pkh);
    cudaGetSymbolAddress((void**)&Pv,   g_Pvh);
    cudaGetSymbolAddress((void**)&xh,   g_xh);
    cudaGetSymbolAddress((void**)&Wall, g_Wall);
    cudaGetSymbolAddress((void**)&Wth,  g_Wth);
    cudaGetSymbolAddress((void**)&th,   g_th);
    cudaGetSymbolAddress((void**)&tl,   g_tl);
    cudaGetSymbolAddress((void**)&tih,  g_tih);
    cudaGetSymbolAddress((void**)&til,  g_til);

    const int HG3S_SMEM = 98304;  // 3 stages x 32 KB (single-term)
    const int HG_SMEM   = 98304;  // 2 stages x 48 KB (2-term)
    cudaFuncSetAttribute(hgemm3s_k, cudaFuncAttributeMaxDynamicSharedMemorySize, HG3S_SMEM);
    cudaFuncSetAttribute(hgemm3_k,  cudaFuncAttributeMaxDynamicSharedMemorySize, HG_SMEM);
    cudaFuncSetAttribute(hgemm_hl_k, cudaFuncAttributeMaxDynamicSharedMemorySize, HG_SMEM);

    // launches 1-5: weight transposes + x conversion (so #6 = hgemm3s for ncu)
    {
        dim3 wb(32, 8);
        dim3 wg(768/32, 2304/32);
        wconvh_k<<<wg, wb>>>(Wq, Wall,              768, 2304);
        wconvh_k<<<wg, wb>>>(Wk, Wall + 2304*768,   768, 2304);
        wconvh_k<<<wg, wb>>>(Wv, Wall + 4608*768,   768, 2304);
        dim3 wg2(2304/32, 768/32);
        wconvh_k<<<wg2, wb>>>(Wt, Wth, 2304, 768);
    }
    convh_k<<<(25096*768 + 255)/256, 256>>>(x, xh, 25096*768);

    // #6: fused QKV projections of x -> fp16 P buffers
    hgemm3s_k<<<dim3(54, (25096 + 127)/128), 256, HG3S_SMEM>>>(
        xh, Wall, bq, bk, bv, Pq, Pk, Pv, 25096, 768);

    rope_init_k<<<(3136*32 + 255)/256, 256>>>();

    // grouped frame attention -> th/tl (hi/lo fp16, conversion fused)
    grattn_k<<<dim3(195, 12, 8), 256>>>();

    // ti = tmp @ Wt + bt -> tih/til (hi/lo fp16, conversion fused)
    hgemm_hl_k<<<dim3(768/128, (1560 + 127)/128), 256, HG_SMEM>>>(
        th, tl, Wth, bt, tih, til, 1560, 768, 2304);

    // fused QKV on ti (2-term, one launch)
    hgemm3_k<<<dim3(54, (1560 + 127)/128), 256, HG_SMEM>>>(
        tih, til, Wall, bq, bk, bv, Aq, Ak, Av, 1560, 768);

    // cls attention -> U row 0
    cls_k<<<dim3(12, 8), 512>>>();

    // xi = 0 attention -> U row 1
    s0_k<<<dim3(7, 7, 96), 256>>>();
    soft0_k<<<96, 256>>>();

    // xi = 1..15 -> U rows 2..16
    attn2x_k<<<dim3(15, 12, 8), 256>>>();

    // Ou = U @ Wf + bf : 136 x 768, K=2304 (tiny, fp32)
    sgemm64_k<<<dim3(768/64, (136 + 63)/64), 256>>>(U, Wf, bf, Ou, 136, 768, 2304);

    // broadcast to output
    scatter_k<<<(int)(((size_t)8*3137*768 + 255)/256), 256>>>(out);
}

// round 17
// speedup vs baseline: 3.7011x; 1.0384x over previous
#include <cuda_runtime.h>
#include <cuda_fp16.h>
#include <math.h>
#include <cstdint>

// ---------------------------------------------------------------------------
// dividedSpaceTimeAttention  (B=8, NH=12, DIM=768, NP=196, NF=16, DH=64)
// Round 15: soft0 w@V coalesced (warp-per-key), grattn 2x2-tiled score phase
// (4x less LDS traffic), batched QKV weight transpose. GEMMs unchanged.
// ---------------------------------------------------------------------------

#define SCALE_C (1.0f/96.0f)

// ------------------------- scratch (device globals) ------------------------
__device__ __align__(256) __half g_Pqh[57821184];     // 8*3137*2304 fp16
__device__ __align__(256) __half g_Pkh[57821184];
__device__ __align__(256) __half g_Pvh[57821184];
__device__ float g_Aq [8*195*2304];
__device__ float g_Ak [8*195*2304];
__device__ float g_Av [8*195*2304];
__device__ float g_S  [96*195*195];
__device__ float g_U  [8*17*2304];
__device__ float g_Ou [8*17*768];
__device__ float g_cos[3136*32];
__device__ float g_sin[3136*32];

// fp16 operands
__device__ __align__(256) __half g_xh [25096*768];
__device__ __align__(256) __half g_Wall[6912*768];     // [Wq^T; Wk^T; Wv^T]
__device__ __align__(256) __half g_Wth[768*2304];      // Wt^T
__device__ __align__(256) __half g_th [1560*2304], g_tl [1560*2304];
__device__ __align__(256) __half g_tih[1560*768],  g_til[1560*768];

// ------------------------- helpers ---------------------------
__device__ __forceinline__ uint32_t smem_to_u32(const void* p) {
    uint32_t a;
    asm("{ .reg .u64 t; cvta.to.shared.u64 t, %1; cvt.u32.u64 %0, t; }"
        : "=r"(a) : "l"(p));
    return a;
}
#define CP_ASYNC16(dst, src) \
    asm volatile("cp.async.cg.shared.global [%0], [%1], 16;" :: "r"(dst), "l"(src))
#define CP_COMMIT() asm volatile("cp.async.commit_group;")

__device__ __forceinline__ void ldmatrix_x4(uint32_t* r, uint32_t addr) {
    asm volatile("ldmatrix.sync.aligned.m8n8.x4.shared.b16 {%0,%1,%2,%3}, [%4];"
        : "=r"(r[0]), "=r"(r[1]), "=r"(r[2]), "=r"(r[3]) : "r"(addr));
}
__device__ __forceinline__ void mma16816(float* c, const uint32_t* a, const uint32_t* b) {
    asm volatile("mma.sync.aligned.m16n8k16.row.col.f32.f16.f16.f32 "
        "{%0,%1,%2,%3}, {%4,%5,%6,%7}, {%8,%9}, {%0,%1,%2,%3};"
        : "+f"(c[0]), "+f"(c[1]), "+f"(c[2]), "+f"(c[3])
        : "r"(a[0]), "r"(a[1]), "r"(a[2]), "r"(a[3]), "r"(b[0]), "r"(b[1]));
}

// ---------------------------------------------------------------------------
// single-term fused QKV hgemm, fp16 OUTPUT (unchanged from R14)
// ---------------------------------------------------------------------------
__global__ void __launch_bounds__(256, 2) hgemm3s_k(
    const __half* __restrict__ A, const __half* __restrict__ W,
    const float* __restrict__ b0, const float* __restrict__ b1, const float* __restrict__ b2,
    __half* __restrict__ C0, __half* __restrict__ C1, __half* __restrict__ C2,
    int M, int K)
{
    extern __shared__ char smem[];
    const uint32_t sb = smem_to_u32(smem);
    const int tid = threadIdx.x;
    const int wid = tid >> 5, lane = tid & 31;
    const int sel = blockIdx.x / 18;
    const int bn = (blockIdx.x % 18) * 128;
    const int bm = blockIdx.y * 128;
    const int wm = (wid >> 2) * 64;
    const int wn = (wid & 3) * 32;
    const float* bias = (sel == 0) ? b0 : ((sel == 1) ? b1 : b2);
    __half* C = (sel == 0) ? C0 : ((sel == 1) ? C1 : C2);
    const int brow0 = sel * 2304 + bn;

    float acc[4][4][4];
#pragma unroll
    for (int i = 0; i < 4; i++)
#pragma unroll
        for (int j = 0; j < 4; j++)
#pragma unroll
            for (int r = 0; r < 4; r++) acc[i][j][r] = 0.f;

    const int G = K >> 6;
    const int lrow = tid >> 1;
    const int lc0 = (tid & 1) * 4;

    auto ISSUE = [&](int g) {
        const int k0 = g << 6;
        const uint32_t base = sb + (g % 3) * 32768;
        int ga = bm + lrow; if (ga >= M) ga = M - 1;
        const __half* ap = A + (size_t)ga * K + k0 + lc0 * 8;
        const __half* bp = W + (size_t)(brow0 + lrow) * K + k0 + lc0 * 8;
#pragma unroll
        for (int j = 0; j < 4; j++) {
            const uint32_t sw = (uint32_t)(lrow * 128 + (((lc0 + j) ^ (lrow & 7)) << 4));
            CP_ASYNC16(base + sw,         ap + j * 8);
            CP_ASYNC16(base + 16384 + sw, bp + j * 8);
        }
        CP_COMMIT();
    };

    ISSUE(0);
    if (G > 1) ISSUE(1);
    for (int g = 0; g < G; g++) {
        if (g + 2 < G) {
            ISSUE(g + 2);
            asm volatile("cp.async.wait_group 2;");
        } else {
            asm volatile("cp.async.wait_group 0;");
        }
        __syncthreads();
        const uint32_t base = sb + (g % 3) * 32768;
#pragma unroll
        for (int ks = 0; ks < 4; ks++) {
            uint32_t af[4][4], bb[2][4];
#pragma unroll
            for (int mf = 0; mf < 4; mf++) {
                const int row = wm + mf * 16 + (lane & 15);
                const int c16 = ks * 2 + (lane >> 4);
                ldmatrix_x4(af[mf], base + row * 128 + ((c16 ^ (row & 7)) << 4));
            }
#pragma unroll
            for (int nh = 0; nh < 2; nh++) {
                const int row = wn + nh * 16 + (lane & 7) + ((lane & 16) >> 1);
                const int c16 = ks * 2 + ((lane >> 3) & 1);
                ldmatrix_x4(bb[nh], base + 16384 + row * 128 + ((c16 ^ (row & 7)) << 4));
            }
#pragma unroll
            for (int mf = 0; mf < 4; mf++)
#pragma unroll
                for (int nf = 0; nf < 4; nf++)
                    mma16816(acc[mf][nf], af[mf], bb[nf >> 1] + (nf & 1) * 2);
        }
        __syncthreads();
    }

    const int r0 = lane >> 2;
    const int c0 = (lane & 3) * 2;
#pragma unroll
    for (int mf = 0; mf < 4; mf++) {
        const int row0 = bm + wm + mf * 16 + r0;
#pragma unroll
        for (int half = 0; half < 2; half++) {
            const int row = row0 + half * 8;
            if (row < M) {
                __half* Cr = C + (size_t)row * 2304 + bn + wn;
                const float* bp = bias + bn + wn;
#pragma unroll
                for (int nf = 0; nf < 4; nf++) {
                    const int col = nf * 8 + c0;
                    float v0 = acc[mf][nf][half * 2 + 0] + bp[col];
                    float v1 = acc[mf][nf][half * 2 + 1] + bp[col + 1];
                    *(__half2*)(Cr + col) = __floats2half2_rn(v0, v1);
                }
            }
        }
    }
}

// ---------------------------------------------------------------------------
// 2-term fused QKV hgemm, fp32 OUTPUT (unchanged)
// ---------------------------------------------------------------------------
__global__ void __launch_bounds__(256, 2) hgemm3_k(
    const __half* __restrict__ Ah, const __half* __restrict__ Al,
    const __half* __restrict__ W,
    const float* __restrict__ b0, const float* __restrict__ b1, const float* __restrict__ b2,
    float* __restrict__ C0, float* __restrict__ C1, float* __restrict__ C2,
    int M, int K)
{
    extern __shared__ char smem[];
    const uint32_t sb = smem_to_u32(smem);
    const int tid = threadIdx.x;
    const int wid = tid >> 5, lane = tid & 31;
    const int sel = blockIdx.x / 18;
    const int bn = (blockIdx.x % 18) * 128;
    const int bm = blockIdx.y * 128;
    const int wm = (wid >> 2) * 64;
    const int wn = (wid & 3) * 32;
    const float* bias = (sel == 0) ? b0 : ((sel == 1) ? b1 : b2);
    float* C = (sel == 0) ? C0 : ((sel == 1) ? C1 : C2);
    const int brow0 = sel * 2304 + bn;

    float acc[4][4][4];
#pragma unroll
    for (int i = 0; i < 4; i++)
#pragma unroll
        for (int j = 0; j < 4; j++)
#pragma unroll
            for (int r = 0; r < 4; r++) acc[i][j][r] = 0.f;

    const int G = K >> 6;
    const int lrow = tid >> 1;
    const int lc0 = (tid & 1) * 4;

    auto ISSUE = [&](int g) {
        const int k0 = g << 6;
        const uint32_t base = sb + (g & 1) * 49152;
        int ga = bm + lrow; if (ga >= M) ga = M - 1;
        const size_t aoff = (size_t)ga * K + k0 + lc0 * 8;
#pragma unroll
        for (int j = 0; j < 4; j++) {
            const uint32_t sw = (uint32_t)(lrow * 128 + (((lc0 + j) ^ (lrow & 7)) << 4));
            CP_ASYNC16(base + sw,         Ah + aoff + j * 8);
            CP_ASYNC16(base + 16384 + sw, Al + aoff + j * 8);
            CP_ASYNC16(base + 32768 + sw, W + (size_t)(brow0 + lrow) * K + k0 + lc0 * 8 + j * 8);
        }
        CP_COMMIT();
    };

    ISSUE(0);
    for (int g = 0; g < G; g++) {
        if (g + 1 < G) {
            ISSUE(g + 1);
            asm volatile("cp.async.wait_group 1;");
        } else {
            asm volatile("cp.async.wait_group 0;");
        }
        __syncthreads();
        const uint32_t base = sb + (g & 1) * 49152;
#pragma unroll
        for (int ks = 0; ks < 4; ks++) {
            uint32_t ah[4][4], al[4][4], bb[2][4];
#pragma unroll
            for (int mf = 0; mf < 4; mf++) {
                const int row = wm + mf * 16 + (lane & 15);
                const int c16 = ks * 2 + (lane >> 4);
                const uint32_t off = row * 128 + ((c16 ^ (row & 7)) << 4);
                ldmatrix_x4(ah[mf], base + off);
                ldmatrix_x4(al[mf], base + 16384 + off);
            }
#pragma unroll
            for (int nh = 0; nh < 2; nh++) {
                const int row = wn + nh * 16 + (lane & 7) + ((lane & 16) >> 1);
                const int c16 = ks * 2 + ((lane >> 3) & 1);
                ldmatrix_x4(bb[nh], base + 32768 + row * 128 + ((c16 ^ (row & 7)) << 4));
            }
#pragma unroll
            for (int mf = 0; mf < 4; mf++)
#pragma unroll
                for (int nf = 0; nf < 4; nf++)
                    mma16816(acc[mf][nf], ah[mf], bb[nf >> 1] + (nf & 1) * 2);
#pragma unroll
            for (int mf = 0; mf < 4; mf++)
#pragma unroll
                for (int nf = 0; nf < 4; nf++)
                    mma16816(acc[mf][nf], al[mf], bb[nf >> 1] + (nf & 1) * 2);
        }
        __syncthreads();
    }

    const int r0 = lane >> 2;
    const int c0 = (lane & 3) * 2;
#pragma unroll
    for (int mf = 0; mf < 4; mf++) {
        const int row0 = bm + wm + mf * 16 + r0;
#pragma unroll
        for (int half = 0; half < 2; half++) {
            const int row = row0 + half * 8;
            if (row < M) {
                float* Cr = C + (size_t)row * 2304 + bn + wn;
                const float* bp = bias + bn + wn;
#pragma unroll
                for (int nf = 0; nf < 4; nf++) {
                    const int col = nf * 8 + c0;
                    Cr[col]     = acc[mf][nf][half * 2 + 0] + bp[col];
                    Cr[col + 1] = acc[mf][nf][half * 2 + 1] + bp[col + 1];
                }
            }
        }
    }
}

// ---------------------------------------------------------------------------
// 2-term hgemm, hi/lo fp16 OUTPUT (unchanged)
// ---------------------------------------------------------------------------
__global__ void __launch_bounds__(256, 2) hgemm_hl_k(
    const __half* __restrict__ Ah, const __half* __restrict__ Al,
    const __half* __restrict__ Bt,
    const float* __restrict__ bias,
    __half* __restrict__ Th, __half* __restrict__ Tl,
    int M, int N, int K)
{
    extern __shared__ char smem[];
    const uint32_t sb = smem_to_u32(smem);
    const int tid = threadIdx.x;
    const int wid = tid >> 5, lane = tid & 31;
    const int bm = blockIdx.y * 128, bn = blockIdx.x * 128;
    const int wm = (wid >> 2) * 64;
    const int wn = (wid & 3) * 32;

    float acc[4][4][4];
#pragma unroll
    for (int i = 0; i < 4; i++)
#pragma unroll
        for (int j = 0; j < 4; j++)
#pragma unroll
            for (int r = 0; r < 4; r++) acc[i][j][r] = 0.f;

    const int G = K >> 6;
    const int lrow = tid >> 1;
    const int lc0 = (tid & 1) * 4;

    auto ISSUE = [&](int g) {
        const int k0 = g << 6;
        const uint32_t base = sb + (g & 1) * 49152;
        int ga = bm + lrow; if (ga >= M) ga = M - 1;
        const size_t aoff = (size_t)ga * K + k0 + lc0 * 8;
#pragma unroll
        for (int j = 0; j < 4; j++) {
            const uint32_t sw = (uint32_t)(lrow * 128 + (((lc0 + j) ^ (lrow & 7)) << 4));
            CP_ASYNC16(base + sw,         Ah + aoff + j * 8);
            CP_ASYNC16(base + 16384 + sw, Al + aoff + j * 8);
            CP_ASYNC16(base + 32768 + sw, Bt + (size_t)(bn + lrow) * K + k0 + lc0 * 8 + j * 8);
        }
        CP_COMMIT();
    };

    ISSUE(0);
    for (int g = 0; g < G; g++) {
        if (g + 1 < G) {
            ISSUE(g + 1);
            asm volatile("cp.async.wait_group 1;");
        } else {
            asm volatile("cp.async.wait_group 0;");
        }
        __syncthreads();
        const uint32_t base = sb + (g & 1) * 49152;
#pragma unroll
        for (int ks = 0; ks < 4; ks++) {
            uint32_t ah[4][4], al[4][4], bb[2][4];
#pragma unroll
            for (int mf = 0; mf < 4; mf++) {
                const int row = wm + mf * 16 + (lane & 15);
                const int c16 = ks * 2 + (lane >> 4);
                const uint32_t off = row * 128 + ((c16 ^ (row & 7)) << 4);
                ldmatrix_x4(ah[mf], base + off);
                ldmatrix_x4(al[mf], base + 16384 + off);
            }
#pragma unroll
            for (int nh = 0; nh < 2; nh++) {
                const int row = wn + nh * 16 + (lane & 7) + ((lane & 16) >> 1);
                const int c16 = ks * 2 + ((lane >> 3) & 1);
                ldmatrix_x4(bb[nh], base + 32768 + row * 128 + ((c16 ^ (row & 7)) << 4));
            }
#pragma unroll
            for (int mf = 0; mf < 4; mf++)
#pragma unroll
                for (int nf = 0; nf < 4; nf++)
                    mma16816(acc[mf][nf], ah[mf], bb[nf >> 1] + (nf & 1) * 2);
#pragma unroll
            for (int mf = 0; mf < 4; mf++)
#pragma unroll
                for (int nf = 0; nf < 4; nf++)
                    mma16816(acc[mf][nf], al[mf], bb[nf >> 1] + (nf & 1) * 2);
        }
        __syncthreads();
    }

    const int r0 = lane >> 2;
    const int c0 = (lane & 3) * 2;
#pragma unroll
    for (int mf = 0; mf < 4; mf++) {
        const int row0 = bm + wm + mf * 16 + r0;
#pragma unroll
        for (int half = 0; half < 2; half++) {
            const int row = row0 + half * 8;
            if (row < M) {
                const float* bp = bias + bn + wn;
#pragma unroll
                for (int nf = 0; nf < 4; nf++) {
                    const int col = nf * 8 + c0;
                    float v0 = acc[mf][nf][half * 2 + 0] + bp[col];
                    float v1 = acc[mf][nf][half * 2 + 1] + bp[col + 1];
                    __half h0 = __float2half_rn(v0), h1 = __float2half_rn(v1);
                    size_t o = (size_t)row * N + bn + wn + col;
                    *(__half2*)(Th + o) = __halves2half2(h0, h1);
                    *(__half2*)(Tl + o) = __floats2half2_rn(v0 - __half2float(h0),
                                                            v1 - __half2float(h1));
                }
            }
        }
    }
}

// ---------------------------------------------------------------------------
// conversions
// ---------------------------------------------------------------------------
__global__ void convh_k(const float* __restrict__ s, __half* __restrict__ h, int n) {
    int i = blockIdx.x * 256 + threadIdx.x;
    if (i >= n) return;
    h[i] = __float2half_rn(s[i]);
}

// batched transpose of the three 768x2304 QKV weights into g_Wall
__global__ void wconvb_k(const float* __restrict__ W0, const float* __restrict__ W1,
                         const float* __restrict__ W2, __half* __restrict__ T) {
    __shared__ float tile[32][33];
    const int z = blockIdx.z;
    const float* W = (z == 0) ? W0 : ((z == 1) ? W1 : W2);
    __half* Tz = T + (size_t)z * 2304 * 768;
    const int k0 = blockIdx.x * 32, n0 = blockIdx.y * 32;
    const int tx = threadIdx.x, ty = threadIdx.y;
    for (int r = ty; r < 32; r += 8)
        tile[r][tx] = W[(size_t)(k0 + r) * 2304 + n0 + tx];
    __syncthreads();
    for (int r = ty; r < 32; r += 8)
        Tz[(size_t)(n0 + r) * 768 + k0 + tx] = __float2half_rn(tile[tx][r]);
}

// W[K,N] -> T[N,K] (transpose, single fp16)
__global__ void wconvh_k(const float* __restrict__ W, __half* __restrict__ T,
                         int K, int N) {
    __shared__ float tile[32][33];
    const int k0 = blockIdx.x * 32, n0 = blockIdx.y * 32;
    const int tx = threadIdx.x, ty = threadIdx.y;
    for (int r = ty; r < 32; r += 8) {
        int k = k0 + r, n = n0 + tx;
        tile[r][tx] = (k < K && n < N) ? W[(size_t)k * N + n] : 0.f;
    }
    __syncthreads();
    for (int r = ty; r < 32; r += 8) {
        int n = n0 + r, k = k0 + tx;
        if (n < N && k < K)
            T[(size_t)n * K + k] = __float2half_rn(tile[tx][r]);
    }
}

// ---------------------------------------------------------------------------
__global__ void rope_init_k() {
    int idx = blockIdx.x * 256 + threadIdx.x;
    if (idx >= 3136*32) return;
    int s = idx >> 5, i = idx & 31;
    float e = (float)(2*i) / 64.f;
    float invf = 1.f / powf(10000.f, e);
    float ang = (float)s * invf;
    g_cos[idx] = (float)cos((double)ang);
    g_sin[idx] = (float)sin((double)ang);
}

// small fp32 GEMM (final 136-row): 64x64 tile, 4x4/thread
__global__ void __launch_bounds__(256) sgemm64_k(
    const float* __restrict__ A, const float* __restrict__ B,
    const float* __restrict__ bias, float* __restrict__ C,
    int M, int N, int K)
{
    __shared__ float As[8][64];
    __shared__ float Bs[8][64];
    const int bm = blockIdx.y * 64, bn = blockIdx.x * 64;
    const int tid = threadIdx.x;
    const int tx = tid & 15, ty = tid >> 4;
    const int arow = tid >> 2, acol = (tid & 3) * 2;
    const int brow = tid >> 5, bcol = (tid & 31) * 2;
    float acc[4][4];
#pragma unroll
    for (int i = 0; i < 4; i++)
#pragma unroll
        for (int j = 0; j < 4; j++) acc[i][j] = 0.f;
    const bool arow_ok = (bm + arow) < M;
    for (int k0 = 0; k0 < K; k0 += 8) {
        float2 av = make_float2(0.f, 0.f);
        if (arow_ok) av = *(const float2*)(A + (size_t)(bm + arow) * K + k0 + acol);
        As[acol][arow] = av.x;  As[acol + 1][arow] = av.y;
        float2 bv = *(const float2*)(B + (size_t)(k0 + brow) * N + bn + bcol);
        Bs[brow][bcol] = bv.x;  Bs[brow][bcol + 1] = bv.y;
        __syncthreads();
#pragma unroll
        for (int kk = 0; kk < 8; kk++) {
            float ar[4], br[4];
#pragma unroll
            for (int i = 0; i < 4; i++) ar[i] = As[kk][ty * 4 + i];
#pragma unroll
            for (int j = 0; j < 4; j++) br[j] = Bs[kk][tx * 4 + j];
#pragma unroll
            for (int i = 0; i < 4; i++)
#pragma unroll
                for (int j = 0; j < 4; j++)
                    acc[i][j] += ar[i] * br[j];
        }
        __syncthreads();
    }
#pragma unroll
    for (int i = 0; i < 4; i++) {
        int m = bm + ty * 4 + i;
        if (m < M)
#pragma unroll
            for (int j = 0; j < 4; j++)
                C[(size_t)m * N + bn + tx * 4 + j] = acc[i][j] + bias[bn + tx * 4 + j];
    }
}

// ---------------------------------------------------------------------------
// Grouped frame-attention: 2x2-tiled score phase (64 threads, q broadcast)
// ---------------------------------------------------------------------------
#define GA 196
__global__ void __launch_bounds__(256) grattn_k() {
    const int p = blockIdx.x + 1;
    const int h = blockIdx.y;
    const int b = blockIdx.z;
    __shared__ float qs[16*GA], ks[16*GA], vs[16*GA];
    __shared__ float S[256], wg[16];
    const int tid = threadIdx.x;

    for (int idx = tid; idx < 16*96; idx += 256) {
        int f = idx / 96, d2 = (idx - f * 96) * 2;
        size_t off = ((size_t)(b * 3137 + 1 + f * 196 + p)) * 2304 + h * 192 + d2;
        float2 q2 = __half22float2(*(const __half2*)(g_Pqh + off));
        float2 k2 = __half22float2(*(const __half2*)(g_Pvh + off));
        float2 v2 = __half22float2(*(const __half2*)(g_Pkh + off));
        qs[f*GA + d2] = q2.x;  qs[f*GA + d2 + 1] = q2.y;
        ks[f*GA + d2] = k2.x;  ks[f*GA + d2 + 1] = k2.y;
        vs[f*GA + d2] = v2.x;  vs[f*GA + d2 + 1] = v2.y;
    }
    __syncthreads();
    for (int idx = tid; idx < 16*32; idx += 256) {
        int f = idx >> 5, i = idx & 31;
        int s = f * 196 + p;
        float c = g_cos[s*32 + i], sn = g_sin[s*32 + i];
        float a0 = qs[f*GA + 2*i], a1 = qs[f*GA + 2*i + 1];
        qs[f*GA + 2*i]     = a0 * c - a1 * sn;
        qs[f*GA + 2*i + 1] = a1 * c + a0 * sn;
        float b0 = ks[f*GA + 2*i], b1 = ks[f*GA + 2*i + 1];
        ks[f*GA + 2*i]     = b0 * c - b1 * sn;
        ks[f*GA + 2*i + 1] = b1 * c + b0 * sn;
    }
    __syncthreads();
    // scores: 64 threads, each computes 2x2 of the 16x16 S matrix.
    // q fragments broadcast across the 8 g-threads sharing an f-pair.
    if (tid < 64) {
        const int f2 = tid >> 3, g2 = tid & 7;
        const float* q0p = qs + (f2*2)   * GA;
        const float* q1p = qs + (f2*2+1) * GA;
        const float* k0p = ks + (g2*2)   * GA;
        const float* k1p = ks + (g2*2+1) * GA;
        float s00 = 0.f, s01 = 0.f, s10 = 0.f, s11 = 0.f;
#pragma unroll
        for (int d = 0; d < 192; d += 4) {
            float4 q0 = *(const float4*)(q0p + d);
            float4 q1 = *(const float4*)(q1p + d);
            float4 k0 = *(const float4*)(k0p + d);
            float4 k1 = *(const float4*)(k1p + d);
            s00 += q0.x*k0.x + q0.y*k0.y + q0.z*k0.z + q0.w*k0.w;
            s01 += q0.x*k1.x + q0.y*k1.y + q0.z*k1.z + q0.w*k1.w;
            s10 += q1.x*k0.x + q1.y*k0.y + q1.z*k0.z + q1.w*k0.w;
            s11 += q1.x*k1.x + q1.y*k1.y + q1.z*k1.z + q1.w*k1.w;
        }
        S[(f2*2)  *16 + g2*2]     = s00 * SCALE_C;
        S[(f2*2)  *16 + g2*2 + 1] = s01 * SCALE_C;
        S[(f2*2+1)*16 + g2*2]     = s10 * SCALE_C;
        S[(f2*2+1)*16 + g2*2 + 1] = s11 * SCALE_C;
    }
    __syncthreads();
    if (tid < 16) {
        float m = -1e30f;
        for (int g = 0; g < 16; g++) m = fmaxf(m, S[tid*16 + g]);
        float sum = 0.f;
        for (int g = 0; g < 16; g++) { float e = expf(S[tid*16 + g] - m); S[tid*16 + g] = e; sum += e; }
        float inv = 1.f / sum;
        for (int g = 0; g < 16; g++) S[tid*16 + g] *= inv;
    }
    __syncthreads();
    if (tid < 16) {
        float a = 0.f;
        for (int f = 0; f < 16; f++) a += S[f*16 + tid];
        wg[tid] = a;
    }
    __syncthreads();
    if (tid < 192) {
        float o = 0.f;
#pragma unroll
        for (int g = 0; g < 16; g++) o += wg[g] * vs[g*GA + tid];
        size_t off = ((size_t)(b * 195 + (p - 1))) * 2304 + h * 192 + tid;
        __half hv = __float2half_rn(o);
        g_th[off] = hv;
        g_tl[off] = __float2half_rn(o - __half2float(hv));
    }
}

// ---------------------------------------------------------------------------
// CLS attention (fp16 P inputs): 512 threads, warp-parallel w@V
// ---------------------------------------------------------------------------
__global__ void __launch_bounds__(512) cls_k() {
    const int h = blockIdx.x, b = blockIdx.y;
    __shared__ float qv[192];
    __shared__ float Sv[3137];
    __shared__ float red[512];
    __shared__ float red2[16][192];
    const int tid = threadIdx.x;
    const int warp = tid >> 5, lane = tid & 31;
    const __half* Pq_ = g_Pqh + (size_t)b*3137*2304 + h*192;
    const __half* Pk_ = g_Pkh + (size_t)b*3137*2304 + h*192;
    const __half* Pv_ = g_Pvh + (size_t)b*3137*2304 + h*192;
    if (tid < 96) {
        float2 v = __half22float2(*(const __half2*)(Pq_ + tid * 2));
        qv[tid*2] = v.x;  qv[tid*2 + 1] = v.y;
    }
    __syncthreads();
    float lm = -1e30f;
    for (int t = tid; t < 3137; t += 512) {
        const __half* kr = Pk_ + (size_t)t*2304;
        float s = 0.f;
        for (int d = 0; d < 192; d += 8) {
            uint4 raw = *(const uint4*)(kr + d);
            const __half2* k2 = (const __half2*)&raw;
            float2 f0 = __half22float2(k2[0]);
            float2 f1 = __half22float2(k2[1]);
            float2 f2 = __half22float2(k2[2]);
            float2 f3 = __half22float2(k2[3]);
            s += f0.x*qv[d]   + f0.y*qv[d+1] + f1.x*qv[d+2] + f1.y*qv[d+3]
               + f2.x*qv[d+4] + f2.y*qv[d+5] + f3.x*qv[d+6] + f3.y*qv[d+7];
        }
        s *= SCALE_C;
        Sv[t] = s;
        lm = fmaxf(lm, s);
    }
    red[tid] = lm; __syncthreads();
    for (int s2 = 256; s2 > 0; s2 >>= 1) {
        if (tid < s2) red[tid] = fmaxf(red[tid], red[tid + s2]);
        __syncthreads();
    }
    const float m = red[0];
    __syncthreads();
    float ls = 0.f;
    for (int t = tid; t < 3137; t += 512) { float e = expf(Sv[t] - m); Sv[t] = e; ls += e; }
    red[tid] = ls; __syncthreads();
    for (int s2 = 256; s2 > 0; s2 >>= 1) {
        if (tid < s2) red[tid] += red[tid + s2];
        __syncthreads();
    }
    const float inv = 1.f / red[0];
    float o[6];
#pragma unroll
    for (int i = 0; i < 6; i++) o[i] = 0.f;
    for (int t = warp; t < 3137; t += 16) {
        const float w = Sv[t];
        const __half* vr = Pv_ + (size_t)t*2304;
#pragma unroll
        for (int i = 0; i < 6; i++) o[i] += w * __half2float(vr[i*32 + lane]);
    }
#pragma unroll
    for (int i = 0; i < 6; i++) red2[warp][i*32 + lane] = o[i];
    __syncthreads();
    if (tid < 192) {
        float s = 0.f;
#pragma unroll
        for (int w = 0; w < 16; w++) s += red2[w][tid];
        g_U[((size_t)b*17 + 0)*2304 + h*192 + tid] = s * inv;
    }
}

// ---------------------------------------------------------------------------
// xi=0 scores
// ---------------------------------------------------------------------------
__global__ void __launch_bounds__(256) s0_k() {
    const int bh = blockIdx.z;
    const int b = bh / 12, h = bh % 12;
    const int i0 = blockIdx.y * 32, j0 = blockIdx.x * 32;
    __shared__ float Qs[16][33], Ks[16][33];
    const int tid = threadIdx.x;
    const int tx = tid & 15, ty = tid >> 4;
    const float* Abase = g_Aq + (size_t)b*195*2304 + h*192;
    const float* Bbase = g_Av + (size_t)b*195*2304 + h*192;
    float acc00 = 0.f, acc01 = 0.f, acc10 = 0.f, acc11 = 0.f;
    const int r = tid >> 3;
    const int c = (tid & 7) * 2;
    for (int k0 = 0; k0 < 192; k0 += 16) {
        int qi = i0 + r;
        float2 qv = make_float2(0.f, 0.f);
        if (qi < 195) qv = *(const float2*)(Abase + (size_t)qi*2304 + k0 + c);
        Qs[c][r] = qv.x; Qs[c+1][r] = qv.y;
        int kj = j0 + r;
        float2 kv = make_float2(0.f, 0.f);
        if (kj < 195) kv = *(const float2*)(Bbase + (size_t)kj*2304 + k0 + c);
        Ks[c][r] = kv.x; Ks[c+1][r] = kv.y;
        __syncthreads();
#pragma unroll
        for (int kk = 0; kk < 16; kk++) {
            float a0 = Qs[kk][ty*2], a1 = Qs[kk][ty*2+1];
            float b0 = Ks[kk][tx*2], b1 = Ks[kk][tx*2+1];
            acc00 += a0*b0; acc01 += a0*b1; acc10 += a1*b0; acc11 += a1*b1;
        }
        __syncthreads();
    }
    float* Sp = g_S + (size_t)bh*195*195;
    int ii = i0 + ty*2, jj = j0 + tx*2;
    if (ii < 195) {
        if (jj   < 195) Sp[(size_t)ii*195 + jj  ] = acc00 * SCALE_C;
        if (jj+1 < 195) Sp[(size_t)ii*195 + jj+1] = acc01 * SCALE_C;
    }
    if (ii+1 < 195) {
        if (jj   < 195) Sp[(size_t)(ii+1)*195 + jj  ] = acc10 * SCALE_C;
        if (jj+1 < 195) Sp[(size_t)(ii+1)*195 + jj+1] = acc11 * SCALE_C;
    }
}

// ---------------------------------------------------------------------------
// xi=0 softmax + coalesced w@V (warp-per-key, smem partials)
// ---------------------------------------------------------------------------
__global__ void __launch_bounds__(256) soft0_k() {
    const int bh = blockIdx.x;
    const int b = bh / 12, h = bh % 12;
    const float* S = g_S + (size_t)bh*195*195;
    __shared__ float wk_s[195];
    __shared__ float part[8][192];
    const int tid = threadIdx.x;
    if (tid < 195) wk_s[tid] = 0.f;
    __syncthreads();
    const int warp = tid >> 5, lane = tid & 31;
    for (int q = warp; q < 195; q += 8) {
        const float* Sq = S + (size_t)q*195;
        float m = -1e30f;
        for (int k = lane; k < 195; k += 32) m = fmaxf(m, Sq[k]);
        for (int o = 16; o; o >>= 1) m = fmaxf(m, __shfl_xor_sync(0xFFFFFFFFu, m, o));
        float sum = 0.f;
        for (int k = lane; k < 195; k += 32) sum += expf(Sq[k] - m);
        if (lane == 0) sum += expf(Sq[0] - m);
        for (int o = 16; o; o >>= 1) sum += __shfl_xor_sync(0xFFFFFFFFu, sum, o);
        const float inv = 1.f / sum;
        const float mult = (q == 0) ? 2.f : 1.f;
        for (int k = lane; k < 195; k += 32) {
            float w = expf(Sq[k] - m) * inv * mult;
            if (k == 0) w *= 2.f;
            atomicAdd(&wk_s[k], w);
        }
    }
    __syncthreads();
    // w@V coalesced: warp w covers keys w, w+8, ...; lane owns 6 dims
    {
        float o[6];
#pragma unroll
        for (int i = 0; i < 6; i++) o[i] = 0.f;
        for (int k = warp; k < 195; k += 8) {
            const float w = wk_s[k];
            const float* vr = g_Ak + ((size_t)(b*195 + k))*2304 + h*192;
#pragma unroll
            for (int i = 0; i < 6; i++) o[i] += w * vr[i*32 + lane];
        }
#pragma unroll
        for (int i = 0; i < 6; i++) part[warp][i*32 + lane] = o[i];
    }
    __syncthreads();
    if (tid < 192) {
        float s = 0.f;
#pragma unroll
        for (int w = 0; w < 8; w++) s += part[w][tid];
        g_U[((size_t)b*17 + 1)*2304 + h*192 + tid] = s;
    }
}

// ---------------------------------------------------------------------------
// xi=1..15
// ---------------------------------------------------------------------------
__global__ void __launch_bounds__(256) attn2x_k() {
    const int xi = blockIdx.x + 1;
    const int h = blockIdx.y, b = blockIdx.z;
    __shared__ float Ksm[16][192];
    __shared__ float Vsm[16][192];
    __shared__ float wk[16];
    const int tid = threadIdx.x;
    for (int idx = tid; idx < 16*192; idx += 256) {
        int j = idx / 192, d = idx - j*192;
        size_t ro = ((size_t)(b*195 + xi + j))*2304 + h*192 + d;
        Ksm[j][d] = g_Av[ro];
        Vsm[j][d] = g_Ak[ro];
    }
    if (tid < 16) wk[tid] = 0.f;
    __syncthreads();
    const int q = tid;
    if (q < 195) {
        const float* Arow = g_Aq + ((size_t)(b*195 + q))*2304 + h*192;
        float s[16];
#pragma unroll
        for (int j = 0; j < 16; j++) s[j] = 0.f;
        for (int d = 0; d < 192; d += 4) {
            float4 qv = *(const float4*)(Arow + d);
#pragma unroll
            for (int j = 0; j < 16; j++)
                s[j] += qv.x*Ksm[j][d] + qv.y*Ksm[j][d+1] + qv.z*Ksm[j][d+2] + qv.w*Ksm[j][d+3];
        }
        float m = -1e30f;
#pragma unroll
        for (int j = 0; j < 16; j++) { s[j] *= SCALE_C; m = fmaxf(m, s[j]); }
        float sum = 0.f;
#pragma unroll
        for (int j = 0; j < 16; j++) { s[j] = expf(s[j] - m); sum += s[j]; }
        const float w = ((q == xi) ? 2.f : 1.f) / sum;
#pragma unroll
        for (int j = 0; j < 16; j++) atomicAdd(&wk[j], s[j] * w);
    }
    __syncthreads();
    if (tid < 192) {
        float o = 0.f;
#pragma unroll
        for (int j = 0; j < 16; j++) o += wk[j] * Vsm[j][tid];
        g_U[((size_t)b*17 + xi + 1)*2304 + h*192 + tid] = o;
    }
}

// ---------------------------------------------------------------------------
__global__ void scatter_k(float* __restrict__ out) {
    size_t idx = (size_t)blockIdx.x * 256 + threadIdx.x;
    const size_t total = (size_t)8 * 3137 * 768;
    if (idx >= total) return;
    int b = (int)(idx / (3137*768));
    int r = (int)(idx % (3137*768));
    int s = r / 768, d = r - s*768;
    int row = (s == 0) ? 0 : 1 + (s - 1) % 16;
    out[idx] = g_Ou[((size_t)b*17 + row)*768 + d];
}

// ---------------------------------------------------------------------------
extern "C" void kernel_launch(void* const* d_in, const int* in_sizes, int n_in,
                              void* d_out, int out_size) {
    const float* x  = (const float*)d_in[0];
    const float* Wq = (const float*)d_in[1];
    const float* bq = (const float*)d_in[2];
    const float* Wk = (const float*)d_in[3];
    const float* bk = (const float*)d_in[4];
    const float* Wv = (const float*)d_in[5];
    const float* bv = (const float*)d_in[6];
    const float* Wt = (const float*)d_in[7];
    const float* bt = (const float*)d_in[8];
    const float* Wf = (const float*)d_in[9];
    const float* bf = (const float*)d_in[10];
    float* out = (float*)d_out;

    float *Aq, *Ak, *Av, *U, *Ou;
    cudaGetSymbolAddress((void**)&Aq,  g_Aq);
    cudaGetSymbolAddress((void**)&Ak,  g_Ak);
    cudaGetSymbolAddress((void**)&Av,  g_Av);
    cudaGetSymbolAddress((void**)&U,   g_U);
    cudaGetSymbolAddress((void**)&Ou,  g_Ou);

    __half *Pq, *Pk, *Pv, *xh, *Wall, *Wth, *th, *tl, *tih, *til;
    cudaGetSymbolAddress((void**)&Pq,   g_Pqh);
    cudaGetSymbolAddress((void**)&Pk,   g_Pkh);
    cudaGetSymbolAddress((void**)&Pv,   g_Pvh);
    cudaGetSymbolAddress((void**)&xh,   g_xh);
    cudaGetSymbolAddress((void**)&Wall, g_Wall);
    cudaGetSymbolAddress((void**)&Wth,  g_Wth);
    cudaGetSymbolAddress((void**)&th,   g_th);
    cudaGetSymbolAddress((void**)&tl,   g_tl);
    cudaGetSymbolAddress((void**)&tih,  g_tih);
    cudaGetSymbolAddress((void**)&til,  g_til);

    const int HG3S_SMEM = 98304;  // 3 stages x 32 KB (single-term)
    const int HG_SMEM   = 98304;  // 2 stages x 48 KB (2-term)
    cudaFuncSetAttribute(hgemm3s_k, cudaFuncAttributeMaxDynamicSharedMemorySize, HG3S_SMEM);
    cudaFuncSetAttribute(hgemm3_k,  cudaFuncAttributeMaxDynamicSharedMemorySize, HG_SMEM);
    cudaFuncSetAttribute(hgemm_hl_k, cudaFuncAttributeMaxDynamicSharedMemorySize, HG_SMEM);

    // 1: batched QKV weight transpose
    wconvb_k<<<dim3(768/32, 2304/32, 3), dim3(32, 8)>>>(Wq, Wk, Wv, Wall);
    // 2: Wt transpose
    wconvh_k<<<dim3(2304/32, 768/32), dim3(32, 8)>>>(Wt, Wth, 2304, 768);
    // 3: x -> fp16
    convh_k<<<(25096*768 + 255)/256, 256>>>(x, xh, 25096*768);
    // 4: rope tables
    rope_init_k<<<(3136*32 + 255)/256, 256>>>();
    // 5: fused QKV projections of x -> fp16 P buffers
    hgemm3s_k<<<dim3(54, (25096 + 127)/128), 256, HG3S_SMEM>>>(
        xh, Wall, bq, bk, bv, Pq, Pk, Pv, 25096, 768);
    // 6 (ncu-profiled): grouped frame attention -> th/tl
    grattn_k<<<dim3(195, 12, 8), 256>>>();

    // ti = tmp @ Wt + bt -> tih/til (hi/lo fp16, conversion fused)
    hgemm_hl_k<<<dim3(768/128, (1560 + 127)/128), 256, HG_SMEM>>>(
        th, tl, Wth, bt, tih, til, 1560, 768, 2304);

    // fused QKV on ti (2-term, one launch)
    hgemm3_k<<<dim3(54, (1560 + 127)/128), 256, HG_SMEM>>>(
        tih, til, Wall, bq, bk, bv, Aq, Ak, Av, 1560, 768);

    // cls attention -> U row 0
    cls_k<<<dim3(12, 8), 512>>>();

    // xi = 0 attention -> U row 1
    s0_k<<<dim3(7, 7, 96), 256>>>();
    soft0_k<<<96, 256>>>();

    // xi = 1..15 -> U rows 2..16
    attn2x_k<<<dim3(15, 12, 8), 256>>>();

    // Ou = U @ Wf + bf : 136 x 768, K=2304 (tiny, fp32)
    sgemm64_k<<<dim3(768/64, (136 + 63)/64), 256>>>(U, Wf, bf, Ou, 136, 768, 2304);

    // broadcast to output
    scatter_k<<<(int)(((size_t)8*3137*768 + 255)/256), 256>>>(out);
}